// round 9
// baseline (speedup 1.0000x reference)
#include <cuda_runtime.h>
#include <cuda_bf16.h>
#include <math.h>
#include <stdint.h>

// Problem constants
#define BB 2
#define TT 4096
#define WW 2048
#define LL 2048
#define HH 8
#define TWD 4
#define HD 256                 // LL / HH
#define MTOT (BB * TT)         // 8192 rows
#define ELEMS ((size_t)MTOT * LL)  // 16,777,216
#define L4C (LL / 4)           // 512

#define SCH 128                // scan chunk length
#define NCH (TT / SCH)         // 32 chunks

// ---------------------------------------------------------------------------
// Scratch buffers (static device globals — no runtime allocation)
// ---------------------------------------------------------------------------
__device__ float g_Y[ELEMS];      // gelu(x @ w_y + b_y)
__device__ float g_XB[ELEMS];     // x @ w_x + b_x
__device__ float g_G1[ELEMS];     // normed
__device__ float g_G2[ELEMS];     // a_masked

__device__ __nv_bfloat16 g_Ah[ELEMS];            // bf16 hi split of current A operand
__device__ __nv_bfloat16 g_Al[ELEMS];            // bf16 lo split
__device__ __nv_bfloat16 g_BhY[(size_t)LL * WW]; // transposed w_y hi [N,K] (reused for w_out)
__device__ __nv_bfloat16 g_BlY[(size_t)LL * WW];
__device__ __nv_bfloat16 g_BhX[(size_t)LL * WW]; // transposed w_x hi [N,K]
__device__ __nv_bfloat16 g_BlX[(size_t)LL * WW];
__device__ __nv_bfloat16 g_GW1h[(size_t)HH * HD * HD];
__device__ __nv_bfloat16 g_GW1l[(size_t)HH * HD * HD];
__device__ __nv_bfloat16 g_GW2h[(size_t)HH * HD * HD];
__device__ __nv_bfloat16 g_GW2l[(size_t)HH * HD * HD];

__device__ float g_Aagg[(size_t)BB * NCH * LL];
__device__ float g_Hend[(size_t)BB * NCH * LL];
__device__ float g_Cin [(size_t)BB * NCH * LL];

// ---------------------------------------------------------------------------
// Low-level helpers (sm_80-portable: ldmatrix / mma.sync / cp.async only)
// ---------------------------------------------------------------------------
__device__ __forceinline__ uint32_t smem_u32(const void* p) {
    uint32_t a;
    asm("{ .reg .u64 t; cvta.to.shared.u64 t, %1; cvt.u32.u64 %0, t; }" : "=r"(a) : "l"(p));
    return a;
}
__device__ __forceinline__ void cp_async16(uint32_t saddr, const void* gaddr) {
    asm volatile("cp.async.cg.shared.global [%0], [%1], 16;" :: "r"(saddr), "l"(gaddr) : "memory");
}
__device__ __forceinline__ void ldm_x4(uint32_t* r, uint32_t addr) {
    asm volatile("ldmatrix.sync.aligned.m8n8.x4.shared.b16 {%0,%1,%2,%3}, [%4];"
                 : "=r"(r[0]), "=r"(r[1]), "=r"(r[2]), "=r"(r[3]) : "r"(addr));
}
__device__ __forceinline__ void mma16816(float* c, const uint32_t* a, const uint32_t* b) {
    asm volatile("mma.sync.aligned.m16n8k16.row.col.f32.bf16.bf16.f32 "
                 "{%0,%1,%2,%3}, {%4,%5,%6,%7}, {%8,%9}, {%0,%1,%2,%3};"
                 : "+f"(c[0]), "+f"(c[1]), "+f"(c[2]), "+f"(c[3])
                 : "r"(a[0]), "r"(a[1]), "r"(a[2]), "r"(a[3]), "r"(b[0]), "r"(b[1]));
}

// ---------------------------------------------------------------------------
// Big GEMM: C[m,n] = EPI( sum_k A[m,k]*B[n,k] + bias[n] )
// 3xbf16 split (Ah*Bh + Ah*Bl + Al*Bh), fp32 accum.
// Tile 128x128x64, 512 threads, 16 warps of 32x32 (4M x 4N),
// 3-stage cp.async pipeline. SMEM rows padded to 144 B.
// ---------------------------------------------------------------------------
#define BKK 64
#define ROWB 144                       // padded row bytes (64*2 + 16)
#define MATB (128 * ROWB)              // 18432 bytes per matrix tile
#define STAGEB (4 * MATB)              // 73728 bytes per stage
#define NSTAGE 3
#define GEMM_SMEM (NSTAGE * STAGEB)    // 221184 bytes

template <int EPI>
__global__ __launch_bounds__(512, 1)
void gemm_tc(const __nv_bfloat16* __restrict__ Ah, const __nv_bfloat16* __restrict__ Al,
             const __nv_bfloat16* __restrict__ Bh, const __nv_bfloat16* __restrict__ Bl,
             const float* __restrict__ bias, float* __restrict__ C,
             int K, int lda, int ldb, int ldc)
{
    extern __shared__ char sm[];
    const uint32_t sbase = smem_u32(sm);
    const int tid  = threadIdx.x;
    const int lane = tid & 31;
    const int wid  = tid >> 5;
    const int m0 = blockIdx.y * 128;
    const int n0 = blockIdx.x * 128;

    const __nv_bfloat16* AbH = Ah + (size_t)m0 * lda;
    const __nv_bfloat16* AbL = Al + (size_t)m0 * lda;
    const __nv_bfloat16* BbH = Bh + (size_t)n0 * ldb;
    const __nv_bfloat16* BbL = Bl + (size_t)n0 * ldb;

    const int NIT = K / BKK;

    auto load_stage = [&](int it, int buf) {
        const int k0 = it * BKK;
        const __nv_bfloat16* srcs[4] = {AbH, AbL, BbH, BbL};
#pragma unroll
        for (int mt = 0; mt < 4; mt++) {
            const int ld = (mt < 2) ? lda : ldb;
            const __nv_bfloat16* src = srcs[mt];
#pragma unroll
            for (int i = 0; i < 2; i++) {
                int c = tid + 512 * i;           // 0..1023
                int row = c >> 3, col = c & 7;
                uint32_t sa = sbase + buf * STAGEB + mt * MATB + row * ROWB + col * 16;
                cp_async16(sa, src + (size_t)row * ld + k0 + col * 8);
            }
        }
        asm volatile("cp.async.commit_group;" ::: "memory");
    };

    // 4 M x 4 N warp grid, each warp 32x32
    const int m0w = (wid & 3) * 32;
    const int n0w = (wid >> 2) * 32;

    float acc[2][4][4];
#pragma unroll
    for (int i = 0; i < 2; i++)
#pragma unroll
        for (int j = 0; j < 4; j++)
#pragma unroll
            for (int e = 0; e < 4; e++) acc[i][j][e] = 0.f;

    load_stage(0, 0);
    if (NIT > 1) load_stage(1, 1);

    for (int it = 0; it < NIT; it++) {
        if (it + 1 < NIT) asm volatile("cp.async.wait_group 1;" ::: "memory");
        else              asm volatile("cp.async.wait_group 0;" ::: "memory");
        __syncthreads();
        if (it + 2 < NIT) load_stage(it + 2, (it + 2) % NSTAGE);

        const int buf = it % NSTAGE;
        const uint32_t sAh = sbase + buf * STAGEB;
        const uint32_t sAl = sAh + MATB;
        const uint32_t sBh = sAh + 2 * MATB;
        const uint32_t sBl = sAh + 3 * MATB;

#pragma unroll
        for (int ks = 0; ks < BKK; ks += 16) {
            uint32_t ah[2][4], al[2][4], bh[4][2], bl[4][2];
            const uint32_t aoff = (uint32_t)(lane & 15) * ROWB + (uint32_t)ks * 2
                                + (uint32_t)(lane >> 4) * 16;
#pragma unroll
            for (int mf = 0; mf < 2; mf++) {
                uint32_t ad = (uint32_t)(m0w + mf * 16) * ROWB + aoff;
                ldm_x4(ah[mf], sAh + ad);
                ldm_x4(al[mf], sAl + ad);
            }
            const uint32_t boff = (uint32_t)(((lane >> 4) << 3) + (lane & 7)) * ROWB
                                + (uint32_t)ks * 2 + (uint32_t)((lane >> 3) & 1) * 16;
#pragma unroll
            for (int nf2 = 0; nf2 < 2; nf2++) {
                uint32_t bd = (uint32_t)(n0w + nf2 * 16) * ROWB + boff;
                uint32_t rh[4], rl[4];
                ldm_x4(rh, sBh + bd);
                ldm_x4(rl, sBl + bd);
                bh[nf2 * 2][0] = rh[0]; bh[nf2 * 2][1] = rh[1];
                bh[nf2 * 2 + 1][0] = rh[2]; bh[nf2 * 2 + 1][1] = rh[3];
                bl[nf2 * 2][0] = rl[0]; bl[nf2 * 2][1] = rl[1];
                bl[nf2 * 2 + 1][0] = rl[2]; bl[nf2 * 2 + 1][1] = rl[3];
            }
#pragma unroll
            for (int mf = 0; mf < 2; mf++)
#pragma unroll
                for (int nf = 0; nf < 4; nf++)
                    mma16816(acc[mf][nf], ah[mf], bh[nf]);
#pragma unroll
            for (int mf = 0; mf < 2; mf++)
#pragma unroll
                for (int nf = 0; nf < 4; nf++)
                    mma16816(acc[mf][nf], ah[mf], bl[nf]);
#pragma unroll
            for (int mf = 0; mf < 2; mf++)
#pragma unroll
                for (int nf = 0; nf < 4; nf++)
                    mma16816(acc[mf][nf], al[mf], bh[nf]);
        }
    }

    // epilogue: bias + activation, direct float2 stores
    const int rbase = m0 + m0w + (lane >> 2);
    const int cbase = n0 + n0w + (lane & 3) * 2;
#pragma unroll
    for (int mf = 0; mf < 2; mf++) {
#pragma unroll
        for (int nf = 0; nf < 4; nf++) {
            int col = cbase + nf * 8;
            float b0 = bias[col], b1 = bias[col + 1];
            float v[4] = {acc[mf][nf][0] + b0, acc[mf][nf][1] + b1,
                          acc[mf][nf][2] + b0, acc[mf][nf][3] + b1};
#pragma unroll
            for (int e = 0; e < 4; e++) {
                if (EPI == 1) {
                    float x = v[e];
                    float t = tanhf(0.7978845608028654f * (x + 0.044715f * x * x * x));
                    v[e] = 0.5f * x * (1.f + t);
                }
            }
            int r0 = rbase + mf * 16;
            *(float2*)&C[(size_t)r0 * ldc + col]       = make_float2(v[0], v[1]);
            *(float2*)&C[(size_t)(r0 + 8) * ldc + col] = make_float2(v[2], v[3]);
        }
    }
}

// ---------------------------------------------------------------------------
// Dual gate GEMM + fused combine epilogue (unchanged, 256 threads).
// conv value reconstructed from its bf16 hi/lo split (Ah + Al) — no f32 buffer.
// ---------------------------------------------------------------------------
#define GMATB (128 * ROWB)             // 18432
#define GSTAGEB (6 * GMATB)            // 110592
#define GATE_SMEM (2 * GSTAGEB)        // 221184

__global__ __launch_bounds__(256, 1)
void gate_tc(const __nv_bfloat16* __restrict__ cAh, const __nv_bfloat16* __restrict__ cAl,
             const __nv_bfloat16* __restrict__ W1h, const __nv_bfloat16* __restrict__ W1l,
             const __nv_bfloat16* __restrict__ W2h, const __nv_bfloat16* __restrict__ W2l,
             const float* __restrict__ ib, const float* __restrict__ ab,
             const float* __restrict__ a_param, const int* __restrict__ seg,
             float* __restrict__ G1, float* __restrict__ G2)
{
    extern __shared__ char sm[];
    const uint32_t sbase = smem_u32(sm);
    const int tid  = threadIdx.x;
    const int lane = tid & 31;
    const int wid  = tid >> 5;
    const int z  = blockIdx.z;           // head
    const int m0 = blockIdx.y * 128;
    const int n0 = blockIdx.x * 128;     // 0 or 128 within head

    const __nv_bfloat16* AbH = cAh + (size_t)m0 * LL + z * HD;
    const __nv_bfloat16* AbL = cAl + (size_t)m0 * LL + z * HD;
    const __nv_bfloat16* B1H = W1h + (size_t)z * HD * HD + (size_t)n0 * HD;
    const __nv_bfloat16* B1L = W1l + (size_t)z * HD * HD + (size_t)n0 * HD;
    const __nv_bfloat16* B2H = W2h + (size_t)z * HD * HD + (size_t)n0 * HD;
    const __nv_bfloat16* B2L = W2l + (size_t)z * HD * HD + (size_t)n0 * HD;

    const int NIT = HD / BKK;   // 4

    auto load_stage = [&](int it, int buf) {
        const int k0 = it * BKK;
        const __nv_bfloat16* srcs[6] = {AbH, AbL, B1H, B1L, B2H, B2L};
#pragma unroll
        for (int mt = 0; mt < 6; mt++) {
            const int ld = (mt < 2) ? LL : HD;
            const __nv_bfloat16* src = srcs[mt];
#pragma unroll
            for (int i = 0; i < 4; i++) {
                int c = tid + 256 * i;
                int row = c >> 3, col = c & 7;
                uint32_t sa = sbase + buf * GSTAGEB + mt * GMATB + row * ROWB + col * 16;
                cp_async16(sa, src + (size_t)row * ld + k0 + col * 8);
            }
        }
        asm volatile("cp.async.commit_group;" ::: "memory");
    };

    const int m0w = (wid & 1) * 64;
    const int n0w = (wid >> 1) * 32;

    float acc[2][4][4][4];
#pragma unroll
    for (int s = 0; s < 2; s++)
#pragma unroll
        for (int i = 0; i < 4; i++)
#pragma unroll
            for (int j = 0; j < 4; j++)
#pragma unroll
                for (int e = 0; e < 4; e++) acc[s][i][j][e] = 0.f;

    load_stage(0, 0);
    load_stage(1, 1);

    for (int it = 0; it < NIT; it++) {
        if (it + 1 < NIT) asm volatile("cp.async.wait_group 1;" ::: "memory");
        else              asm volatile("cp.async.wait_group 0;" ::: "memory");
        __syncthreads();

        const int buf = it & 1;
        const uint32_t sA = sbase + buf * GSTAGEB;

#pragma unroll
        for (int ks = 0; ks < BKK; ks += 16) {
            uint32_t ah[4][4], al[4][4];
            const uint32_t aoff = (uint32_t)(lane & 15) * ROWB + (uint32_t)ks * 2
                                + (uint32_t)(lane >> 4) * 16;
#pragma unroll
            for (int mf = 0; mf < 4; mf++) {
                uint32_t ad = (uint32_t)(m0w + mf * 16) * ROWB + aoff;
                ldm_x4(ah[mf], sA + ad);
                ldm_x4(al[mf], sA + GMATB + ad);
            }
            const uint32_t boff = (uint32_t)(((lane >> 4) << 3) + (lane & 7)) * ROWB
                                + (uint32_t)ks * 2 + (uint32_t)((lane >> 3) & 1) * 16;
#pragma unroll
            for (int s = 0; s < 2; s++) {
                uint32_t bh[4][2], bl[4][2];
                const uint32_t sBh = sA + (2 + 2 * s) * GMATB;
                const uint32_t sBl = sBh + GMATB;
#pragma unroll
                for (int nf2 = 0; nf2 < 2; nf2++) {
                    uint32_t bd = (uint32_t)(n0w + nf2 * 16) * ROWB + boff;
                    uint32_t rh[4], rl[4];
                    ldm_x4(rh, sBh + bd);
                    ldm_x4(rl, sBl + bd);
                    bh[nf2 * 2][0] = rh[0]; bh[nf2 * 2][1] = rh[1];
                    bh[nf2 * 2 + 1][0] = rh[2]; bh[nf2 * 2 + 1][1] = rh[3];
                    bl[nf2 * 2][0] = rl[0]; bl[nf2 * 2][1] = rl[1];
                    bl[nf2 * 2 + 1][0] = rl[2]; bl[nf2 * 2 + 1][1] = rl[3];
                }
#pragma unroll
                for (int mf = 0; mf < 4; mf++)
#pragma unroll
                    for (int nf = 0; nf < 4; nf++)
                        mma16816(acc[s][mf][nf], ah[mf], bh[nf]);
#pragma unroll
                for (int mf = 0; mf < 4; mf++)
#pragma unroll
                    for (int nf = 0; nf < 4; nf++)
                        mma16816(acc[s][mf][nf], ah[mf], bl[nf]);
#pragma unroll
                for (int mf = 0; mf < 4; mf++)
#pragma unroll
                    for (int nf = 0; nf < 4; nf++)
                        mma16816(acc[s][mf][nf], al[mf], bh[nf]);
            }
        }
        __syncthreads();
        if (it + 2 < NIT) load_stage(it + 2, it & 1);
    }

    // fused combine epilogue (conv reconstructed from hi/lo split)
    const int rbase = m0 + m0w + (lane >> 2);          // global row
    const int cloc0 = n0 + n0w + (lane & 3) * 2;       // col within head
#pragma unroll
    for (int mf = 0; mf < 4; mf++) {
#pragma unroll
        for (int half = 0; half < 2; half++) {
            int row = rbase + mf * 16 + half * 8;
            bool reset = (seg[row] == 0);
#pragma unroll
            for (int nf = 0; nf < 4; nf++) {
                int cl = cloc0 + nf * 8;               // col within head (0..255)
                size_t go = (size_t)row * LL + (size_t)z * HD + cl;
                uint32_t chp = *(const uint32_t*)&cAh[go];
                uint32_t clp = *(const uint32_t*)&cAl[go];
                float outn[2], outa[2];
#pragma unroll
                for (int e = 0; e < 2; e++) {
                    float c1 = acc[0][mf][nf][half * 2 + e] + ib[z * HD + cl + e];
                    float c2 = acc[1][mf][nf][half * 2 + e] + ab[z * HD + cl + e];
                    float gi = 1.f / (1.f + expf(-c1));
                    float ga = 1.f / (1.f + expf(-c2));
                    float ap = a_param[z * HD + cl + e];
                    float sp = log1pf(expf(ap));
                    float la = -8.f * ga * sp;
                    float a = expf(la);
                    float mult = reset ? 1.f : sqrtf(fmaxf(1.f - expf(2.f * la), 0.f));
                    uint16_t hb = (uint16_t)((e == 0) ? (chp & 0xFFFF) : (chp >> 16));
                    uint16_t lb = (uint16_t)((e == 0) ? (clp & 0xFFFF) : (clp >> 16));
                    float cvv = __bfloat162float(__ushort_as_bfloat16(hb))
                              + __bfloat162float(__ushort_as_bfloat16(lb));
                    outn[e] = cvv * gi * mult;
                    outa[e] = reset ? 0.f : a;
                }
                *(float2*)&G1[go] = make_float2(outn[0], outn[1]);
                *(float2*)&G2[go] = make_float2(outa[0], outa[1]);
            }
        }
    }
}

// ---------------------------------------------------------------------------
// f32 -> bf16 hi/lo split (vectorized x4)
// ---------------------------------------------------------------------------
__device__ __forceinline__ uint32_t pk2(float a, float b) {
    uint32_t lo = (uint32_t)__bfloat16_as_ushort(__float2bfloat16_rn(a));
    uint32_t hi = (uint32_t)__bfloat16_as_ushort(__float2bfloat16_rn(b));
    return lo | (hi << 16);
}
__device__ __forceinline__ void split_f4(float4 v, uint2& H, uint2& L) {
    __nv_bfloat16 hx = __float2bfloat16_rn(v.x), hy = __float2bfloat16_rn(v.y);
    __nv_bfloat16 hz = __float2bfloat16_rn(v.z), hw = __float2bfloat16_rn(v.w);
    H.x = (uint32_t)__bfloat16_as_ushort(hx) | ((uint32_t)__bfloat16_as_ushort(hy) << 16);
    H.y = (uint32_t)__bfloat16_as_ushort(hz) | ((uint32_t)__bfloat16_as_ushort(hw) << 16);
    L.x = pk2(v.x - __bfloat162float(hx), v.y - __bfloat162float(hy));
    L.y = pk2(v.z - __bfloat162float(hz), v.w - __bfloat162float(hw));
}
__global__ void split4_k(const float4* __restrict__ in, uint2* __restrict__ oh,
                         uint2* __restrict__ ol, long n4)
{
    long i = (long)blockIdx.x * blockDim.x + threadIdx.x;
    if (i >= n4) return;
    uint2 H, L;
    split_f4(in[i], H, L);
    oh[i] = H; ol[i] = L;
}

// ---------------------------------------------------------------------------
// Transposing split: in [K,N] f32 -> out [N,K] bf16 hi/lo (batched)
// ---------------------------------------------------------------------------
__global__ void tsplit_k(const float* __restrict__ in, __nv_bfloat16* __restrict__ oh,
                         __nv_bfloat16* __restrict__ ol, int K, int N,
                         long inBatch, long outBatch)
{
    __shared__ float t[32][33];
    int z = blockIdx.z;
    const float* ib = in + (long)z * inBatch;
    int kb = blockIdx.y * 32, nb = blockIdx.x * 32;
    for (int i = threadIdx.y; i < 32; i += 8)
        t[i][threadIdx.x] = ib[(size_t)(kb + i) * N + nb + threadIdx.x];
    __syncthreads();
    for (int i = threadIdx.y; i < 32; i += 8) {
        int n = nb + i, k = kb + threadIdx.x;
        float v = t[threadIdx.x][i];
        __nv_bfloat16 h = __float2bfloat16_rn(v);
        size_t o = (long)z * outBatch + (size_t)n * K + k;
        oh[o] = h;
        ol[o] = __float2bfloat16_rn(v - __bfloat162float(h));
    }
}

// ---------------------------------------------------------------------------
// Causal depthwise temporal conv (TW=4) -> bf16 hi/lo split output
// ---------------------------------------------------------------------------
__global__ void conv_k(const float4* __restrict__ xb, const float4* __restrict__ cw,
                       const float4* __restrict__ cb,
                       uint2* __restrict__ oh, uint2* __restrict__ ol)
{
    long idx = (long)blockIdx.x * blockDim.x + threadIdx.x;
    if (idx >= (long)MTOT * L4C) return;
    int l4 = (int)(idx % L4C);
    int m = (int)(idx / L4C);
    int t = m % TT;
    float4 acc = cb[l4];
#pragma unroll
    for (int j = 0; j < TWD; j++) {
        int dt = TWD - 1 - j;
        if (t - dt >= 0) {
            float4 w = cw[j * L4C + l4];
            float4 x = xb[(long)(m - dt) * L4C + l4];
            acc.x = fmaf(w.x, x.x, acc.x);
            acc.y = fmaf(w.y, x.y, acc.y);
            acc.z = fmaf(w.z, x.z, acc.z);
            acc.w = fmaf(w.w, x.w, acc.w);
        }
    }
    uint2 H, L;
    split_f4(acc, H, L);
    oh[idx] = H; ol[idx] = L;
}

// ---------------------------------------------------------------------------
// Chunked scan (scalar over L): h_t = a_t h_{t-1} + x_t
// Pass 3 fused with elementwise gate (h*y) and bf16 split for the final GEMM.
// ---------------------------------------------------------------------------
__global__ void scan_p1(const float* __restrict__ a, const float* __restrict__ x,
                        float* __restrict__ Aagg, float* __restrict__ Hend)
{
    long idx = (long)blockIdx.x * blockDim.x + threadIdx.x;  // over B*NCH*L
    if (idx >= (long)BB * NCH * LL) return;
    int l = (int)(idx % LL);
    int r = (int)(idx / LL);
    int c = r % NCH, b = r / NCH;
    size_t base = ((size_t)b * TT + (size_t)c * SCH) * LL + l;
    float h = 0.f, ap = 1.f;
#pragma unroll 4
    for (int t = 0; t < SCH; t++) {
        float av = a[base + (size_t)t * LL];
        h = fmaf(av, h, x[base + (size_t)t * LL]);
        ap *= av;
    }
    Aagg[idx] = ap; Hend[idx] = h;
}
__global__ void scan_p2(const float* __restrict__ Aagg, const float* __restrict__ Hend,
                        float* __restrict__ Cin)
{
    int idx = blockIdx.x * blockDim.x + threadIdx.x;
    if (idx >= BB * LL) return;
    int l = idx % LL, b = idx / LL;
    float cin = 0.f;
    for (int c = 0; c < NCH; c++) {
        size_t j = ((size_t)b * NCH + c) * LL + l;
        Cin[j] = cin;
        cin = fmaf(Aagg[j], cin, Hend[j]);
    }
}
__global__ void scan_p3f(const float* __restrict__ a, const float* __restrict__ x,
                         const float* __restrict__ Cin, const float* __restrict__ y,
                         __nv_bfloat16* __restrict__ oh, __nv_bfloat16* __restrict__ ol)
{
    long idx = (long)blockIdx.x * blockDim.x + threadIdx.x;
    if (idx >= (long)BB * NCH * LL) return;
    int l = (int)(idx % LL);
    int r = (int)(idx / LL);
    int c = r % NCH, b = r / NCH;
    size_t base = ((size_t)b * TT + (size_t)c * SCH) * LL + l;
    float h = Cin[idx];
#pragma unroll 4
    for (int t = 0; t < SCH; t++) {
        size_t o = base + (size_t)t * LL;
        h = fmaf(a[o], h, x[o]);
        float v = h * y[o];
        __nv_bfloat16 hi = __float2bfloat16_rn(v);
        oh[o] = hi;
        ol[o] = __float2bfloat16_rn(v - __bfloat162float(hi));
    }
}

// ---------------------------------------------------------------------------
// Launch (big GEMMs in launch slots 3 and 4 for ncu window)
// ---------------------------------------------------------------------------
extern "C" void kernel_launch(void* const* d_in, const int* in_sizes, int n_in,
                              void* d_out, int out_size)
{
    const float* x       = (const float*)d_in[0];
    const int*   seg     = (const int*)  d_in[1];
    const float* w_y     = (const float*)d_in[2];
    const float* b_y     = (const float*)d_in[3];
    const float* w_x     = (const float*)d_in[4];
    const float* b_x     = (const float*)d_in[5];
    const float* w_out   = (const float*)d_in[6];
    const float* b_out   = (const float*)d_in[7];
    const float* conv_w  = (const float*)d_in[8];
    const float* conv_b  = (const float*)d_in[9];
    const float* a_param = (const float*)d_in[10];
    const float* igate_w = (const float*)d_in[11];
    const float* igate_b = (const float*)d_in[12];
    const float* agate_w = (const float*)d_in[13];
    const float* agate_b = (const float*)d_in[14];
    float* out = (float*)d_out;

    float *Y, *XB, *G1, *G2, *Aagg, *Hend, *Cin;
    __nv_bfloat16 *Ah, *Al, *BhY, *BlY, *BhX, *BlX, *GW1h, *GW1l, *GW2h, *GW2l;
    cudaGetSymbolAddress((void**)&Y, g_Y);
    cudaGetSymbolAddress((void**)&XB, g_XB);
    cudaGetSymbolAddress((void**)&G1, g_G1);
    cudaGetSymbolAddress((void**)&G2, g_G2);
    cudaGetSymbolAddress((void**)&Ah, g_Ah);
    cudaGetSymbolAddress((void**)&Al, g_Al);
    cudaGetSymbolAddress((void**)&BhY, g_BhY);
    cudaGetSymbolAddress((void**)&BlY, g_BlY);
    cudaGetSymbolAddress((void**)&BhX, g_BhX);
    cudaGetSymbolAddress((void**)&BlX, g_BlX);
    cudaGetSymbolAddress((void**)&GW1h, g_GW1h);
    cudaGetSymbolAddress((void**)&GW1l, g_GW1l);
    cudaGetSymbolAddress((void**)&GW2h, g_GW2h);
    cudaGetSymbolAddress((void**)&GW2l, g_GW2l);
    cudaGetSymbolAddress((void**)&Aagg, g_Aagg);
    cudaGetSymbolAddress((void**)&Hend, g_Hend);
    cudaGetSymbolAddress((void**)&Cin, g_Cin);

    cudaFuncSetAttribute(gemm_tc<0>, cudaFuncAttributeMaxDynamicSharedMemorySize, GEMM_SMEM);
    cudaFuncSetAttribute(gemm_tc<1>, cudaFuncAttributeMaxDynamicSharedMemorySize, GEMM_SMEM);
    cudaFuncSetAttribute(gate_tc, cudaFuncAttributeMaxDynamicSharedMemorySize, GATE_SMEM);

    const long n4 = (long)ELEMS / 4;
    const int eb = (int)((n4 + 255) / 256);
    dim3 tgrid(WW / 32, WW / 32, 1);
    dim3 tblk(32, 8, 1);
    dim3 bigGrid(LL / 128, MTOT / 128, 1);     // (16, 64)
    dim3 gateGrid(HD / 128, MTOT / 128, HH);   // (2, 64, 8)
    dim3 ggrid(HD / 32, HD / 32, HH);

    // slot 0: w_y^T split
    tsplit_k<<<tgrid, tblk>>>(w_y, BhY, BlY, WW, LL, 0, 0);
    // slot 1: split x -> Ah/Al
    split4_k<<<eb, 256>>>((const float4*)x, (uint2*)Ah, (uint2*)Al, n4);
    // slot 2: w_x^T split
    tsplit_k<<<tgrid, tblk>>>(w_x, BhX, BlX, WW, LL, 0, 0);
    // slot 3: GEMM -> Y (gelu)
    gemm_tc<1><<<bigGrid, 512, GEMM_SMEM>>>(Ah, Al, BhY, BlY, b_y, Y, WW, WW, WW, LL);
    // slot 4: GEMM -> XB
    gemm_tc<0><<<bigGrid, 512, GEMM_SMEM>>>(Ah, Al, BhX, BlX, b_x, XB, WW, WW, WW, LL);
    // slot 5: conv -> bf16 hi/lo split into Ah/Al
    {
        long tot = (long)MTOT * L4C;
        conv_k<<<(int)((tot + 255) / 256), 256>>>((const float4*)XB, (const float4*)conv_w,
                                                  (const float4*)conv_b,
                                                  (uint2*)Ah, (uint2*)Al);
    }
    // slots 6-7: gate weight transposes
    tsplit_k<<<ggrid, tblk>>>(igate_w, GW1h, GW1l, HD, HD, (long)HD * HD, (long)HD * HD);
    tsplit_k<<<ggrid, tblk>>>(agate_w, GW2h, GW2l, HD, HD, (long)HD * HD, (long)HD * HD);
    // slot 8: dual gate GEMM with fused combine
    gate_tc<<<gateGrid, 256, GATE_SMEM>>>(Ah, Al, GW1h, GW1l, GW2h, GW2l,
                                          igate_b, agate_b, a_param, seg, G1, G2);
    // slots 9-11: chunked scan ; pass 3 fused with h*y and split into Ah/Al
    {
        long tot = (long)BB * NCH * LL;
        int blocks = (int)((tot + 255) / 256);
        scan_p1<<<blocks, 256>>>(G2, G1, Aagg, Hend);
        scan_p2<<<(BB * LL + 255) / 256, 256>>>(Aagg, Hend, Cin);
        scan_p3f<<<blocks, 256>>>(G2, G1, Cin, Y, Ah, Al);
    }
    // slot 12: w_out^T split (reuse Y-weight buffers)
    tsplit_k<<<tgrid, tblk>>>(w_out, BhY, BlY, LL, WW, 0, 0);
    // slot 13: final GEMM -> out
    gemm_tc<0><<<bigGrid, 512, GEMM_SMEM>>>(Ah, Al, BhY, BlY, b_out, out, LL, LL, LL, WW);
}

// round 10
// speedup vs baseline: 1.3603x; 1.3603x over previous
#include <cuda_runtime.h>
#include <cuda_bf16.h>
#include <cuda_fp16.h>
#include <math.h>
#include <stdint.h>

// Problem constants
#define BB 2
#define TT 4096
#define WW 2048
#define LL 2048
#define HH 8
#define TWD 4
#define HD 256                 // LL / HH
#define MTOT (BB * TT)         // 8192 rows
#define ELEMS ((size_t)MTOT * LL)  // 16,777,216
#define L4C (LL / 4)           // 512

#define SCH 128                // scan chunk length
#define NCH (TT / SCH)         // 32 chunks

// ---------------------------------------------------------------------------
// Scratch buffers (static device globals — no runtime allocation)
// ---------------------------------------------------------------------------
__device__ float g_Y[ELEMS];      // gelu(x @ w_y + b_y)
__device__ float g_XB[ELEMS];     // x @ w_x + b_x
__device__ float g_G1[ELEMS];     // normed
__device__ float g_G2[ELEMS];     // a_masked

__device__ __half g_Ah[ELEMS];            // fp16 hi split of current A operand
__device__ __half g_Al[ELEMS];            // fp16 lo split (residual)
__device__ __half g_BY[(size_t)LL * WW];  // transposed w_y fp16 [N,K] (reused for w_out)
__device__ __half g_BX[(size_t)LL * WW];  // transposed w_x fp16 [N,K]
__device__ __half g_GW1[(size_t)HH * HD * HD];
__device__ __half g_GW2[(size_t)HH * HD * HD];

__device__ float g_Aagg[(size_t)BB * NCH * LL];
__device__ float g_Hend[(size_t)BB * NCH * LL];
__device__ float g_Cin [(size_t)BB * NCH * LL];

// ---------------------------------------------------------------------------
// Low-level helpers (sm_80-portable: ldmatrix / mma.sync / cp.async only)
// ---------------------------------------------------------------------------
__device__ __forceinline__ uint32_t smem_u32(const void* p) {
    uint32_t a;
    asm("{ .reg .u64 t; cvta.to.shared.u64 t, %1; cvt.u32.u64 %0, t; }" : "=r"(a) : "l"(p));
    return a;
}
__device__ __forceinline__ void cp_async16(uint32_t saddr, const void* gaddr) {
    asm volatile("cp.async.cg.shared.global [%0], [%1], 16;" :: "r"(saddr), "l"(gaddr) : "memory");
}
__device__ __forceinline__ void ldm_x4(uint32_t* r, uint32_t addr) {
    asm volatile("ldmatrix.sync.aligned.m8n8.x4.shared.b16 {%0,%1,%2,%3}, [%4];"
                 : "=r"(r[0]), "=r"(r[1]), "=r"(r[2]), "=r"(r[3]) : "r"(addr));
}
// fp16 inputs, fp32 accumulate
__device__ __forceinline__ void mma16816(float* c, const uint32_t* a, const uint32_t* b) {
    asm volatile("mma.sync.aligned.m16n8k16.row.col.f32.f16.f16.f32 "
                 "{%0,%1,%2,%3}, {%4,%5,%6,%7}, {%8,%9}, {%0,%1,%2,%3};"
                 : "+f"(c[0]), "+f"(c[1]), "+f"(c[2]), "+f"(c[3])
                 : "r"(a[0]), "r"(a[1]), "r"(a[2]), "r"(a[3]), "r"(b[0]), "r"(b[1]));
}

// ---------------------------------------------------------------------------
// Big GEMM: C[m,n] = EPI( sum_k A[m,k]*B[n,k] + bias[n] )
// 2xfp16 split (Ah*Bh + Al*Bh = A*Bh), fp32 accum. Error ~ A*Bl ~ 2^-12.
// Tile 128x128x64, 256 threads, 8 warps of 64x32, 3-stage cp.async pipeline.
// 3 matrices per stage (Ah, Al, Bh). SMEM rows padded to 144 B.
// ---------------------------------------------------------------------------
#define BKK 64
#define ROWB 144                       // padded row bytes (64*2 + 16)
#define MATB (128 * ROWB)              // 18432 bytes per matrix tile
#define STAGEB (3 * MATB)              // 55296 bytes per stage
#define NSTAGE 3
#define GEMM_SMEM (NSTAGE * STAGEB)    // 165888 bytes

template <int EPI>
__global__ __launch_bounds__(256, 1)
void gemm_tc(const __half* __restrict__ Ah, const __half* __restrict__ Al,
             const __half* __restrict__ Bh,
             const float* __restrict__ bias, float* __restrict__ C,
             int K, int lda, int ldb, int ldc)
{
    extern __shared__ char sm[];
    const uint32_t sbase = smem_u32(sm);
    const int tid  = threadIdx.x;
    const int lane = tid & 31;
    const int wid  = tid >> 5;
    const int m0 = blockIdx.y * 128;
    const int n0 = blockIdx.x * 128;

    const __half* AbH = Ah + (size_t)m0 * lda;
    const __half* AbL = Al + (size_t)m0 * lda;
    const __half* BbH = Bh + (size_t)n0 * ldb;

    const int NIT = K / BKK;

    auto load_stage = [&](int it, int buf) {
        const int k0 = it * BKK;
        const __half* srcs[3] = {AbH, AbL, BbH};
#pragma unroll
        for (int mt = 0; mt < 3; mt++) {
            const int ld = (mt < 2) ? lda : ldb;
            const __half* src = srcs[mt];
#pragma unroll
            for (int i = 0; i < 4; i++) {
                int c = tid + 256 * i;           // 0..1023
                int row = c >> 3, col = c & 7;
                uint32_t sa = sbase + buf * STAGEB + mt * MATB + row * ROWB + col * 16;
                cp_async16(sa, src + (size_t)row * ld + k0 + col * 8);
            }
        }
        asm volatile("cp.async.commit_group;" ::: "memory");
    };

    const int m0w = (wid & 1) * 64;
    const int n0w = (wid >> 1) * 32;

    float acc[4][4][4];
#pragma unroll
    for (int i = 0; i < 4; i++)
#pragma unroll
        for (int j = 0; j < 4; j++)
#pragma unroll
            for (int e = 0; e < 4; e++) acc[i][j][e] = 0.f;

    load_stage(0, 0);
    if (NIT > 1) load_stage(1, 1);

    for (int it = 0; it < NIT; it++) {
        if (it + 1 < NIT) asm volatile("cp.async.wait_group 1;" ::: "memory");
        else              asm volatile("cp.async.wait_group 0;" ::: "memory");
        __syncthreads();
        if (it + 2 < NIT) load_stage(it + 2, (it + 2) % NSTAGE);

        const int buf = it % NSTAGE;
        const uint32_t sAh = sbase + buf * STAGEB;
        const uint32_t sAl = sAh + MATB;
        const uint32_t sBh = sAh + 2 * MATB;

#pragma unroll
        for (int ks = 0; ks < BKK; ks += 16) {
            uint32_t ah[4][4], al[4][4], bh[4][2];
            const uint32_t aoff = (uint32_t)(lane & 15) * ROWB + (uint32_t)ks * 2
                                + (uint32_t)(lane >> 4) * 16;
#pragma unroll
            for (int mf = 0; mf < 4; mf++) {
                uint32_t ad = (uint32_t)(m0w + mf * 16) * ROWB + aoff;
                ldm_x4(ah[mf], sAh + ad);
                ldm_x4(al[mf], sAl + ad);
            }
            const uint32_t boff = (uint32_t)(((lane >> 4) << 3) + (lane & 7)) * ROWB
                                + (uint32_t)ks * 2 + (uint32_t)((lane >> 3) & 1) * 16;
#pragma unroll
            for (int nf2 = 0; nf2 < 2; nf2++) {
                uint32_t bd = (uint32_t)(n0w + nf2 * 16) * ROWB + boff;
                uint32_t rh[4];
                ldm_x4(rh, sBh + bd);
                bh[nf2 * 2][0] = rh[0]; bh[nf2 * 2][1] = rh[1];
                bh[nf2 * 2 + 1][0] = rh[2]; bh[nf2 * 2 + 1][1] = rh[3];
            }
#pragma unroll
            for (int mf = 0; mf < 4; mf++)
#pragma unroll
                for (int nf = 0; nf < 4; nf++)
                    mma16816(acc[mf][nf], ah[mf], bh[nf]);
#pragma unroll
            for (int mf = 0; mf < 4; mf++)
#pragma unroll
                for (int nf = 0; nf < 4; nf++)
                    mma16816(acc[mf][nf], al[mf], bh[nf]);
        }
    }

    // epilogue: bias + activation, direct float2 stores
    const int rbase = m0 + m0w + (lane >> 2);
    const int cbase = n0 + n0w + (lane & 3) * 2;
#pragma unroll
    for (int mf = 0; mf < 4; mf++) {
#pragma unroll
        for (int nf = 0; nf < 4; nf++) {
            int col = cbase + nf * 8;
            float b0 = bias[col], b1 = bias[col + 1];
            float v[4] = {acc[mf][nf][0] + b0, acc[mf][nf][1] + b1,
                          acc[mf][nf][2] + b0, acc[mf][nf][3] + b1};
#pragma unroll
            for (int e = 0; e < 4; e++) {
                if (EPI == 1) {
                    float x = v[e];
                    float t = tanhf(0.7978845608028654f * (x + 0.044715f * x * x * x));
                    v[e] = 0.5f * x * (1.f + t);
                }
            }
            int r0 = rbase + mf * 16;
            *(float2*)&C[(size_t)r0 * ldc + col]       = make_float2(v[0], v[1]);
            *(float2*)&C[(size_t)(r0 + 8) * ldc + col] = make_float2(v[2], v[3]);
        }
    }
}

// ---------------------------------------------------------------------------
// Dual gate GEMM + fused combine epilogue. 2xfp16 split.
// 4 matrices per stage (Ah, Al, W1, W2). conv reconstructed as Ah+Al (~exact).
// ---------------------------------------------------------------------------
#define GMATB (128 * ROWB)             // 18432
#define GSTAGEB (4 * GMATB)            // 73728
#define GATE_SMEM (2 * GSTAGEB)        // 147456

__global__ __launch_bounds__(256, 1)
void gate_tc(const __half* __restrict__ cAh, const __half* __restrict__ cAl,
             const __half* __restrict__ W1, const __half* __restrict__ W2,
             const float* __restrict__ ib, const float* __restrict__ ab,
             const float* __restrict__ a_param, const int* __restrict__ seg,
             float* __restrict__ G1, float* __restrict__ G2)
{
    extern __shared__ char sm[];
    const uint32_t sbase = smem_u32(sm);
    const int tid  = threadIdx.x;
    const int lane = tid & 31;
    const int wid  = tid >> 5;
    const int z  = blockIdx.z;           // head
    const int m0 = blockIdx.y * 128;
    const int n0 = blockIdx.x * 128;     // 0 or 128 within head

    const __half* AbH = cAh + (size_t)m0 * LL + z * HD;
    const __half* AbL = cAl + (size_t)m0 * LL + z * HD;
    const __half* B1  = W1 + (size_t)z * HD * HD + (size_t)n0 * HD;
    const __half* B2  = W2 + (size_t)z * HD * HD + (size_t)n0 * HD;

    const int NIT = HD / BKK;   // 4

    auto load_stage = [&](int it, int buf) {
        const int k0 = it * BKK;
        const __half* srcs[4] = {AbH, AbL, B1, B2};
#pragma unroll
        for (int mt = 0; mt < 4; mt++) {
            const int ld = (mt < 2) ? LL : HD;
            const __half* src = srcs[mt];
#pragma unroll
            for (int i = 0; i < 4; i++) {
                int c = tid + 256 * i;
                int row = c >> 3, col = c & 7;
                uint32_t sa = sbase + buf * GSTAGEB + mt * GMATB + row * ROWB + col * 16;
                cp_async16(sa, src + (size_t)row * ld + k0 + col * 8);
            }
        }
        asm volatile("cp.async.commit_group;" ::: "memory");
    };

    const int m0w = (wid & 1) * 64;
    const int n0w = (wid >> 1) * 32;

    float acc[2][4][4][4];
#pragma unroll
    for (int s = 0; s < 2; s++)
#pragma unroll
        for (int i = 0; i < 4; i++)
#pragma unroll
            for (int j = 0; j < 4; j++)
#pragma unroll
                for (int e = 0; e < 4; e++) acc[s][i][j][e] = 0.f;

    load_stage(0, 0);
    load_stage(1, 1);

    for (int it = 0; it < NIT; it++) {
        if (it + 1 < NIT) asm volatile("cp.async.wait_group 1;" ::: "memory");
        else              asm volatile("cp.async.wait_group 0;" ::: "memory");
        __syncthreads();

        const int buf = it & 1;
        const uint32_t sA = sbase + buf * GSTAGEB;

#pragma unroll
        for (int ks = 0; ks < BKK; ks += 16) {
            uint32_t ah[4][4], al[4][4];
            const uint32_t aoff = (uint32_t)(lane & 15) * ROWB + (uint32_t)ks * 2
                                + (uint32_t)(lane >> 4) * 16;
#pragma unroll
            for (int mf = 0; mf < 4; mf++) {
                uint32_t ad = (uint32_t)(m0w + mf * 16) * ROWB + aoff;
                ldm_x4(ah[mf], sA + ad);
                ldm_x4(al[mf], sA + GMATB + ad);
            }
            const uint32_t boff = (uint32_t)(((lane >> 4) << 3) + (lane & 7)) * ROWB
                                + (uint32_t)ks * 2 + (uint32_t)((lane >> 3) & 1) * 16;
#pragma unroll
            for (int s = 0; s < 2; s++) {
                uint32_t bh[4][2];
                const uint32_t sB = sA + (2 + s) * GMATB;
#pragma unroll
                for (int nf2 = 0; nf2 < 2; nf2++) {
                    uint32_t bd = (uint32_t)(n0w + nf2 * 16) * ROWB + boff;
                    uint32_t rh[4];
                    ldm_x4(rh, sB + bd);
                    bh[nf2 * 2][0] = rh[0]; bh[nf2 * 2][1] = rh[1];
                    bh[nf2 * 2 + 1][0] = rh[2]; bh[nf2 * 2 + 1][1] = rh[3];
                }
#pragma unroll
                for (int mf = 0; mf < 4; mf++)
#pragma unroll
                    for (int nf = 0; nf < 4; nf++)
                        mma16816(acc[s][mf][nf], ah[mf], bh[nf]);
#pragma unroll
                for (int mf = 0; mf < 4; mf++)
#pragma unroll
                    for (int nf = 0; nf < 4; nf++)
                        mma16816(acc[s][mf][nf], al[mf], bh[nf]);
            }
        }
        __syncthreads();
        if (it + 2 < NIT) load_stage(it + 2, it & 1);
    }

    // fused combine epilogue (conv reconstructed from fp16 hi/lo split)
    const int rbase = m0 + m0w + (lane >> 2);          // global row
    const int cloc0 = n0 + n0w + (lane & 3) * 2;       // col within head
#pragma unroll
    for (int mf = 0; mf < 4; mf++) {
#pragma unroll
        for (int half = 0; half < 2; half++) {
            int row = rbase + mf * 16 + half * 8;
            bool reset = (seg[row] == 0);
#pragma unroll
            for (int nf = 0; nf < 4; nf++) {
                int cl = cloc0 + nf * 8;               // col within head (0..255)
                size_t go = (size_t)row * LL + (size_t)z * HD + cl;
                uint32_t chp = *(const uint32_t*)&cAh[go];
                uint32_t clp = *(const uint32_t*)&cAl[go];
                float outn[2], outa[2];
#pragma unroll
                for (int e = 0; e < 2; e++) {
                    float c1 = acc[0][mf][nf][half * 2 + e] + ib[z * HD + cl + e];
                    float c2 = acc[1][mf][nf][half * 2 + e] + ab[z * HD + cl + e];
                    float gi = 1.f / (1.f + expf(-c1));
                    float ga = 1.f / (1.f + expf(-c2));
                    float ap = a_param[z * HD + cl + e];
                    float sp = log1pf(expf(ap));
                    float la = -8.f * ga * sp;
                    float a = expf(la);
                    float mult = reset ? 1.f : sqrtf(fmaxf(1.f - expf(2.f * la), 0.f));
                    uint16_t hb = (uint16_t)((e == 0) ? (chp & 0xFFFF) : (chp >> 16));
                    uint16_t lb = (uint16_t)((e == 0) ? (clp & 0xFFFF) : (clp >> 16));
                    float cvv = __half2float(__ushort_as_half(hb))
                              + __half2float(__ushort_as_half(lb));
                    outn[e] = cvv * gi * mult;
                    outa[e] = reset ? 0.f : a;
                }
                *(float2*)&G1[go] = make_float2(outn[0], outn[1]);
                *(float2*)&G2[go] = make_float2(outa[0], outa[1]);
            }
        }
    }
}

// ---------------------------------------------------------------------------
// f32 -> fp16 hi/lo split (vectorized x4)
// ---------------------------------------------------------------------------
__device__ __forceinline__ uint32_t pk2h(__half a, __half b) {
    return (uint32_t)__half_as_ushort(a) | ((uint32_t)__half_as_ushort(b) << 16);
}
__device__ __forceinline__ void split_f4h(float4 v, uint2& H, uint2& L) {
    __half hx = __float2half_rn(v.x), hy = __float2half_rn(v.y);
    __half hz = __float2half_rn(v.z), hw = __float2half_rn(v.w);
    H.x = pk2h(hx, hy);
    H.y = pk2h(hz, hw);
    L.x = pk2h(__float2half_rn(v.x - __half2float(hx)), __float2half_rn(v.y - __half2float(hy)));
    L.y = pk2h(__float2half_rn(v.z - __half2float(hz)), __float2half_rn(v.w - __half2float(hw)));
}
__global__ void split4_k(const float4* __restrict__ in, uint2* __restrict__ oh,
                         uint2* __restrict__ ol, long n4)
{
    long i = (long)blockIdx.x * blockDim.x + threadIdx.x;
    if (i >= n4) return;
    uint2 H, L;
    split_f4h(in[i], H, L);
    oh[i] = H; ol[i] = L;
}

// ---------------------------------------------------------------------------
// Transposing convert: in [K,N] f32 -> out [N,K] fp16 (batched)
// ---------------------------------------------------------------------------
__global__ void tsplit_k(const float* __restrict__ in, __half* __restrict__ oh,
                         int K, int N, long inBatch, long outBatch)
{
    __shared__ float t[32][33];
    int z = blockIdx.z;
    const float* ib = in + (long)z * inBatch;
    int kb = blockIdx.y * 32, nb = blockIdx.x * 32;
    for (int i = threadIdx.y; i < 32; i += 8)
        t[i][threadIdx.x] = ib[(size_t)(kb + i) * N + nb + threadIdx.x];
    __syncthreads();
    for (int i = threadIdx.y; i < 32; i += 8) {
        int n = nb + i, k = kb + threadIdx.x;
        size_t o = (long)z * outBatch + (size_t)n * K + k;
        oh[o] = __float2half_rn(t[threadIdx.x][i]);
    }
}

// ---------------------------------------------------------------------------
// Causal depthwise temporal conv (TW=4) -> fp16 hi/lo split output
// ---------------------------------------------------------------------------
__global__ void conv_k(const float4* __restrict__ xb, const float4* __restrict__ cw,
                       const float4* __restrict__ cb,
                       uint2* __restrict__ oh, uint2* __restrict__ ol)
{
    long idx = (long)blockIdx.x * blockDim.x + threadIdx.x;
    if (idx >= (long)MTOT * L4C) return;
    int l4 = (int)(idx % L4C);
    int m = (int)(idx / L4C);
    int t = m % TT;
    float4 acc = cb[l4];
#pragma unroll
    for (int j = 0; j < TWD; j++) {
        int dt = TWD - 1 - j;
        if (t - dt >= 0) {
            float4 w = cw[j * L4C + l4];
            float4 x = xb[(long)(m - dt) * L4C + l4];
            acc.x = fmaf(w.x, x.x, acc.x);
            acc.y = fmaf(w.y, x.y, acc.y);
            acc.z = fmaf(w.z, x.z, acc.z);
            acc.w = fmaf(w.w, x.w, acc.w);
        }
    }
    uint2 H, L;
    split_f4h(acc, H, L);
    oh[idx] = H; ol[idx] = L;
}

// ---------------------------------------------------------------------------
// Chunked scan (scalar over L): h_t = a_t h_{t-1} + x_t
// Pass 3 fused with elementwise gate (h*y) and fp16 split for the final GEMM.
// ---------------------------------------------------------------------------
__global__ void scan_p1(const float* __restrict__ a, const float* __restrict__ x,
                        float* __restrict__ Aagg, float* __restrict__ Hend)
{
    long idx = (long)blockIdx.x * blockDim.x + threadIdx.x;  // over B*NCH*L
    if (idx >= (long)BB * NCH * LL) return;
    int l = (int)(idx % LL);
    int r = (int)(idx / LL);
    int c = r % NCH, b = r / NCH;
    size_t base = ((size_t)b * TT + (size_t)c * SCH) * LL + l;
    float h = 0.f, ap = 1.f;
#pragma unroll 4
    for (int t = 0; t < SCH; t++) {
        float av = a[base + (size_t)t * LL];
        h = fmaf(av, h, x[base + (size_t)t * LL]);
        ap *= av;
    }
    Aagg[idx] = ap; Hend[idx] = h;
}
__global__ void scan_p2(const float* __restrict__ Aagg, const float* __restrict__ Hend,
                        float* __restrict__ Cin)
{
    int idx = blockIdx.x * blockDim.x + threadIdx.x;
    if (idx >= BB * LL) return;
    int l = idx % LL, b = idx / LL;
    float cin = 0.f;
    for (int c = 0; c < NCH; c++) {
        size_t j = ((size_t)b * NCH + c) * LL + l;
        Cin[j] = cin;
        cin = fmaf(Aagg[j], cin, Hend[j]);
    }
}
__global__ void scan_p3f(const float* __restrict__ a, const float* __restrict__ x,
                         const float* __restrict__ Cin, const float* __restrict__ y,
                         __half* __restrict__ oh, __half* __restrict__ ol)
{
    long idx = (long)blockIdx.x * blockDim.x + threadIdx.x;
    if (idx >= (long)BB * NCH * LL) return;
    int l = (int)(idx % LL);
    int r = (int)(idx / LL);
    int c = r % NCH, b = r / NCH;
    size_t base = ((size_t)b * TT + (size_t)c * SCH) * LL + l;
    float h = Cin[idx];
#pragma unroll 4
    for (int t = 0; t < SCH; t++) {
        size_t o = base + (size_t)t * LL;
        h = fmaf(a[o], h, x[o]);
        float v = h * y[o];
        __half hi = __float2half_rn(v);
        oh[o] = hi;
        ol[o] = __float2half_rn(v - __half2float(hi));
    }
}

// ---------------------------------------------------------------------------
// Launch (big GEMMs in launch slots 3 and 4 for ncu window)
// ---------------------------------------------------------------------------
extern "C" void kernel_launch(void* const* d_in, const int* in_sizes, int n_in,
                              void* d_out, int out_size)
{
    const float* x       = (const float*)d_in[0];
    const int*   seg     = (const int*)  d_in[1];
    const float* w_y     = (const float*)d_in[2];
    const float* b_y     = (const float*)d_in[3];
    const float* w_x     = (const float*)d_in[4];
    const float* b_x     = (const float*)d_in[5];
    const float* w_out   = (const float*)d_in[6];
    const float* b_out   = (const float*)d_in[7];
    const float* conv_w  = (const float*)d_in[8];
    const float* conv_b  = (const float*)d_in[9];
    const float* a_param = (const float*)d_in[10];
    const float* igate_w = (const float*)d_in[11];
    const float* igate_b = (const float*)d_in[12];
    const float* agate_w = (const float*)d_in[13];
    const float* agate_b = (const float*)d_in[14];
    float* out = (float*)d_out;

    float *Y, *XB, *G1, *G2, *Aagg, *Hend, *Cin;
    __half *Ah, *Al, *BY, *BX, *GW1, *GW2;
    cudaGetSymbolAddress((void**)&Y, g_Y);
    cudaGetSymbolAddress((void**)&XB, g_XB);
    cudaGetSymbolAddress((void**)&G1, g_G1);
    cudaGetSymbolAddress((void**)&G2, g_G2);
    cudaGetSymbolAddress((void**)&Ah, g_Ah);
    cudaGetSymbolAddress((void**)&Al, g_Al);
    cudaGetSymbolAddress((void**)&BY, g_BY);
    cudaGetSymbolAddress((void**)&BX, g_BX);
    cudaGetSymbolAddress((void**)&GW1, g_GW1);
    cudaGetSymbolAddress((void**)&GW2, g_GW2);
    cudaGetSymbolAddress((void**)&Aagg, g_Aagg);
    cudaGetSymbolAddress((void**)&Hend, g_Hend);
    cudaGetSymbolAddress((void**)&Cin, g_Cin);

    cudaFuncSetAttribute(gemm_tc<0>, cudaFuncAttributeMaxDynamicSharedMemorySize, GEMM_SMEM);
    cudaFuncSetAttribute(gemm_tc<1>, cudaFuncAttributeMaxDynamicSharedMemorySize, GEMM_SMEM);
    cudaFuncSetAttribute(gate_tc, cudaFuncAttributeMaxDynamicSharedMemorySize, GATE_SMEM);

    const long n4 = (long)ELEMS / 4;
    const int eb = (int)((n4 + 255) / 256);
    dim3 tgrid(WW / 32, WW / 32, 1);
    dim3 tblk(32, 8, 1);
    dim3 bigGrid(LL / 128, MTOT / 128, 1);     // (16, 64)
    dim3 gateGrid(HD / 128, MTOT / 128, HH);   // (2, 64, 8)
    dim3 ggrid(HD / 32, HD / 32, HH);

    // slot 0: w_y^T convert
    tsplit_k<<<tgrid, tblk>>>(w_y, BY, WW, LL, 0, 0);
    // slot 1: split x -> Ah/Al
    split4_k<<<eb, 256>>>((const float4*)x, (uint2*)Ah, (uint2*)Al, n4);
    // slot 2: w_x^T convert
    tsplit_k<<<tgrid, tblk>>>(w_x, BX, WW, LL, 0, 0);
    // slot 3: GEMM -> Y (gelu)
    gemm_tc<1><<<bigGrid, 256, GEMM_SMEM>>>(Ah, Al, BY, b_y, Y, WW, WW, WW, LL);
    // slot 4: GEMM -> XB
    gemm_tc<0><<<bigGrid, 256, GEMM_SMEM>>>(Ah, Al, BX, b_x, XB, WW, WW, WW, LL);
    // slot 5: conv -> fp16 hi/lo split into Ah/Al
    {
        long tot = (long)MTOT * L4C;
        conv_k<<<(int)((tot + 255) / 256), 256>>>((const float4*)XB, (const float4*)conv_w,
                                                  (const float4*)conv_b,
                                                  (uint2*)Ah, (uint2*)Al);
    }
    // slots 6-7: gate weight transposes
    tsplit_k<<<ggrid, tblk>>>(igate_w, GW1, HD, HD, (long)HD * HD, (long)HD * HD);
    tsplit_k<<<ggrid, tblk>>>(agate_w, GW2, HD, HD, (long)HD * HD, (long)HD * HD);
    // slot 8: dual gate GEMM with fused combine
    gate_tc<<<gateGrid, 256, GATE_SMEM>>>(Ah, Al, GW1, GW2,
                                          igate_b, agate_b, a_param, seg, G1, G2);
    // slots 9-11: chunked scan ; pass 3 fused with h*y and split into Ah/Al
    {
        long tot = (long)BB * NCH * LL;
        int blocks = (int)((tot + 255) / 256);
        scan_p1<<<blocks, 256>>>(G2, G1, Aagg, Hend);
        scan_p2<<<(BB * LL + 255) / 256, 256>>>(Aagg, Hend, Cin);
        scan_p3f<<<blocks, 256>>>(G2, G1, Cin, Y, Ah, Al);
    }
    // slot 12: w_out^T convert (reuse BY buffer)
    tsplit_k<<<tgrid, tblk>>>(w_out, BY, LL, WW, 0, 0);
    // slot 13: final GEMM -> out
    gemm_tc<0><<<bigGrid, 256, GEMM_SMEM>>>(Ah, Al, BY, b_out, out, LL, LL, LL, WW);
}

// round 11
// speedup vs baseline: 1.5208x; 1.1180x over previous
#include <cuda_runtime.h>
#include <cuda_bf16.h>
#include <cuda_fp16.h>
#include <math.h>
#include <stdint.h>

// Problem constants
#define BB 2
#define TT 4096
#define WW 2048
#define LL 2048
#define HH 8
#define TWD 4
#define HD 256                 // LL / HH
#define MTOT (BB * TT)         // 8192 rows
#define ELEMS ((size_t)MTOT * LL)  // 16,777,216
#define L4C (LL / 4)           // 512

#define SCH 128                // scan chunk length
#define NCH (TT / SCH)         // 32 chunks

// ---------------------------------------------------------------------------
// Scratch buffers (static device globals — no runtime allocation)
// ---------------------------------------------------------------------------
__device__ float g_Y[ELEMS];      // gelu(x @ w_y + b_y)
__device__ float g_XB[ELEMS];     // x @ w_x + b_x
__device__ float g_G1[ELEMS];     // normed
__device__ float g_G2[ELEMS];     // a_masked

__device__ __half g_Ah[ELEMS];            // fp16 hi split of current A operand
__device__ __half g_Al[ELEMS];            // fp16 lo split (residual)
__device__ __half g_BY[(size_t)LL * WW];  // transposed w_y fp16 [N,K] (reused for w_out)
__device__ __half g_BX[(size_t)LL * WW];  // transposed w_x fp16 [N,K]
__device__ __half g_GW1[(size_t)HH * HD * HD];
__device__ __half g_GW2[(size_t)HH * HD * HD];

__device__ float g_Aagg[(size_t)BB * NCH * LL];
__device__ float g_Hend[(size_t)BB * NCH * LL];
__device__ float g_Cin [(size_t)BB * NCH * LL];

// ---------------------------------------------------------------------------
// Low-level helpers (sm_80-portable: ldmatrix / mma.sync / cp.async only)
// ---------------------------------------------------------------------------
__device__ __forceinline__ uint32_t smem_u32(const void* p) {
    uint32_t a;
    asm("{ .reg .u64 t; cvta.to.shared.u64 t, %1; cvt.u32.u64 %0, t; }" : "=r"(a) : "l"(p));
    return a;
}
__device__ __forceinline__ void cp_async16(uint32_t saddr, const void* gaddr) {
    asm volatile("cp.async.cg.shared.global [%0], [%1], 16;" :: "r"(saddr), "l"(gaddr) : "memory");
}
__device__ __forceinline__ void ldm_x4(uint32_t* r, uint32_t addr) {
    asm volatile("ldmatrix.sync.aligned.m8n8.x4.shared.b16 {%0,%1,%2,%3}, [%4];"
                 : "=r"(r[0]), "=r"(r[1]), "=r"(r[2]), "=r"(r[3]) : "r"(addr));
}
// fp16 inputs, fp32 accumulate
__device__ __forceinline__ void mma16816(float* c, const uint32_t* a, const uint32_t* b) {
    asm volatile("mma.sync.aligned.m16n8k16.row.col.f32.f16.f16.f32 "
                 "{%0,%1,%2,%3}, {%4,%5,%6,%7}, {%8,%9}, {%0,%1,%2,%3};"
                 : "+f"(c[0]), "+f"(c[1]), "+f"(c[2]), "+f"(c[3])
                 : "r"(a[0]), "r"(a[1]), "r"(a[2]), "r"(a[3]), "r"(b[0]), "r"(b[1]));
}

// ---------------------------------------------------------------------------
// Big GEMM: C[m,n] = EPI( sum_k A[m,k]*B[n,k] + bias[n] )
// 2xfp16 split (Ah*Bh + Al*Bh = A*Bh), fp32 accum.
// Tile 128x128x64, 256 threads, 8 warps of 64x32.
// 2-stage cp.async pipeline + 2 CTAs/SM for cross-CTA bubble filling.
// 3 matrices per stage (Ah, Al, Bh). SMEM rows padded to 144 B.
// ---------------------------------------------------------------------------
#define BKK 64
#define ROWB 144                       // padded row bytes (64*2 + 16)
#define MATB (128 * ROWB)              // 18432 bytes per matrix tile
#define STAGEB (3 * MATB)              // 55296 bytes per stage
#define NSTAGE 2
#define GEMM_SMEM (NSTAGE * STAGEB)    // 110592 bytes -> 2 CTAs/SM

template <int EPI>
__global__ __launch_bounds__(256, 2)
void gemm_tc(const __half* __restrict__ Ah, const __half* __restrict__ Al,
             const __half* __restrict__ Bh,
             const float* __restrict__ bias, float* __restrict__ C,
             int K, int lda, int ldb, int ldc)
{
    extern __shared__ char sm[];
    const uint32_t sbase = smem_u32(sm);
    const int tid  = threadIdx.x;
    const int lane = tid & 31;
    const int wid  = tid >> 5;
    const int m0 = blockIdx.y * 128;
    const int n0 = blockIdx.x * 128;

    const __half* AbH = Ah + (size_t)m0 * lda;
    const __half* AbL = Al + (size_t)m0 * lda;
    const __half* BbH = Bh + (size_t)n0 * ldb;

    const int NIT = K / BKK;

    auto load_stage = [&](int it, int buf) {
        const int k0 = it * BKK;
        const __half* srcs[3] = {AbH, AbL, BbH};
#pragma unroll
        for (int mt = 0; mt < 3; mt++) {
            const int ld = (mt < 2) ? lda : ldb;
            const __half* src = srcs[mt];
#pragma unroll
            for (int i = 0; i < 4; i++) {
                int c = tid + 256 * i;           // 0..1023
                int row = c >> 3, col = c & 7;
                uint32_t sa = sbase + buf * STAGEB + mt * MATB + row * ROWB + col * 16;
                cp_async16(sa, src + (size_t)row * ld + k0 + col * 8);
            }
        }
        asm volatile("cp.async.commit_group;" ::: "memory");
    };

    const int m0w = (wid & 1) * 64;
    const int n0w = (wid >> 1) * 32;

    float acc[4][4][4];
#pragma unroll
    for (int i = 0; i < 4; i++)
#pragma unroll
        for (int j = 0; j < 4; j++)
#pragma unroll
            for (int e = 0; e < 4; e++) acc[i][j][e] = 0.f;

    load_stage(0, 0);
    if (NIT > 1) load_stage(1, 1);

    for (int it = 0; it < NIT; it++) {
        if (it + 1 < NIT) asm volatile("cp.async.wait_group 1;" ::: "memory");
        else              asm volatile("cp.async.wait_group 0;" ::: "memory");
        __syncthreads();

        const int buf = it & 1;
        const uint32_t sAh = sbase + buf * STAGEB;
        const uint32_t sAl = sAh + MATB;
        const uint32_t sBh = sAh + 2 * MATB;

#pragma unroll
        for (int ks = 0; ks < BKK; ks += 16) {
            uint32_t ah[4][4], al[4][4], bh[4][2];
            const uint32_t aoff = (uint32_t)(lane & 15) * ROWB + (uint32_t)ks * 2
                                + (uint32_t)(lane >> 4) * 16;
#pragma unroll
            for (int mf = 0; mf < 4; mf++) {
                uint32_t ad = (uint32_t)(m0w + mf * 16) * ROWB + aoff;
                ldm_x4(ah[mf], sAh + ad);
                ldm_x4(al[mf], sAl + ad);
            }
            const uint32_t boff = (uint32_t)(((lane >> 4) << 3) + (lane & 7)) * ROWB
                                + (uint32_t)ks * 2 + (uint32_t)((lane >> 3) & 1) * 16;
#pragma unroll
            for (int nf2 = 0; nf2 < 2; nf2++) {
                uint32_t bd = (uint32_t)(n0w + nf2 * 16) * ROWB + boff;
                uint32_t rh[4];
                ldm_x4(rh, sBh + bd);
                bh[nf2 * 2][0] = rh[0]; bh[nf2 * 2][1] = rh[1];
                bh[nf2 * 2 + 1][0] = rh[2]; bh[nf2 * 2 + 1][1] = rh[3];
            }
#pragma unroll
            for (int mf = 0; mf < 4; mf++)
#pragma unroll
                for (int nf = 0; nf < 4; nf++)
                    mma16816(acc[mf][nf], ah[mf], bh[nf]);
#pragma unroll
            for (int mf = 0; mf < 4; mf++)
#pragma unroll
                for (int nf = 0; nf < 4; nf++)
                    mma16816(acc[mf][nf], al[mf], bh[nf]);
        }
        __syncthreads();
        if (it + 2 < NIT) load_stage(it + 2, it & 1);
    }

    // epilogue: bias + activation, direct float2 stores
    const int rbase = m0 + m0w + (lane >> 2);
    const int cbase = n0 + n0w + (lane & 3) * 2;
#pragma unroll
    for (int mf = 0; mf < 4; mf++) {
#pragma unroll
        for (int nf = 0; nf < 4; nf++) {
            int col = cbase + nf * 8;
            float b0 = bias[col], b1 = bias[col + 1];
            float v[4] = {acc[mf][nf][0] + b0, acc[mf][nf][1] + b1,
                          acc[mf][nf][2] + b0, acc[mf][nf][3] + b1};
#pragma unroll
            for (int e = 0; e < 4; e++) {
                if (EPI == 1) {
                    float x = v[e];
                    float t = tanhf(0.7978845608028654f * (x + 0.044715f * x * x * x));
                    v[e] = 0.5f * x * (1.f + t);
                }
            }
            int r0 = rbase + mf * 16;
            *(float2*)&C[(size_t)r0 * ldc + col]       = make_float2(v[0], v[1]);
            *(float2*)&C[(size_t)(r0 + 8) * ldc + col] = make_float2(v[2], v[3]);
        }
    }
}

// ---------------------------------------------------------------------------
// Dual gate GEMM + fused combine epilogue. 2xfp16 split.
// 4 matrices per stage (Ah, Al, W1, W2). conv reconstructed as Ah+Al (~exact).
// ---------------------------------------------------------------------------
#define GMATB (128 * ROWB)             // 18432
#define GSTAGEB (4 * GMATB)            // 73728
#define GATE_SMEM (2 * GSTAGEB)        // 147456

__global__ __launch_bounds__(256, 1)
void gate_tc(const __half* __restrict__ cAh, const __half* __restrict__ cAl,
             const __half* __restrict__ W1, const __half* __restrict__ W2,
             const float* __restrict__ ib, const float* __restrict__ ab,
             const float* __restrict__ a_param, const int* __restrict__ seg,
             float* __restrict__ G1, float* __restrict__ G2)
{
    extern __shared__ char sm[];
    const uint32_t sbase = smem_u32(sm);
    const int tid  = threadIdx.x;
    const int lane = tid & 31;
    const int wid  = tid >> 5;
    const int z  = blockIdx.z;           // head
    const int m0 = blockIdx.y * 128;
    const int n0 = blockIdx.x * 128;     // 0 or 128 within head

    const __half* AbH = cAh + (size_t)m0 * LL + z * HD;
    const __half* AbL = cAl + (size_t)m0 * LL + z * HD;
    const __half* B1  = W1 + (size_t)z * HD * HD + (size_t)n0 * HD;
    const __half* B2  = W2 + (size_t)z * HD * HD + (size_t)n0 * HD;

    const int NIT = HD / BKK;   // 4

    auto load_stage = [&](int it, int buf) {
        const int k0 = it * BKK;
        const __half* srcs[4] = {AbH, AbL, B1, B2};
#pragma unroll
        for (int mt = 0; mt < 4; mt++) {
            const int ld = (mt < 2) ? LL : HD;
            const __half* src = srcs[mt];
#pragma unroll
            for (int i = 0; i < 4; i++) {
                int c = tid + 256 * i;
                int row = c >> 3, col = c & 7;
                uint32_t sa = sbase + buf * GSTAGEB + mt * GMATB + row * ROWB + col * 16;
                cp_async16(sa, src + (size_t)row * ld + k0 + col * 8);
            }
        }
        asm volatile("cp.async.commit_group;" ::: "memory");
    };

    const int m0w = (wid & 1) * 64;
    const int n0w = (wid >> 1) * 32;

    float acc[2][4][4][4];
#pragma unroll
    for (int s = 0; s < 2; s++)
#pragma unroll
        for (int i = 0; i < 4; i++)
#pragma unroll
            for (int j = 0; j < 4; j++)
#pragma unroll
                for (int e = 0; e < 4; e++) acc[s][i][j][e] = 0.f;

    load_stage(0, 0);
    load_stage(1, 1);

    for (int it = 0; it < NIT; it++) {
        if (it + 1 < NIT) asm volatile("cp.async.wait_group 1;" ::: "memory");
        else              asm volatile("cp.async.wait_group 0;" ::: "memory");
        __syncthreads();

        const int buf = it & 1;
        const uint32_t sA = sbase + buf * GSTAGEB;

#pragma unroll
        for (int ks = 0; ks < BKK; ks += 16) {
            uint32_t ah[4][4], al[4][4];
            const uint32_t aoff = (uint32_t)(lane & 15) * ROWB + (uint32_t)ks * 2
                                + (uint32_t)(lane >> 4) * 16;
#pragma unroll
            for (int mf = 0; mf < 4; mf++) {
                uint32_t ad = (uint32_t)(m0w + mf * 16) * ROWB + aoff;
                ldm_x4(ah[mf], sA + ad);
                ldm_x4(al[mf], sA + GMATB + ad);
            }
            const uint32_t boff = (uint32_t)(((lane >> 4) << 3) + (lane & 7)) * ROWB
                                + (uint32_t)ks * 2 + (uint32_t)((lane >> 3) & 1) * 16;
#pragma unroll
            for (int s = 0; s < 2; s++) {
                uint32_t bh[4][2];
                const uint32_t sB = sA + (2 + s) * GMATB;
#pragma unroll
                for (int nf2 = 0; nf2 < 2; nf2++) {
                    uint32_t bd = (uint32_t)(n0w + nf2 * 16) * ROWB + boff;
                    uint32_t rh[4];
                    ldm_x4(rh, sB + bd);
                    bh[nf2 * 2][0] = rh[0]; bh[nf2 * 2][1] = rh[1];
                    bh[nf2 * 2 + 1][0] = rh[2]; bh[nf2 * 2 + 1][1] = rh[3];
                }
#pragma unroll
                for (int mf = 0; mf < 4; mf++)
#pragma unroll
                    for (int nf = 0; nf < 4; nf++)
                        mma16816(acc[s][mf][nf], ah[mf], bh[nf]);
#pragma unroll
                for (int mf = 0; mf < 4; mf++)
#pragma unroll
                    for (int nf = 0; nf < 4; nf++)
                        mma16816(acc[s][mf][nf], al[mf], bh[nf]);
            }
        }
        __syncthreads();
        if (it + 2 < NIT) load_stage(it + 2, it & 1);
    }

    // fused combine epilogue (conv reconstructed from fp16 hi/lo split)
    const int rbase = m0 + m0w + (lane >> 2);          // global row
    const int cloc0 = n0 + n0w + (lane & 3) * 2;       // col within head
#pragma unroll
    for (int mf = 0; mf < 4; mf++) {
#pragma unroll
        for (int half = 0; half < 2; half++) {
            int row = rbase + mf * 16 + half * 8;
            bool reset = (seg[row] == 0);
#pragma unroll
            for (int nf = 0; nf < 4; nf++) {
                int cl = cloc0 + nf * 8;               // col within head (0..255)
                size_t go = (size_t)row * LL + (size_t)z * HD + cl;
                uint32_t chp = *(const uint32_t*)&cAh[go];
                uint32_t clp = *(const uint32_t*)&cAl[go];
                float outn[2], outa[2];
#pragma unroll
                for (int e = 0; e < 2; e++) {
                    float c1 = acc[0][mf][nf][half * 2 + e] + ib[z * HD + cl + e];
                    float c2 = acc[1][mf][nf][half * 2 + e] + ab[z * HD + cl + e];
                    float gi = 1.f / (1.f + expf(-c1));
                    float ga = 1.f / (1.f + expf(-c2));
                    float ap = a_param[z * HD + cl + e];
                    float sp = log1pf(expf(ap));
                    float la = -8.f * ga * sp;
                    float a = expf(la);
                    float mult = reset ? 1.f : sqrtf(fmaxf(1.f - expf(2.f * la), 0.f));
                    uint16_t hb = (uint16_t)((e == 0) ? (chp & 0xFFFF) : (chp >> 16));
                    uint16_t lb = (uint16_t)((e == 0) ? (clp & 0xFFFF) : (clp >> 16));
                    float cvv = __half2float(__ushort_as_half(hb))
                              + __half2float(__ushort_as_half(lb));
                    outn[e] = cvv * gi * mult;
                    outa[e] = reset ? 0.f : a;
                }
                *(float2*)&G1[go] = make_float2(outn[0], outn[1]);
                *(float2*)&G2[go] = make_float2(outa[0], outa[1]);
            }
        }
    }
}

// ---------------------------------------------------------------------------
// f32 -> fp16 hi/lo split (vectorized x4)
// ---------------------------------------------------------------------------
__device__ __forceinline__ uint32_t pk2h(__half a, __half b) {
    return (uint32_t)__half_as_ushort(a) | ((uint32_t)__half_as_ushort(b) << 16);
}
__device__ __forceinline__ void split_f4h(float4 v, uint2& H, uint2& L) {
    __half hx = __float2half_rn(v.x), hy = __float2half_rn(v.y);
    __half hz = __float2half_rn(v.z), hw = __float2half_rn(v.w);
    H.x = pk2h(hx, hy);
    H.y = pk2h(hz, hw);
    L.x = pk2h(__float2half_rn(v.x - __half2float(hx)), __float2half_rn(v.y - __half2float(hy)));
    L.y = pk2h(__float2half_rn(v.z - __half2float(hz)), __float2half_rn(v.w - __half2float(hw)));
}
__global__ void split4_k(const float4* __restrict__ in, uint2* __restrict__ oh,
                         uint2* __restrict__ ol, long n4)
{
    long i = (long)blockIdx.x * blockDim.x + threadIdx.x;
    if (i >= n4) return;
    uint2 H, L;
    split_f4h(in[i], H, L);
    oh[i] = H; ol[i] = L;
}

// ---------------------------------------------------------------------------
// Transposing convert: in [K,N] f32 -> out [N,K] fp16 (batched)
// ---------------------------------------------------------------------------
__global__ void tsplit_k(const float* __restrict__ in, __half* __restrict__ oh,
                         int K, int N, long inBatch, long outBatch)
{
    __shared__ float t[32][33];
    int z = blockIdx.z;
    const float* ib = in + (long)z * inBatch;
    int kb = blockIdx.y * 32, nb = blockIdx.x * 32;
    for (int i = threadIdx.y; i < 32; i += 8)
        t[i][threadIdx.x] = ib[(size_t)(kb + i) * N + nb + threadIdx.x];
    __syncthreads();
    for (int i = threadIdx.y; i < 32; i += 8) {
        int n = nb + i, k = kb + threadIdx.x;
        size_t o = (long)z * outBatch + (size_t)n * K + k;
        oh[o] = __float2half_rn(t[threadIdx.x][i]);
    }
}

// ---------------------------------------------------------------------------
// Causal depthwise temporal conv (TW=4) -> fp16 hi/lo split output
// ---------------------------------------------------------------------------
__global__ void conv_k(const float4* __restrict__ xb, const float4* __restrict__ cw,
                       const float4* __restrict__ cb,
                       uint2* __restrict__ oh, uint2* __restrict__ ol)
{
    long idx = (long)blockIdx.x * blockDim.x + threadIdx.x;
    if (idx >= (long)MTOT * L4C) return;
    int l4 = (int)(idx % L4C);
    int m = (int)(idx / L4C);
    int t = m % TT;
    float4 acc = cb[l4];
#pragma unroll
    for (int j = 0; j < TWD; j++) {
        int dt = TWD - 1 - j;
        if (t - dt >= 0) {
            float4 w = cw[j * L4C + l4];
            float4 x = xb[(long)(m - dt) * L4C + l4];
            acc.x = fmaf(w.x, x.x, acc.x);
            acc.y = fmaf(w.y, x.y, acc.y);
            acc.z = fmaf(w.z, x.z, acc.z);
            acc.w = fmaf(w.w, x.w, acc.w);
        }
    }
    uint2 H, L;
    split_f4h(acc, H, L);
    oh[idx] = H; ol[idx] = L;
}

// ---------------------------------------------------------------------------
// Chunked scan (scalar over L): h_t = a_t h_{t-1} + x_t
// Pass 3 fused with elementwise gate (h*y) and fp16 split for the final GEMM.
// ---------------------------------------------------------------------------
__global__ void scan_p1(const float* __restrict__ a, const float* __restrict__ x,
                        float* __restrict__ Aagg, float* __restrict__ Hend)
{
    long idx = (long)blockIdx.x * blockDim.x + threadIdx.x;  // over B*NCH*L
    if (idx >= (long)BB * NCH * LL) return;
    int l = (int)(idx % LL);
    int r = (int)(idx / LL);
    int c = r % NCH, b = r / NCH;
    size_t base = ((size_t)b * TT + (size_t)c * SCH) * LL + l;
    float h = 0.f, ap = 1.f;
#pragma unroll 4
    for (int t = 0; t < SCH; t++) {
        float av = a[base + (size_t)t * LL];
        h = fmaf(av, h, x[base + (size_t)t * LL]);
        ap *= av;
    }
    Aagg[idx] = ap; Hend[idx] = h;
}
__global__ void scan_p2(const float* __restrict__ Aagg, const float* __restrict__ Hend,
                        float* __restrict__ Cin)
{
    int idx = blockIdx.x * blockDim.x + threadIdx.x;
    if (idx >= BB * LL) return;
    int l = idx % LL, b = idx / LL;
    float cin = 0.f;
    for (int c = 0; c < NCH; c++) {
        size_t j = ((size_t)b * NCH + c) * LL + l;
        Cin[j] = cin;
        cin = fmaf(Aagg[j], cin, Hend[j]);
    }
}
__global__ void scan_p3f(const float* __restrict__ a, const float* __restrict__ x,
                         const float* __restrict__ Cin, const float* __restrict__ y,
                         __half* __restrict__ oh, __half* __restrict__ ol)
{
    long idx = (long)blockIdx.x * blockDim.x + threadIdx.x;
    if (idx >= (long)BB * NCH * LL) return;
    int l = (int)(idx % LL);
    int r = (int)(idx / LL);
    int c = r % NCH, b = r / NCH;
    size_t base = ((size_t)b * TT + (size_t)c * SCH) * LL + l;
    float h = Cin[idx];
#pragma unroll 4
    for (int t = 0; t < SCH; t++) {
        size_t o = base + (size_t)t * LL;
        h = fmaf(a[o], h, x[o]);
        float v = h * y[o];
        __half hi = __float2half_rn(v);
        oh[o] = hi;
        ol[o] = __float2half_rn(v - __half2float(hi));
    }
}

// ---------------------------------------------------------------------------
// Launch (big GEMMs in launch slots 3 and 4 for ncu window)
// ---------------------------------------------------------------------------
extern "C" void kernel_launch(void* const* d_in, const int* in_sizes, int n_in,
                              void* d_out, int out_size)
{
    const float* x       = (const float*)d_in[0];
    const int*   seg     = (const int*)  d_in[1];
    const float* w_y     = (const float*)d_in[2];
    const float* b_y     = (const float*)d_in[3];
    const float* w_x     = (const float*)d_in[4];
    const float* b_x     = (const float*)d_in[5];
    const float* w_out   = (const float*)d_in[6];
    const float* b_out   = (const float*)d_in[7];
    const float* conv_w  = (const float*)d_in[8];
    const float* conv_b  = (const float*)d_in[9];
    const float* a_param = (const float*)d_in[10];
    const float* igate_w = (const float*)d_in[11];
    const float* igate_b = (const float*)d_in[12];
    const float* agate_w = (const float*)d_in[13];
    const float* agate_b = (const float*)d_in[14];
    float* out = (float*)d_out;

    float *Y, *XB, *G1, *G2, *Aagg, *Hend, *Cin;
    __half *Ah, *Al, *BY, *BX, *GW1, *GW2;
    cudaGetSymbolAddress((void**)&Y, g_Y);
    cudaGetSymbolAddress((void**)&XB, g_XB);
    cudaGetSymbolAddress((void**)&G1, g_G1);
    cudaGetSymbolAddress((void**)&G2, g_G2);
    cudaGetSymbolAddress((void**)&Ah, g_Ah);
    cudaGetSymbolAddress((void**)&Al, g_Al);
    cudaGetSymbolAddress((void**)&BY, g_BY);
    cudaGetSymbolAddress((void**)&BX, g_BX);
    cudaGetSymbolAddress((void**)&GW1, g_GW1);
    cudaGetSymbolAddress((void**)&GW2, g_GW2);
    cudaGetSymbolAddress((void**)&Aagg, g_Aagg);
    cudaGetSymbolAddress((void**)&Hend, g_Hend);
    cudaGetSymbolAddress((void**)&Cin, g_Cin);

    cudaFuncSetAttribute(gemm_tc<0>, cudaFuncAttributeMaxDynamicSharedMemorySize, GEMM_SMEM);
    cudaFuncSetAttribute(gemm_tc<1>, cudaFuncAttributeMaxDynamicSharedMemorySize, GEMM_SMEM);
    cudaFuncSetAttribute(gate_tc, cudaFuncAttributeMaxDynamicSharedMemorySize, GATE_SMEM);

    const long n4 = (long)ELEMS / 4;
    const int eb = (int)((n4 + 255) / 256);
    dim3 tgrid(WW / 32, WW / 32, 1);
    dim3 tblk(32, 8, 1);
    dim3 bigGrid(LL / 128, MTOT / 128, 1);     // (16, 64)
    dim3 gateGrid(HD / 128, MTOT / 128, HH);   // (2, 64, 8)
    dim3 ggrid(HD / 32, HD / 32, HH);

    // slot 0: w_y^T convert
    tsplit_k<<<tgrid, tblk>>>(w_y, BY, WW, LL, 0, 0);
    // slot 1: split x -> Ah/Al
    split4_k<<<eb, 256>>>((const float4*)x, (uint2*)Ah, (uint2*)Al, n4);
    // slot 2: w_x^T convert
    tsplit_k<<<tgrid, tblk>>>(w_x, BX, WW, LL, 0, 0);
    // slot 3: GEMM -> Y (gelu)
    gemm_tc<1><<<bigGrid, 256, GEMM_SMEM>>>(Ah, Al, BY, b_y, Y, WW, WW, WW, LL);
    // slot 4: GEMM -> XB
    gemm_tc<0><<<bigGrid, 256, GEMM_SMEM>>>(Ah, Al, BX, b_x, XB, WW, WW, WW, LL);
    // slot 5: conv -> fp16 hi/lo split into Ah/Al
    {
        long tot = (long)MTOT * L4C;
        conv_k<<<(int)((tot + 255) / 256), 256>>>((const float4*)XB, (const float4*)conv_w,
                                                  (const float4*)conv_b,
                                                  (uint2*)Ah, (uint2*)Al);
    }
    // slots 6-7: gate weight transposes
    tsplit_k<<<ggrid, tblk>>>(igate_w, GW1, HD, HD, (long)HD * HD, (long)HD * HD);
    tsplit_k<<<ggrid, tblk>>>(agate_w, GW2, HD, HD, (long)HD * HD, (long)HD * HD);
    // slot 8: dual gate GEMM with fused combine
    gate_tc<<<gateGrid, 256, GATE_SMEM>>>(Ah, Al, GW1, GW2,
                                          igate_b, agate_b, a_param, seg, G1, G2);
    // slots 9-11: chunked scan ; pass 3 fused with h*y and split into Ah/Al
    {
        long tot = (long)BB * NCH * LL;
        int blocks = (int)((tot + 255) / 256);
        scan_p1<<<blocks, 256>>>(G2, G1, Aagg, Hend);
        scan_p2<<<(BB * LL + 255) / 256, 256>>>(Aagg, Hend, Cin);
        scan_p3f<<<blocks, 256>>>(G2, G1, Cin, Y, Ah, Al);
    }
    // slot 12: w_out^T convert (reuse BY buffer)
    tsplit_k<<<tgrid, tblk>>>(w_out, BY, LL, WW, 0, 0);
    // slot 13: final GEMM -> out
    gemm_tc<0><<<bigGrid, 256, GEMM_SMEM>>>(Ah, Al, BY, b_out, out, LL, LL, LL, WW);
}

// round 12
// speedup vs baseline: 1.5433x; 1.0148x over previous
#include <cuda_runtime.h>
#include <cuda_bf16.h>
#include <cuda_fp16.h>
#include <math.h>
#include <stdint.h>

// Problem constants
#define BB 2
#define TT 4096
#define WW 2048
#define LL 2048
#define HH 8
#define TWD 4
#define HD 256                 // LL / HH
#define MTOT (BB * TT)         // 8192 rows
#define ELEMS ((size_t)MTOT * LL)  // 16,777,216
#define L4C (LL / 4)           // 512

#define SCH 128                // scan chunk length
#define NCH (TT / SCH)         // 32 chunks

// ---------------------------------------------------------------------------
// Scratch buffers (static device globals — no runtime allocation)
// ---------------------------------------------------------------------------
__device__ float g_Y[ELEMS];      // gelu(x @ w_y + b_y)
__device__ float g_XB[ELEMS];     // x @ w_x + b_x
__device__ float g_G1[ELEMS];     // normed
__device__ float g_G2[ELEMS];     // a_masked

__device__ __half g_Ah[ELEMS];            // fp16 hi split of current A operand
__device__ __half g_Al[ELEMS];            // fp16 lo split (residual)
__device__ __half g_BY[(size_t)LL * WW];  // transposed w_y fp16 [N,K]
__device__ __half g_BX[(size_t)LL * WW];  // transposed w_x fp16 [N,K]
__device__ __half g_BO[(size_t)LL * WW];  // transposed w_out fp16 [N,K]
__device__ __half g_GW1[(size_t)HH * HD * HD];
__device__ __half g_GW2[(size_t)HH * HD * HD];

__device__ float g_Aagg[(size_t)BB * NCH * LL];
__device__ float g_Hend[(size_t)BB * NCH * LL];
__device__ float g_Cin [(size_t)BB * NCH * LL];

// ---------------------------------------------------------------------------
// Low-level helpers (sm_80-portable: ldmatrix / mma.sync / cp.async only)
// ---------------------------------------------------------------------------
__device__ __forceinline__ uint32_t smem_u32(const void* p) {
    uint32_t a;
    asm("{ .reg .u64 t; cvta.to.shared.u64 t, %1; cvt.u32.u64 %0, t; }" : "=r"(a) : "l"(p));
    return a;
}
__device__ __forceinline__ void cp_async16(uint32_t saddr, const void* gaddr) {
    asm volatile("cp.async.cg.shared.global [%0], [%1], 16;" :: "r"(saddr), "l"(gaddr) : "memory");
}
__device__ __forceinline__ void ldm_x4(uint32_t* r, uint32_t addr) {
    asm volatile("ldmatrix.sync.aligned.m8n8.x4.shared.b16 {%0,%1,%2,%3}, [%4];"
                 : "=r"(r[0]), "=r"(r[1]), "=r"(r[2]), "=r"(r[3]) : "r"(addr));
}
// fp16 inputs, fp32 accumulate
__device__ __forceinline__ void mma16816(float* c, const uint32_t* a, const uint32_t* b) {
    asm volatile("mma.sync.aligned.m16n8k16.row.col.f32.f16.f16.f32 "
                 "{%0,%1,%2,%3}, {%4,%5,%6,%7}, {%8,%9}, {%0,%1,%2,%3};"
                 : "+f"(c[0]), "+f"(c[1]), "+f"(c[2]), "+f"(c[3])
                 : "r"(a[0]), "r"(a[1]), "r"(a[2]), "r"(a[3]), "r"(b[0]), "r"(b[1]));
}

// ---------------------------------------------------------------------------
// Big GEMM core (R11-proven): C[m,n] = EPI( sum_k A[m,k]*B[n,k] + bias[n] )
// 2xfp16 split (Ah*Bh + Al*Bh = A*Bh), fp32 accum.
// Tile 128x128x64, 256 threads, 8 warps of 64x32.
// 2-stage cp.async pipeline + 2 CTAs/SM for cross-CTA bubble filling.
// ---------------------------------------------------------------------------
#define BKK 64
#define ROWB 144                       // padded row bytes (64*2 + 16)
#define MATB (128 * ROWB)              // 18432 bytes per matrix tile
#define STAGEB (3 * MATB)              // 55296 bytes per stage
#define NSTAGE 2
#define GEMM_SMEM (NSTAGE * STAGEB)    // 110592 bytes -> 2 CTAs/SM

// core body shared by both entry points
template <bool DUAL, int EPI>
__device__ __forceinline__
void gemm_body(const __half* __restrict__ Ah, const __half* __restrict__ Al,
               const __half* __restrict__ Bh,
               const float* __restrict__ bias, float* __restrict__ C,
               int K, int lda, int ldb, int ldc, bool gel)
{
    extern __shared__ char sm[];
    const uint32_t sbase = smem_u32(sm);
    const int tid  = threadIdx.x;
    const int lane = tid & 31;
    const int wid  = tid >> 5;
    const int m0 = blockIdx.y * 128;
    const int n0 = blockIdx.x * 128;

    const __half* AbH = Ah + (size_t)m0 * lda;
    const __half* AbL = Al + (size_t)m0 * lda;
    const __half* BbH = Bh + (size_t)n0 * ldb;

    const int NIT = K / BKK;

    auto load_stage = [&](int it, int buf) {
        const int k0 = it * BKK;
        const __half* srcs[3] = {AbH, AbL, BbH};
#pragma unroll
        for (int mt = 0; mt < 3; mt++) {
            const int ld = (mt < 2) ? lda : ldb;
            const __half* src = srcs[mt];
#pragma unroll
            for (int i = 0; i < 4; i++) {
                int c = tid + 256 * i;           // 0..1023
                int row = c >> 3, col = c & 7;
                uint32_t sa = sbase + buf * STAGEB + mt * MATB + row * ROWB + col * 16;
                cp_async16(sa, src + (size_t)row * ld + k0 + col * 8);
            }
        }
        asm volatile("cp.async.commit_group;" ::: "memory");
    };

    const int m0w = (wid & 1) * 64;
    const int n0w = (wid >> 1) * 32;

    float acc[4][4][4];
#pragma unroll
    for (int i = 0; i < 4; i++)
#pragma unroll
        for (int j = 0; j < 4; j++)
#pragma unroll
            for (int e = 0; e < 4; e++) acc[i][j][e] = 0.f;

    load_stage(0, 0);
    if (NIT > 1) load_stage(1, 1);

    for (int it = 0; it < NIT; it++) {
        if (it + 1 < NIT) asm volatile("cp.async.wait_group 1;" ::: "memory");
        else              asm volatile("cp.async.wait_group 0;" ::: "memory");
        __syncthreads();

        const int buf = it & 1;
        const uint32_t sAh = sbase + buf * STAGEB;
        const uint32_t sAl = sAh + MATB;
        const uint32_t sBh = sAh + 2 * MATB;

#pragma unroll
        for (int ks = 0; ks < BKK; ks += 16) {
            uint32_t ah[4][4], al[4][4], bh[4][2];
            const uint32_t aoff = (uint32_t)(lane & 15) * ROWB + (uint32_t)ks * 2
                                + (uint32_t)(lane >> 4) * 16;
#pragma unroll
            for (int mf = 0; mf < 4; mf++) {
                uint32_t ad = (uint32_t)(m0w + mf * 16) * ROWB + aoff;
                ldm_x4(ah[mf], sAh + ad);
                ldm_x4(al[mf], sAl + ad);
            }
            const uint32_t boff = (uint32_t)(((lane >> 4) << 3) + (lane & 7)) * ROWB
                                + (uint32_t)ks * 2 + (uint32_t)((lane >> 3) & 1) * 16;
#pragma unroll
            for (int nf2 = 0; nf2 < 2; nf2++) {
                uint32_t bd = (uint32_t)(n0w + nf2 * 16) * ROWB + boff;
                uint32_t rh[4];
                ldm_x4(rh, sBh + bd);
                bh[nf2 * 2][0] = rh[0]; bh[nf2 * 2][1] = rh[1];
                bh[nf2 * 2 + 1][0] = rh[2]; bh[nf2 * 2 + 1][1] = rh[3];
            }
#pragma unroll
            for (int mf = 0; mf < 4; mf++)
#pragma unroll
                for (int nf = 0; nf < 4; nf++)
                    mma16816(acc[mf][nf], ah[mf], bh[nf]);
#pragma unroll
            for (int mf = 0; mf < 4; mf++)
#pragma unroll
                for (int nf = 0; nf < 4; nf++)
                    mma16816(acc[mf][nf], al[mf], bh[nf]);
        }
        __syncthreads();
        if (it + 2 < NIT) load_stage(it + 2, it & 1);
    }

    // epilogue: bias + optional gelu, direct float2 stores
    const int rbase = m0 + m0w + (lane >> 2);
    const int cbase = n0 + n0w + (lane & 3) * 2;
    const bool dogel = DUAL ? gel : (EPI == 1);
#pragma unroll
    for (int mf = 0; mf < 4; mf++) {
#pragma unroll
        for (int nf = 0; nf < 4; nf++) {
            int col = cbase + nf * 8;
            float b0 = bias[col], b1 = bias[col + 1];
            float v[4] = {acc[mf][nf][0] + b0, acc[mf][nf][1] + b1,
                          acc[mf][nf][2] + b0, acc[mf][nf][3] + b1};
            if (dogel) {
#pragma unroll
                for (int e = 0; e < 4; e++) {
                    float x = v[e];
                    float t = tanhf(0.7978845608028654f * (x + 0.044715f * x * x * x));
                    v[e] = 0.5f * x * (1.f + t);
                }
            }
            int r0 = rbase + mf * 16;
            *(float2*)&C[(size_t)r0 * ldc + col]       = make_float2(v[0], v[1]);
            *(float2*)&C[(size_t)(r0 + 8) * ldc + col] = make_float2(v[2], v[3]);
        }
    }
}

// dual-output launch: z=0 -> gelu(x@w_y+b_y) into Y ; z=1 -> x@w_x+b_x into XB
__global__ __launch_bounds__(256, 2)
void gemm_dual(const __half* __restrict__ Ah, const __half* __restrict__ Al,
               const __half* __restrict__ B0, const __half* __restrict__ B1,
               const float* __restrict__ bias0, const float* __restrict__ bias1,
               float* __restrict__ C0, float* __restrict__ C1,
               int K, int lda, int ldb, int ldc)
{
    const bool gel = (blockIdx.z == 0);
    const __half* Bh  = gel ? B0 : B1;
    const float* bias = gel ? bias0 : bias1;
    float* C          = gel ? C0 : C1;
    gemm_body<true, 0>(Ah, Al, Bh, bias, C, K, lda, ldb, ldc, gel);
}

// single-output launch (final GEMM)
template <int EPI>
__global__ __launch_bounds__(256, 2)
void gemm_tc(const __half* __restrict__ Ah, const __half* __restrict__ Al,
             const __half* __restrict__ Bh,
             const float* __restrict__ bias, float* __restrict__ C,
             int K, int lda, int ldb, int ldc)
{
    gemm_body<false, EPI>(Ah, Al, Bh, bias, C, K, lda, ldb, ldc, false);
}

// ---------------------------------------------------------------------------
// Dual gate GEMM + fused combine epilogue. 2xfp16 split.
// 4 matrices per stage (Ah, Al, W1, W2). conv reconstructed as Ah+Al (~exact).
// ---------------------------------------------------------------------------
#define GMATB (128 * ROWB)             // 18432
#define GSTAGEB (4 * GMATB)            // 73728
#define GATE_SMEM (2 * GSTAGEB)        // 147456

__global__ __launch_bounds__(256, 1)
void gate_tc(const __half* __restrict__ cAh, const __half* __restrict__ cAl,
             const __half* __restrict__ W1, const __half* __restrict__ W2,
             const float* __restrict__ ib, const float* __restrict__ ab,
             const float* __restrict__ a_param, const int* __restrict__ seg,
             float* __restrict__ G1, float* __restrict__ G2)
{
    extern __shared__ char sm[];
    const uint32_t sbase = smem_u32(sm);
    const int tid  = threadIdx.x;
    const int lane = tid & 31;
    const int wid  = tid >> 5;
    const int z  = blockIdx.z;           // head
    const int m0 = blockIdx.y * 128;
    const int n0 = blockIdx.x * 128;     // 0 or 128 within head

    const __half* AbH = cAh + (size_t)m0 * LL + z * HD;
    const __half* AbL = cAl + (size_t)m0 * LL + z * HD;
    const __half* B1  = W1 + (size_t)z * HD * HD + (size_t)n0 * HD;
    const __half* B2  = W2 + (size_t)z * HD * HD + (size_t)n0 * HD;

    const int NIT = HD / BKK;   // 4

    auto load_stage = [&](int it, int buf) {
        const int k0 = it * BKK;
        const __half* srcs[4] = {AbH, AbL, B1, B2};
#pragma unroll
        for (int mt = 0; mt < 4; mt++) {
            const int ld = (mt < 2) ? LL : HD;
            const __half* src = srcs[mt];
#pragma unroll
            for (int i = 0; i < 4; i++) {
                int c = tid + 256 * i;
                int row = c >> 3, col = c & 7;
                uint32_t sa = sbase + buf * GSTAGEB + mt * GMATB + row * ROWB + col * 16;
                cp_async16(sa, src + (size_t)row * ld + k0 + col * 8);
            }
        }
        asm volatile("cp.async.commit_group;" ::: "memory");
    };

    const int m0w = (wid & 1) * 64;
    const int n0w = (wid >> 1) * 32;

    float acc[2][4][4][4];
#pragma unroll
    for (int s = 0; s < 2; s++)
#pragma unroll
        for (int i = 0; i < 4; i++)
#pragma unroll
            for (int j = 0; j < 4; j++)
#pragma unroll
                for (int e = 0; e < 4; e++) acc[s][i][j][e] = 0.f;

    load_stage(0, 0);
    load_stage(1, 1);

    for (int it = 0; it < NIT; it++) {
        if (it + 1 < NIT) asm volatile("cp.async.wait_group 1;" ::: "memory");
        else              asm volatile("cp.async.wait_group 0;" ::: "memory");
        __syncthreads();

        const int buf = it & 1;
        const uint32_t sA = sbase + buf * GSTAGEB;

#pragma unroll
        for (int ks = 0; ks < BKK; ks += 16) {
            uint32_t ah[4][4], al[4][4];
            const uint32_t aoff = (uint32_t)(lane & 15) * ROWB + (uint32_t)ks * 2
                                + (uint32_t)(lane >> 4) * 16;
#pragma unroll
            for (int mf = 0; mf < 4; mf++) {
                uint32_t ad = (uint32_t)(m0w + mf * 16) * ROWB + aoff;
                ldm_x4(ah[mf], sA + ad);
                ldm_x4(al[mf], sA + GMATB + ad);
            }
            const uint32_t boff = (uint32_t)(((lane >> 4) << 3) + (lane & 7)) * ROWB
                                + (uint32_t)ks * 2 + (uint32_t)((lane >> 3) & 1) * 16;
#pragma unroll
            for (int s = 0; s < 2; s++) {
                uint32_t bh[4][2];
                const uint32_t sB = sA + (2 + s) * GMATB;
#pragma unroll
                for (int nf2 = 0; nf2 < 2; nf2++) {
                    uint32_t bd = (uint32_t)(n0w + nf2 * 16) * ROWB + boff;
                    uint32_t rh[4];
                    ldm_x4(rh, sB + bd);
                    bh[nf2 * 2][0] = rh[0]; bh[nf2 * 2][1] = rh[1];
                    bh[nf2 * 2 + 1][0] = rh[2]; bh[nf2 * 2 + 1][1] = rh[3];
                }
#pragma unroll
                for (int mf = 0; mf < 4; mf++)
#pragma unroll
                    for (int nf = 0; nf < 4; nf++)
                        mma16816(acc[s][mf][nf], ah[mf], bh[nf]);
#pragma unroll
                for (int mf = 0; mf < 4; mf++)
#pragma unroll
                    for (int nf = 0; nf < 4; nf++)
                        mma16816(acc[s][mf][nf], al[mf], bh[nf]);
            }
        }
        __syncthreads();
        if (it + 2 < NIT) load_stage(it + 2, it & 1);
    }

    // fused combine epilogue (conv reconstructed from fp16 hi/lo split)
    const int rbase = m0 + m0w + (lane >> 2);          // global row
    const int cloc0 = n0 + n0w + (lane & 3) * 2;       // col within head
#pragma unroll
    for (int mf = 0; mf < 4; mf++) {
#pragma unroll
        for (int half = 0; half < 2; half++) {
            int row = rbase + mf * 16 + half * 8;
            bool reset = (seg[row] == 0);
#pragma unroll
            for (int nf = 0; nf < 4; nf++) {
                int cl = cloc0 + nf * 8;               // col within head (0..255)
                size_t go = (size_t)row * LL + (size_t)z * HD + cl;
                uint32_t chp = *(const uint32_t*)&cAh[go];
                uint32_t clp = *(const uint32_t*)&cAl[go];
                float outn[2], outa[2];
#pragma unroll
                for (int e = 0; e < 2; e++) {
                    float c1 = acc[0][mf][nf][half * 2 + e] + ib[z * HD + cl + e];
                    float c2 = acc[1][mf][nf][half * 2 + e] + ab[z * HD + cl + e];
                    float gi = 1.f / (1.f + expf(-c1));
                    float ga = 1.f / (1.f + expf(-c2));
                    float ap = a_param[z * HD + cl + e];
                    float sp = log1pf(expf(ap));
                    float la = -8.f * ga * sp;
                    float a = expf(la);
                    float mult = reset ? 1.f : sqrtf(fmaxf(1.f - expf(2.f * la), 0.f));
                    uint16_t hb = (uint16_t)((e == 0) ? (chp & 0xFFFF) : (chp >> 16));
                    uint16_t lb = (uint16_t)((e == 0) ? (clp & 0xFFFF) : (clp >> 16));
                    float cvv = __half2float(__ushort_as_half(hb))
                              + __half2float(__ushort_as_half(lb));
                    outn[e] = cvv * gi * mult;
                    outa[e] = reset ? 0.f : a;
                }
                *(float2*)&G1[go] = make_float2(outn[0], outn[1]);
                *(float2*)&G2[go] = make_float2(outa[0], outa[1]);
            }
        }
    }
}

// ---------------------------------------------------------------------------
// f32 -> fp16 hi/lo split (vectorized x4)
// ---------------------------------------------------------------------------
__device__ __forceinline__ uint32_t pk2h(__half a, __half b) {
    return (uint32_t)__half_as_ushort(a) | ((uint32_t)__half_as_ushort(b) << 16);
}
__device__ __forceinline__ void split_f4h(float4 v, uint2& H, uint2& L) {
    __half hx = __float2half_rn(v.x), hy = __float2half_rn(v.y);
    __half hz = __float2half_rn(v.z), hw = __float2half_rn(v.w);
    H.x = pk2h(hx, hy);
    H.y = pk2h(hz, hw);
    L.x = pk2h(__float2half_rn(v.x - __half2float(hx)), __float2half_rn(v.y - __half2float(hy)));
    L.y = pk2h(__float2half_rn(v.z - __half2float(hz)), __float2half_rn(v.w - __half2float(hw)));
}
__global__ void split4_k(const float4* __restrict__ in, uint2* __restrict__ oh,
                         uint2* __restrict__ ol, long n4)
{
    long i = (long)blockIdx.x * blockDim.x + threadIdx.x;
    if (i >= n4) return;
    uint2 H, L;
    split_f4h(in[i], H, L);
    oh[i] = H; ol[i] = L;
}

// ---------------------------------------------------------------------------
// Transposing convert for 3 big weights in one launch:
// z selects (w_y->BY, w_x->BX, w_out->BO). Dims differ only in roles (all 2048x2048).
// ---------------------------------------------------------------------------
__global__ void tsplit3_k(const float* __restrict__ s0, const float* __restrict__ s1,
                          const float* __restrict__ s2,
                          __half* __restrict__ d0, __half* __restrict__ d1,
                          __half* __restrict__ d2)
{
    __shared__ float t[32][33];
    const int z = blockIdx.z;
    const float* in = (z == 0) ? s0 : (z == 1) ? s1 : s2;
    __half* oh      = (z == 0) ? d0 : (z == 1) ? d1 : d2;
    const int K = WW, N = LL;     // 2048 x 2048 for all three
    int kb = blockIdx.y * 32, nb = blockIdx.x * 32;
    for (int i = threadIdx.y; i < 32; i += 8)
        t[i][threadIdx.x] = in[(size_t)(kb + i) * N + nb + threadIdx.x];
    __syncthreads();
    for (int i = threadIdx.y; i < 32; i += 8) {
        int n = nb + i, k = kb + threadIdx.x;
        oh[(size_t)n * K + k] = __float2half_rn(t[threadIdx.x][i]);
    }
}

// gate weights: z 0..15 -> (head = z&7, src = z>>3 ? agate : igate)
__global__ void tsplitg_k(const float* __restrict__ ig, const float* __restrict__ ag,
                          __half* __restrict__ d1, __half* __restrict__ d2)
{
    __shared__ float t[32][33];
    const int z = blockIdx.z;
    const int head = z & 7;
    const float* in = ((z >> 3) ? ag : ig) + (size_t)head * HD * HD;
    __half* oh      = ((z >> 3) ? d2 : d1) + (size_t)head * HD * HD;
    int kb = blockIdx.y * 32, nb = blockIdx.x * 32;
    for (int i = threadIdx.y; i < 32; i += 8)
        t[i][threadIdx.x] = in[(size_t)(kb + i) * HD + nb + threadIdx.x];
    __syncthreads();
    for (int i = threadIdx.y; i < 32; i += 8) {
        int n = nb + i, k = kb + threadIdx.x;
        oh[(size_t)n * HD + k] = __float2half_rn(t[threadIdx.x][i]);
    }
}

// ---------------------------------------------------------------------------
// Causal depthwise temporal conv (TW=4) -> fp16 hi/lo split output
// ---------------------------------------------------------------------------
__global__ void conv_k(const float4* __restrict__ xb, const float4* __restrict__ cw,
                       const float4* __restrict__ cb,
                       uint2* __restrict__ oh, uint2* __restrict__ ol)
{
    long idx = (long)blockIdx.x * blockDim.x + threadIdx.x;
    if (idx >= (long)MTOT * L4C) return;
    int l4 = (int)(idx % L4C);
    int m = (int)(idx / L4C);
    int t = m % TT;
    float4 acc = cb[l4];
#pragma unroll
    for (int j = 0; j < TWD; j++) {
        int dt = TWD - 1 - j;
        if (t - dt >= 0) {
            float4 w = cw[j * L4C + l4];
            float4 x = xb[(long)(m - dt) * L4C + l4];
            acc.x = fmaf(w.x, x.x, acc.x);
            acc.y = fmaf(w.y, x.y, acc.y);
            acc.z = fmaf(w.z, x.z, acc.z);
            acc.w = fmaf(w.w, x.w, acc.w);
        }
    }
    uint2 H, L;
    split_f4h(acc, H, L);
    oh[idx] = H; ol[idx] = L;
}

// ---------------------------------------------------------------------------
// Chunked scan (scalar over L): h_t = a_t h_{t-1} + x_t
// Pass 3 fused with elementwise gate (h*y) and fp16 split for the final GEMM.
// ---------------------------------------------------------------------------
__global__ void scan_p1(const float* __restrict__ a, const float* __restrict__ x,
                        float* __restrict__ Aagg, float* __restrict__ Hend)
{
    long idx = (long)blockIdx.x * blockDim.x + threadIdx.x;  // over B*NCH*L
    if (idx >= (long)BB * NCH * LL) return;
    int l = (int)(idx % LL);
    int r = (int)(idx / LL);
    int c = r % NCH, b = r / NCH;
    size_t base = ((size_t)b * TT + (size_t)c * SCH) * LL + l;
    float h = 0.f, ap = 1.f;
#pragma unroll 4
    for (int t = 0; t < SCH; t++) {
        float av = a[base + (size_t)t * LL];
        h = fmaf(av, h, x[base + (size_t)t * LL]);
        ap *= av;
    }
    Aagg[idx] = ap; Hend[idx] = h;
}
__global__ void scan_p2(const float* __restrict__ Aagg, const float* __restrict__ Hend,
                        float* __restrict__ Cin)
{
    int idx = blockIdx.x * blockDim.x + threadIdx.x;
    if (idx >= BB * LL) return;
    int l = idx % LL, b = idx / LL;
    float cin = 0.f;
    for (int c = 0; c < NCH; c++) {
        size_t j = ((size_t)b * NCH + c) * LL + l;
        Cin[j] = cin;
        cin = fmaf(Aagg[j], cin, Hend[j]);
    }
}
__global__ void scan_p3f(const float* __restrict__ a, const float* __restrict__ x,
                         const float* __restrict__ Cin, const float* __restrict__ y,
                         __half* __restrict__ oh, __half* __restrict__ ol)
{
    long idx = (long)blockIdx.x * blockDim.x + threadIdx.x;
    if (idx >= (long)BB * NCH * LL) return;
    int l = (int)(idx % LL);
    int r = (int)(idx / LL);
    int c = r % NCH, b = r / NCH;
    size_t base = ((size_t)b * TT + (size_t)c * SCH) * LL + l;
    float h = Cin[idx];
#pragma unroll 4
    for (int t = 0; t < SCH; t++) {
        size_t o = base + (size_t)t * LL;
        h = fmaf(a[o], h, x[o]);
        float v = h * y[o];
        __half hi = __float2half_rn(v);
        oh[o] = hi;
        ol[o] = __float2half_rn(v - __half2float(hi));
    }
}

// ---------------------------------------------------------------------------
// Launch
// ---------------------------------------------------------------------------
extern "C" void kernel_launch(void* const* d_in, const int* in_sizes, int n_in,
                              void* d_out, int out_size)
{
    const float* x       = (const float*)d_in[0];
    const int*   seg     = (const int*)  d_in[1];
    const float* w_y     = (const float*)d_in[2];
    const float* b_y     = (const float*)d_in[3];
    const float* w_x     = (const float*)d_in[4];
    const float* b_x     = (const float*)d_in[5];
    const float* w_out   = (const float*)d_in[6];
    const float* b_out   = (const float*)d_in[7];
    const float* conv_w  = (const float*)d_in[8];
    const float* conv_b  = (const float*)d_in[9];
    const float* a_param = (const float*)d_in[10];
    const float* igate_w = (const float*)d_in[11];
    const float* igate_b = (const float*)d_in[12];
    const float* agate_w = (const float*)d_in[13];
    const float* agate_b = (const float*)d_in[14];
    float* out = (float*)d_out;

    float *Y, *XB, *G1, *G2, *Aagg, *Hend, *Cin;
    __half *Ah, *Al, *BY, *BX, *BO, *GW1, *GW2;
    cudaGetSymbolAddress((void**)&Y, g_Y);
    cudaGetSymbolAddress((void**)&XB, g_XB);
    cudaGetSymbolAddress((void**)&G1, g_G1);
    cudaGetSymbolAddress((void**)&G2, g_G2);
    cudaGetSymbolAddress((void**)&Ah, g_Ah);
    cudaGetSymbolAddress((void**)&Al, g_Al);
    cudaGetSymbolAddress((void**)&BY, g_BY);
    cudaGetSymbolAddress((void**)&BX, g_BX);
    cudaGetSymbolAddress((void**)&BO, g_BO);
    cudaGetSymbolAddress((void**)&GW1, g_GW1);
    cudaGetSymbolAddress((void**)&GW2, g_GW2);
    cudaGetSymbolAddress((void**)&Aagg, g_Aagg);
    cudaGetSymbolAddress((void**)&Hend, g_Hend);
    cudaGetSymbolAddress((void**)&Cin, g_Cin);

    cudaFuncSetAttribute(gemm_dual, cudaFuncAttributeMaxDynamicSharedMemorySize, GEMM_SMEM);
    cudaFuncSetAttribute(gemm_tc<0>, cudaFuncAttributeMaxDynamicSharedMemorySize, GEMM_SMEM);
    cudaFuncSetAttribute(gate_tc, cudaFuncAttributeMaxDynamicSharedMemorySize, GATE_SMEM);

    const long n4 = (long)ELEMS / 4;
    const int eb = (int)((n4 + 255) / 256);
    dim3 t3grid(WW / 32, WW / 32, 3);
    dim3 tblk(32, 8, 1);
    dim3 dualGrid(LL / 128, MTOT / 128, 2);    // (16, 64, 2)
    dim3 bigGrid(LL / 128, MTOT / 128, 1);     // (16, 64)
    dim3 gateGrid(HD / 128, MTOT / 128, HH);   // (2, 64, 8)
    dim3 ggrid(HD / 32, HD / 32, 16);

    // slot 0: split x -> Ah/Al
    split4_k<<<eb, 256>>>((const float4*)x, (uint2*)Ah, (uint2*)Al, n4);
    // slot 1: all three big weight transposes in one launch
    tsplit3_k<<<t3grid, tblk>>>(w_y, w_x, w_out, BY, BX, BO);
    // slot 2: both gate weight transposes in one launch
    tsplitg_k<<<ggrid, tblk>>>(igate_w, agate_w, GW1, GW2);
    // slot 3: merged dual GEMM -> Y (gelu) and XB
    gemm_dual<<<dualGrid, 256, GEMM_SMEM>>>(Ah, Al, BY, BX, b_y, b_x, Y, XB,
                                            WW, WW, WW, LL);
    // slot 4: conv -> fp16 hi/lo split into Ah/Al
    {
        long tot = (long)MTOT * L4C;
        conv_k<<<(int)((tot + 255) / 256), 256>>>((const float4*)XB, (const float4*)conv_w,
                                                  (const float4*)conv_b,
                                                  (uint2*)Ah, (uint2*)Al);
    }
    // slot 5: dual gate GEMM with fused combine
    gate_tc<<<gateGrid, 256, GATE_SMEM>>>(Ah, Al, GW1, GW2,
                                          igate_b, agate_b, a_param, seg, G1, G2);
    // slots 6-8: chunked scan ; pass 3 fused with h*y and split into Ah/Al
    {
        long tot = (long)BB * NCH * LL;
        int blocks = (int)((tot + 255) / 256);
        scan_p1<<<blocks, 256>>>(G2, G1, Aagg, Hend);
        scan_p2<<<(BB * LL + 255) / 256, 256>>>(Aagg, Hend, Cin);
        scan_p3f<<<blocks, 256>>>(G2, G1, Cin, Y, Ah, Al);
    }
    // slot 9: final GEMM -> out
    gemm_tc<0><<<bigGrid, 256, GEMM_SMEM>>>(Ah, Al, BO, b_out, out, LL, LL, LL, WW);
}

// round 13
// speedup vs baseline: 1.9321x; 1.2520x over previous
#include <cuda_runtime.h>
#include <cuda_bf16.h>
#include <cuda_fp16.h>
#include <math.h>
#include <stdint.h>

// Problem constants
#define BB 2
#define TT 4096
#define WW 2048
#define LL 2048
#define HH 8
#define TWD 4
#define HD 256                 // LL / HH
#define MTOT (BB * TT)         // 8192 rows
#define ELEMS ((size_t)MTOT * LL)  // 16,777,216
#define L4C (LL / 4)           // 512

#define SCH 128                // scan chunk length
#define NCH (TT / SCH)         // 32 chunks

// ---------------------------------------------------------------------------
// Scratch buffers (static device globals — no runtime allocation)
// ---------------------------------------------------------------------------
__device__ float g_Y[ELEMS];      // gelu(x @ w_y + b_y)
__device__ float g_XB[ELEMS];     // x @ w_x + b_x
__device__ float g_G1[ELEMS];     // normed
__device__ float g_G2[ELEMS];     // a_masked

__device__ __half g_Ah[ELEMS];            // fp16 hi split of current A operand
__device__ __half g_Al[ELEMS];            // fp16 lo split (residual)
__device__ __half g_BY[(size_t)LL * WW];  // transposed w_y fp16 [N,K]
__device__ __half g_BX[(size_t)LL * WW];  // transposed w_x fp16 [N,K]
__device__ __half g_BO[(size_t)LL * WW];  // transposed w_out fp16 [N,K]
__device__ __half g_GW1[(size_t)HH * HD * HD];
__device__ __half g_GW2[(size_t)HH * HD * HD];

__device__ float g_Aagg[(size_t)BB * NCH * LL];
__device__ float g_Hend[(size_t)BB * NCH * LL];
__device__ float g_Cin [(size_t)BB * NCH * LL];

// ---------------------------------------------------------------------------
// Low-level helpers (sm_80-portable: ldmatrix / mma.sync / cp.async only)
// ---------------------------------------------------------------------------
__device__ __forceinline__ uint32_t smem_u32(const void* p) {
    uint32_t a;
    asm("{ .reg .u64 t; cvta.to.shared.u64 t, %1; cvt.u32.u64 %0, t; }" : "=r"(a) : "l"(p));
    return a;
}
__device__ __forceinline__ void cp_async16(uint32_t saddr, const void* gaddr) {
    asm volatile("cp.async.cg.shared.global [%0], [%1], 16;" :: "r"(saddr), "l"(gaddr) : "memory");
}
__device__ __forceinline__ void ldm_x4(uint32_t* r, uint32_t addr) {
    asm volatile("ldmatrix.sync.aligned.m8n8.x4.shared.b16 {%0,%1,%2,%3}, [%4];"
                 : "=r"(r[0]), "=r"(r[1]), "=r"(r[2]), "=r"(r[3]) : "r"(addr));
}
// fp16 inputs, fp32 accumulate
__device__ __forceinline__ void mma16816(float* c, const uint32_t* a, const uint32_t* b) {
    asm volatile("mma.sync.aligned.m16n8k16.row.col.f32.f16.f16.f32 "
                 "{%0,%1,%2,%3}, {%4,%5,%6,%7}, {%8,%9}, {%0,%1,%2,%3};"
                 : "+f"(c[0]), "+f"(c[1]), "+f"(c[2]), "+f"(c[3])
                 : "r"(a[0]), "r"(a[1]), "r"(a[2]), "r"(a[3]), "r"(b[0]), "r"(b[1]));
}

// ---------------------------------------------------------------------------
// Big GEMM core: C[m,n] = EPI( sum_k A[m,k]*B[n,k] + bias[n] )
// NPROD=2: Ah*Bh + Al*Bh (full A precision); NPROD=1: Ah*Bh only.
// Tile 128x128x64, 256 threads, 8 warps of 64x32.
// 2-stage cp.async pipeline + 2 CTAs/SM for cross-CTA bubble filling.
// ---------------------------------------------------------------------------
#define BKK 64
#define ROWB 144                       // padded row bytes (64*2 + 16)
#define MATB (128 * ROWB)              // 18432 bytes per matrix tile
#define STAGEB (3 * MATB)              // 55296 bytes per stage
#define NSTAGE 2
#define GEMM_SMEM (NSTAGE * STAGEB)    // 110592 bytes -> 2 CTAs/SM

template <int NPROD>
__device__ __forceinline__
void gemm_core(const __half* __restrict__ Ah, const __half* __restrict__ Al,
               const __half* __restrict__ Bh,
               const float* __restrict__ bias, float* __restrict__ C,
               int K, int lda, int ldb, int ldc, bool dogel)
{
    extern __shared__ char sm[];
    const uint32_t sbase = smem_u32(sm);
    const int tid  = threadIdx.x;
    const int lane = tid & 31;
    const int wid  = tid >> 5;
    const int m0 = blockIdx.y * 128;
    const int n0 = blockIdx.x * 128;

    const __half* AbH = Ah + (size_t)m0 * lda;
    const __half* AbL = (NPROD == 2) ? (Al + (size_t)m0 * lda) : AbH;
    const __half* BbH = Bh + (size_t)n0 * ldb;

    const int NIT = K / BKK;

    auto load_stage = [&](int it, int buf) {
        const int k0 = it * BKK;
        const __half* srcs[3] = {AbH, AbL, BbH};
#pragma unroll
        for (int mt = 0; mt < 3; mt++) {
            if (NPROD == 1 && mt == 1) continue;   // skip Al tile
            const int ld = (mt < 2) ? lda : ldb;
            const __half* src = srcs[mt];
#pragma unroll
            for (int i = 0; i < 4; i++) {
                int c = tid + 256 * i;           // 0..1023
                int row = c >> 3, col = c & 7;
                uint32_t sa = sbase + buf * STAGEB + mt * MATB + row * ROWB + col * 16;
                cp_async16(sa, src + (size_t)row * ld + k0 + col * 8);
            }
        }
        asm volatile("cp.async.commit_group;" ::: "memory");
    };

    const int m0w = (wid & 1) * 64;
    const int n0w = (wid >> 1) * 32;

    float acc[4][4][4];
#pragma unroll
    for (int i = 0; i < 4; i++)
#pragma unroll
        for (int j = 0; j < 4; j++)
#pragma unroll
            for (int e = 0; e < 4; e++) acc[i][j][e] = 0.f;

    load_stage(0, 0);
    if (NIT > 1) load_stage(1, 1);

    for (int it = 0; it < NIT; it++) {
        if (it + 1 < NIT) asm volatile("cp.async.wait_group 1;" ::: "memory");
        else              asm volatile("cp.async.wait_group 0;" ::: "memory");
        __syncthreads();

        const int buf = it & 1;
        const uint32_t sAh = sbase + buf * STAGEB;
        const uint32_t sAl = sAh + MATB;
        const uint32_t sBh = sAh + 2 * MATB;

#pragma unroll
        for (int ks = 0; ks < BKK; ks += 16) {
            uint32_t ah[4][4], al[4][4], bh[4][2];
            const uint32_t aoff = (uint32_t)(lane & 15) * ROWB + (uint32_t)ks * 2
                                + (uint32_t)(lane >> 4) * 16;
#pragma unroll
            for (int mf = 0; mf < 4; mf++) {
                uint32_t ad = (uint32_t)(m0w + mf * 16) * ROWB + aoff;
                ldm_x4(ah[mf], sAh + ad);
                if (NPROD == 2) ldm_x4(al[mf], sAl + ad);
            }
            const uint32_t boff = (uint32_t)(((lane >> 4) << 3) + (lane & 7)) * ROWB
                                + (uint32_t)ks * 2 + (uint32_t)((lane >> 3) & 1) * 16;
#pragma unroll
            for (int nf2 = 0; nf2 < 2; nf2++) {
                uint32_t bd = (uint32_t)(n0w + nf2 * 16) * ROWB + boff;
                uint32_t rh[4];
                ldm_x4(rh, sBh + bd);
                bh[nf2 * 2][0] = rh[0]; bh[nf2 * 2][1] = rh[1];
                bh[nf2 * 2 + 1][0] = rh[2]; bh[nf2 * 2 + 1][1] = rh[3];
            }
#pragma unroll
            for (int mf = 0; mf < 4; mf++)
#pragma unroll
                for (int nf = 0; nf < 4; nf++)
                    mma16816(acc[mf][nf], ah[mf], bh[nf]);
            if (NPROD == 2) {
#pragma unroll
                for (int mf = 0; mf < 4; mf++)
#pragma unroll
                    for (int nf = 0; nf < 4; nf++)
                        mma16816(acc[mf][nf], al[mf], bh[nf]);
            }
        }
        __syncthreads();
        if (it + 2 < NIT) load_stage(it + 2, it & 1);
    }

    // epilogue: bias + optional gelu, direct float2 stores
    const int rbase = m0 + m0w + (lane >> 2);
    const int cbase = n0 + n0w + (lane & 3) * 2;
#pragma unroll
    for (int mf = 0; mf < 4; mf++) {
#pragma unroll
        for (int nf = 0; nf < 4; nf++) {
            int col = cbase + nf * 8;
            float b0 = bias[col], b1 = bias[col + 1];
            float v[4] = {acc[mf][nf][0] + b0, acc[mf][nf][1] + b1,
                          acc[mf][nf][2] + b0, acc[mf][nf][3] + b1};
            if (dogel) {
#pragma unroll
                for (int e = 0; e < 4; e++) {
                    float x = v[e];
                    float t = tanhf(0.7978845608028654f * (x + 0.044715f * x * x * x));
                    v[e] = 0.5f * x * (1.f + t);
                }
            }
            int r0 = rbase + mf * 16;
            *(float2*)&C[(size_t)r0 * ldc + col]       = make_float2(v[0], v[1]);
            *(float2*)&C[(size_t)(r0 + 8) * ldc + col] = make_float2(v[2], v[3]);
        }
    }
}

// dual-output launch: z=0 -> gelu(x@w_y+b_y) into Y (1-product) ;
//                     z=1 -> x@w_x+b_x into XB (2-product, precision-critical)
__global__ __launch_bounds__(256, 2)
void gemm_dual(const __half* __restrict__ Ah, const __half* __restrict__ Al,
               const __half* __restrict__ B0, const __half* __restrict__ B1,
               const float* __restrict__ bias0, const float* __restrict__ bias1,
               float* __restrict__ C0, float* __restrict__ C1,
               int K, int lda, int ldb, int ldc)
{
    if (blockIdx.z == 0)
        gemm_core<1>(Ah, Al, B0, bias0, C0, K, lda, ldb, ldc, true);
    else
        gemm_core<2>(Ah, Al, B1, bias1, C1, K, lda, ldb, ldc, false);
}

// single-output 1-product launch (final GEMM)
__global__ __launch_bounds__(256, 2)
void gemm_single(const __half* __restrict__ Ah, const __half* __restrict__ Bh,
                 const float* __restrict__ bias, float* __restrict__ C,
                 int K, int lda, int ldb, int ldc)
{
    gemm_core<1>(Ah, nullptr, Bh, bias, C, K, lda, ldb, ldc, false);
}

// ---------------------------------------------------------------------------
// Dual gate GEMM + fused combine epilogue. 2xfp16 split (precision-critical).
// 4 matrices per stage (Ah, Al, W1, W2). conv reconstructed as Ah+Al (~exact).
// ---------------------------------------------------------------------------
#define GMATB (128 * ROWB)             // 18432
#define GSTAGEB (4 * GMATB)            // 73728
#define GATE_SMEM (2 * GSTAGEB)        // 147456

__global__ __launch_bounds__(256, 1)
void gate_tc(const __half* __restrict__ cAh, const __half* __restrict__ cAl,
             const __half* __restrict__ W1, const __half* __restrict__ W2,
             const float* __restrict__ ib, const float* __restrict__ ab,
             const float* __restrict__ a_param, const int* __restrict__ seg,
             float* __restrict__ G1, float* __restrict__ G2)
{
    extern __shared__ char sm[];
    const uint32_t sbase = smem_u32(sm);
    const int tid  = threadIdx.x;
    const int lane = tid & 31;
    const int wid  = tid >> 5;
    const int z  = blockIdx.z;           // head
    const int m0 = blockIdx.y * 128;
    const int n0 = blockIdx.x * 128;     // 0 or 128 within head

    const __half* AbH = cAh + (size_t)m0 * LL + z * HD;
    const __half* AbL = cAl + (size_t)m0 * LL + z * HD;
    const __half* B1  = W1 + (size_t)z * HD * HD + (size_t)n0 * HD;
    const __half* B2  = W2 + (size_t)z * HD * HD + (size_t)n0 * HD;

    const int NIT = HD / BKK;   // 4

    auto load_stage = [&](int it, int buf) {
        const int k0 = it * BKK;
        const __half* srcs[4] = {AbH, AbL, B1, B2};
#pragma unroll
        for (int mt = 0; mt < 4; mt++) {
            const int ld = (mt < 2) ? LL : HD;
            const __half* src = srcs[mt];
#pragma unroll
            for (int i = 0; i < 4; i++) {
                int c = tid + 256 * i;
                int row = c >> 3, col = c & 7;
                uint32_t sa = sbase + buf * GSTAGEB + mt * GMATB + row * ROWB + col * 16;
                cp_async16(sa, src + (size_t)row * ld + k0 + col * 8);
            }
        }
        asm volatile("cp.async.commit_group;" ::: "memory");
    };

    const int m0w = (wid & 1) * 64;
    const int n0w = (wid >> 1) * 32;

    float acc[2][4][4][4];
#pragma unroll
    for (int s = 0; s < 2; s++)
#pragma unroll
        for (int i = 0; i < 4; i++)
#pragma unroll
            for (int j = 0; j < 4; j++)
#pragma unroll
                for (int e = 0; e < 4; e++) acc[s][i][j][e] = 0.f;

    load_stage(0, 0);
    load_stage(1, 1);

    for (int it = 0; it < NIT; it++) {
        if (it + 1 < NIT) asm volatile("cp.async.wait_group 1;" ::: "memory");
        else              asm volatile("cp.async.wait_group 0;" ::: "memory");
        __syncthreads();

        const int buf = it & 1;
        const uint32_t sA = sbase + buf * GSTAGEB;

#pragma unroll
        for (int ks = 0; ks < BKK; ks += 16) {
            uint32_t ah[4][4], al[4][4];
            const uint32_t aoff = (uint32_t)(lane & 15) * ROWB + (uint32_t)ks * 2
                                + (uint32_t)(lane >> 4) * 16;
#pragma unroll
            for (int mf = 0; mf < 4; mf++) {
                uint32_t ad = (uint32_t)(m0w + mf * 16) * ROWB + aoff;
                ldm_x4(ah[mf], sA + ad);
                ldm_x4(al[mf], sA + GMATB + ad);
            }
            const uint32_t boff = (uint32_t)(((lane >> 4) << 3) + (lane & 7)) * ROWB
                                + (uint32_t)ks * 2 + (uint32_t)((lane >> 3) & 1) * 16;
#pragma unroll
            for (int s = 0; s < 2; s++) {
                uint32_t bh[4][2];
                const uint32_t sB = sA + (2 + s) * GMATB;
#pragma unroll
                for (int nf2 = 0; nf2 < 2; nf2++) {
                    uint32_t bd = (uint32_t)(n0w + nf2 * 16) * ROWB + boff;
                    uint32_t rh[4];
                    ldm_x4(rh, sB + bd);
                    bh[nf2 * 2][0] = rh[0]; bh[nf2 * 2][1] = rh[1];
                    bh[nf2 * 2 + 1][0] = rh[2]; bh[nf2 * 2 + 1][1] = rh[3];
                }
#pragma unroll
                for (int mf = 0; mf < 4; mf++)
#pragma unroll
                    for (int nf = 0; nf < 4; nf++)
                        mma16816(acc[s][mf][nf], ah[mf], bh[nf]);
#pragma unroll
                for (int mf = 0; mf < 4; mf++)
#pragma unroll
                    for (int nf = 0; nf < 4; nf++)
                        mma16816(acc[s][mf][nf], al[mf], bh[nf]);
            }
        }
        __syncthreads();
        if (it + 2 < NIT) load_stage(it + 2, it & 1);
    }

    // fused combine epilogue (conv reconstructed from fp16 hi/lo split)
    const int rbase = m0 + m0w + (lane >> 2);          // global row
    const int cloc0 = n0 + n0w + (lane & 3) * 2;       // col within head
#pragma unroll
    for (int mf = 0; mf < 4; mf++) {
#pragma unroll
        for (int half = 0; half < 2; half++) {
            int row = rbase + mf * 16 + half * 8;
            bool reset = (seg[row] == 0);
#pragma unroll
            for (int nf = 0; nf < 4; nf++) {
                int cl = cloc0 + nf * 8;               // col within head (0..255)
                size_t go = (size_t)row * LL + (size_t)z * HD + cl;
                uint32_t chp = *(const uint32_t*)&cAh[go];
                uint32_t clp = *(const uint32_t*)&cAl[go];
                float outn[2], outa[2];
#pragma unroll
                for (int e = 0; e < 2; e++) {
                    float c1 = acc[0][mf][nf][half * 2 + e] + ib[z * HD + cl + e];
                    float c2 = acc[1][mf][nf][half * 2 + e] + ab[z * HD + cl + e];
                    float gi = 1.f / (1.f + expf(-c1));
                    float ga = 1.f / (1.f + expf(-c2));
                    float ap = a_param[z * HD + cl + e];
                    float sp = log1pf(expf(ap));
                    float la = -8.f * ga * sp;
                    float a = expf(la);
                    float mult = reset ? 1.f : sqrtf(fmaxf(1.f - expf(2.f * la), 0.f));
                    uint16_t hb = (uint16_t)((e == 0) ? (chp & 0xFFFF) : (chp >> 16));
                    uint16_t lb = (uint16_t)((e == 0) ? (clp & 0xFFFF) : (clp >> 16));
                    float cvv = __half2float(__ushort_as_half(hb))
                              + __half2float(__ushort_as_half(lb));
                    outn[e] = cvv * gi * mult;
                    outa[e] = reset ? 0.f : a;
                }
                *(float2*)&G1[go] = make_float2(outn[0], outn[1]);
                *(float2*)&G2[go] = make_float2(outa[0], outa[1]);
            }
        }
    }
}

// ---------------------------------------------------------------------------
// f32 -> fp16 hi/lo split (vectorized x4)
// ---------------------------------------------------------------------------
__device__ __forceinline__ uint32_t pk2h(__half a, __half b) {
    return (uint32_t)__half_as_ushort(a) | ((uint32_t)__half_as_ushort(b) << 16);
}
__device__ __forceinline__ void split_f4h(float4 v, uint2& H, uint2& L) {
    __half hx = __float2half_rn(v.x), hy = __float2half_rn(v.y);
    __half hz = __float2half_rn(v.z), hw = __float2half_rn(v.w);
    H.x = pk2h(hx, hy);
    H.y = pk2h(hz, hw);
    L.x = pk2h(__float2half_rn(v.x - __half2float(hx)), __float2half_rn(v.y - __half2float(hy)));
    L.y = pk2h(__float2half_rn(v.z - __half2float(hz)), __float2half_rn(v.w - __half2float(hw)));
}
__global__ void split4_k(const float4* __restrict__ in, uint2* __restrict__ oh,
                         uint2* __restrict__ ol, long n4)
{
    long i = (long)blockIdx.x * blockDim.x + threadIdx.x;
    if (i >= n4) return;
    uint2 H, L;
    split_f4h(in[i], H, L);
    oh[i] = H; ol[i] = L;
}

// ---------------------------------------------------------------------------
// Transposing convert for 3 big weights in one launch
// ---------------------------------------------------------------------------
__global__ void tsplit3_k(const float* __restrict__ s0, const float* __restrict__ s1,
                          const float* __restrict__ s2,
                          __half* __restrict__ d0, __half* __restrict__ d1,
                          __half* __restrict__ d2)
{
    __shared__ float t[32][33];
    const int z = blockIdx.z;
    const float* in = (z == 0) ? s0 : (z == 1) ? s1 : s2;
    __half* oh      = (z == 0) ? d0 : (z == 1) ? d1 : d2;
    const int K = WW, N = LL;
    int kb = blockIdx.y * 32, nb = blockIdx.x * 32;
    for (int i = threadIdx.y; i < 32; i += 8)
        t[i][threadIdx.x] = in[(size_t)(kb + i) * N + nb + threadIdx.x];
    __syncthreads();
    for (int i = threadIdx.y; i < 32; i += 8) {
        int n = nb + i, k = kb + threadIdx.x;
        oh[(size_t)n * K + k] = __float2half_rn(t[threadIdx.x][i]);
    }
}

// gate weights: z 0..15 -> (head = z&7, src = z>>3 ? agate : igate)
__global__ void tsplitg_k(const float* __restrict__ ig, const float* __restrict__ ag,
                          __half* __restrict__ d1, __half* __restrict__ d2)
{
    __shared__ float t[32][33];
    const int z = blockIdx.z;
    const int head = z & 7;
    const float* in = ((z >> 3) ? ag : ig) + (size_t)head * HD * HD;
    __half* oh      = ((z >> 3) ? d2 : d1) + (size_t)head * HD * HD;
    int kb = blockIdx.y * 32, nb = blockIdx.x * 32;
    for (int i = threadIdx.y; i < 32; i += 8)
        t[i][threadIdx.x] = in[(size_t)(kb + i) * HD + nb + threadIdx.x];
    __syncthreads();
    for (int i = threadIdx.y; i < 32; i += 8) {
        int n = nb + i, k = kb + threadIdx.x;
        oh[(size_t)n * HD + k] = __float2half_rn(t[threadIdx.x][i]);
    }
}

// ---------------------------------------------------------------------------
// Causal depthwise temporal conv (TW=4) -> fp16 hi/lo split output
// ---------------------------------------------------------------------------
__global__ void conv_k(const float4* __restrict__ xb, const float4* __restrict__ cw,
                       const float4* __restrict__ cb,
                       uint2* __restrict__ oh, uint2* __restrict__ ol)
{
    long idx = (long)blockIdx.x * blockDim.x + threadIdx.x;
    if (idx >= (long)MTOT * L4C) return;
    int l4 = (int)(idx % L4C);
    int m = (int)(idx / L4C);
    int t = m % TT;
    float4 acc = cb[l4];
#pragma unroll
    for (int j = 0; j < TWD; j++) {
        int dt = TWD - 1 - j;
        if (t - dt >= 0) {
            float4 w = cw[j * L4C + l4];
            float4 x = xb[(long)(m - dt) * L4C + l4];
            acc.x = fmaf(w.x, x.x, acc.x);
            acc.y = fmaf(w.y, x.y, acc.y);
            acc.z = fmaf(w.z, x.z, acc.z);
            acc.w = fmaf(w.w, x.w, acc.w);
        }
    }
    uint2 H, L;
    split_f4h(acc, H, L);
    oh[idx] = H; ol[idx] = L;
}

// ---------------------------------------------------------------------------
// Chunked scan (scalar over L): h_t = a_t h_{t-1} + x_t
// Pass 3 fused with gate (h*y) and fp16 convert (hi only) for the final GEMM.
// ---------------------------------------------------------------------------
__global__ void scan_p1(const float* __restrict__ a, const float* __restrict__ x,
                        float* __restrict__ Aagg, float* __restrict__ Hend)
{
    long idx = (long)blockIdx.x * blockDim.x + threadIdx.x;  // over B*NCH*L
    if (idx >= (long)BB * NCH * LL) return;
    int l = (int)(idx % LL);
    int r = (int)(idx / LL);
    int c = r % NCH, b = r / NCH;
    size_t base = ((size_t)b * TT + (size_t)c * SCH) * LL + l;
    float h = 0.f, ap = 1.f;
#pragma unroll 4
    for (int t = 0; t < SCH; t++) {
        float av = a[base + (size_t)t * LL];
        h = fmaf(av, h, x[base + (size_t)t * LL]);
        ap *= av;
    }
    Aagg[idx] = ap; Hend[idx] = h;
}
__global__ void scan_p2(const float* __restrict__ Aagg, const float* __restrict__ Hend,
                        float* __restrict__ Cin)
{
    int idx = blockIdx.x * blockDim.x + threadIdx.x;
    if (idx >= BB * LL) return;
    int l = idx % LL, b = idx / LL;
    float cin = 0.f;
    for (int c = 0; c < NCH; c++) {
        size_t j = ((size_t)b * NCH + c) * LL + l;
        Cin[j] = cin;
        cin = fmaf(Aagg[j], cin, Hend[j]);
    }
}
__global__ void scan_p3f(const float* __restrict__ a, const float* __restrict__ x,
                         const float* __restrict__ Cin, const float* __restrict__ y,
                         __half* __restrict__ oh)
{
    long idx = (long)blockIdx.x * blockDim.x + threadIdx.x;
    if (idx >= (long)BB * NCH * LL) return;
    int l = (int)(idx % LL);
    int r = (int)(idx / LL);
    int c = r % NCH, b = r / NCH;
    size_t base = ((size_t)b * TT + (size_t)c * SCH) * LL + l;
    float h = Cin[idx];
#pragma unroll 4
    for (int t = 0; t < SCH; t++) {
        size_t o = base + (size_t)t * LL;
        h = fmaf(a[o], h, x[o]);
        oh[o] = __float2half_rn(h * y[o]);
    }
}

// ---------------------------------------------------------------------------
// Launch
// ---------------------------------------------------------------------------
extern "C" void kernel_launch(void* const* d_in, const int* in_sizes, int n_in,
                              void* d_out, int out_size)
{
    const float* x       = (const float*)d_in[0];
    const int*   seg     = (const int*)  d_in[1];
    const float* w_y     = (const float*)d_in[2];
    const float* b_y     = (const float*)d_in[3];
    const float* w_x     = (const float*)d_in[4];
    const float* b_x     = (const float*)d_in[5];
    const float* w_out   = (const float*)d_in[6];
    const float* b_out   = (const float*)d_in[7];
    const float* conv_w  = (const float*)d_in[8];
    const float* conv_b  = (const float*)d_in[9];
    const float* a_param = (const float*)d_in[10];
    const float* igate_w = (const float*)d_in[11];
    const float* igate_b = (const float*)d_in[12];
    const float* agate_w = (const float*)d_in[13];
    const float* agate_b = (const float*)d_in[14];
    float* out = (float*)d_out;

    float *Y, *XB, *G1, *G2, *Aagg, *Hend, *Cin;
    __half *Ah, *Al, *BY, *BX, *BO, *GW1, *GW2;
    cudaGetSymbolAddress((void**)&Y, g_Y);
    cudaGetSymbolAddress((void**)&XB, g_XB);
    cudaGetSymbolAddress((void**)&G1, g_G1);
    cudaGetSymbolAddress((void**)&G2, g_G2);
    cudaGetSymbolAddress((void**)&Ah, g_Ah);
    cudaGetSymbolAddress((void**)&Al, g_Al);
    cudaGetSymbolAddress((void**)&BY, g_BY);
    cudaGetSymbolAddress((void**)&BX, g_BX);
    cudaGetSymbolAddress((void**)&BO, g_BO);
    cudaGetSymbolAddress((void**)&GW1, g_GW1);
    cudaGetSymbolAddress((void**)&GW2, g_GW2);
    cudaGetSymbolAddress((void**)&Aagg, g_Aagg);
    cudaGetSymbolAddress((void**)&Hend, g_Hend);
    cudaGetSymbolAddress((void**)&Cin, g_Cin);

    cudaFuncSetAttribute(gemm_dual, cudaFuncAttributeMaxDynamicSharedMemorySize, GEMM_SMEM);
    cudaFuncSetAttribute(gemm_single, cudaFuncAttributeMaxDynamicSharedMemorySize, GEMM_SMEM);
    cudaFuncSetAttribute(gate_tc, cudaFuncAttributeMaxDynamicSharedMemorySize, GATE_SMEM);

    const long n4 = (long)ELEMS / 4;
    const int eb = (int)((n4 + 255) / 256);
    dim3 t3grid(WW / 32, WW / 32, 3);
    dim3 tblk(32, 8, 1);
    dim3 dualGrid(LL / 128, MTOT / 128, 2);    // (16, 64, 2)
    dim3 bigGrid(LL / 128, MTOT / 128, 1);     // (16, 64)
    dim3 gateGrid(HD / 128, MTOT / 128, HH);   // (2, 64, 8)
    dim3 ggrid(HD / 32, HD / 32, 16);

    // slot 0: split x -> Ah/Al
    split4_k<<<eb, 256>>>((const float4*)x, (uint2*)Ah, (uint2*)Al, n4);
    // slot 1: all three big weight transposes in one launch
    tsplit3_k<<<t3grid, tblk>>>(w_y, w_x, w_out, BY, BX, BO);
    // slot 2: both gate weight transposes in one launch
    tsplitg_k<<<ggrid, tblk>>>(igate_w, agate_w, GW1, GW2);
    // slot 3: merged dual GEMM -> Y (gelu, 1-product) and XB (2-product)
    gemm_dual<<<dualGrid, 256, GEMM_SMEM>>>(Ah, Al, BY, BX, b_y, b_x, Y, XB,
                                            WW, WW, WW, LL);
    // slot 4: conv -> fp16 hi/lo split into Ah/Al
    {
        long tot = (long)MTOT * L4C;
        conv_k<<<(int)((tot + 255) / 256), 256>>>((const float4*)XB, (const float4*)conv_w,
                                                  (const float4*)conv_b,
                                                  (uint2*)Ah, (uint2*)Al);
    }
    // slot 5: dual gate GEMM with fused combine
    gate_tc<<<gateGrid, 256, GATE_SMEM>>>(Ah, Al, GW1, GW2,
                                          igate_b, agate_b, a_param, seg, G1, G2);
    // slots 6-8: chunked scan ; pass 3 fused with h*y and fp16 convert into Ah
    {
        long tot = (long)BB * NCH * LL;
        int blocks = (int)((tot + 255) / 256);
        scan_p1<<<blocks, 256>>>(G2, G1, Aagg, Hend);
        scan_p2<<<(BB * LL + 255) / 256, 256>>>(Aagg, Hend, Cin);
        scan_p3f<<<blocks, 256>>>(G2, G1, Cin, Y, Ah);
    }
    // slot 9: final GEMM -> out (1-product)
    gemm_single<<<bigGrid, 256, GEMM_SMEM>>>(Ah, BO, b_out, out, LL, LL, LL, WW);
}

// round 14
// speedup vs baseline: 2.2122x; 1.1449x over previous
#include <cuda_runtime.h>
#include <cuda_bf16.h>
#include <cuda_fp16.h>
#include <math.h>
#include <stdint.h>

// Problem constants
#define BB 2
#define TT 4096
#define WW 2048
#define LL 2048
#define HH 8
#define TWD 4
#define HD 256                 // LL / HH
#define MTOT (BB * TT)         // 8192 rows
#define ELEMS ((size_t)MTOT * LL)  // 16,777,216
#define L4C (LL / 4)           // 512

#define SCH 128                // scan chunk length
#define NCH (TT / SCH)         // 32 chunks

// ---------------------------------------------------------------------------
// Scratch buffers (static device globals — no runtime allocation)
// ---------------------------------------------------------------------------
__device__ float g_Y[ELEMS];      // gelu(x @ w_y + b_y)
__device__ float g_XB[ELEMS];     // x @ w_x + b_x
__device__ float g_G1[ELEMS];     // normed
__device__ float g_G2[ELEMS];     // a_masked

__device__ __half g_Ah[ELEMS];            // fp16 hi of current A operand
__device__ __half g_Al[ELEMS];            // fp16 lo residual (gate path only)
__device__ __half g_BY[(size_t)LL * WW];  // transposed w_y fp16 [N,K]
__device__ __half g_BX[(size_t)LL * WW];  // transposed w_x fp16 [N,K]
__device__ __half g_BO[(size_t)LL * WW];  // transposed w_out fp16 [N,K]
__device__ __half g_GW1[(size_t)HH * HD * HD];
__device__ __half g_GW2[(size_t)HH * HD * HD];

__device__ float g_Aagg[(size_t)BB * NCH * LL];
__device__ float g_Hend[(size_t)BB * NCH * LL];
__device__ float g_Cin [(size_t)BB * NCH * LL];

// ---------------------------------------------------------------------------
// Low-level helpers (sm_80-portable: ldmatrix / mma.sync / cp.async only)
// ---------------------------------------------------------------------------
__device__ __forceinline__ uint32_t smem_u32(const void* p) {
    uint32_t a;
    asm("{ .reg .u64 t; cvta.to.shared.u64 t, %1; cvt.u32.u64 %0, t; }" : "=r"(a) : "l"(p));
    return a;
}
__device__ __forceinline__ void cp_async16(uint32_t saddr, const void* gaddr) {
    asm volatile("cp.async.cg.shared.global [%0], [%1], 16;" :: "r"(saddr), "l"(gaddr) : "memory");
}
__device__ __forceinline__ void ldm_x4(uint32_t* r, uint32_t addr) {
    asm volatile("ldmatrix.sync.aligned.m8n8.x4.shared.b16 {%0,%1,%2,%3}, [%4];"
                 : "=r"(r[0]), "=r"(r[1]), "=r"(r[2]), "=r"(r[3]) : "r"(addr));
}
// fp16 inputs, fp32 accumulate
__device__ __forceinline__ void mma16816(float* c, const uint32_t* a, const uint32_t* b) {
    asm volatile("mma.sync.aligned.m16n8k16.row.col.f32.f16.f16.f32 "
                 "{%0,%1,%2,%3}, {%4,%5,%6,%7}, {%8,%9}, {%0,%1,%2,%3};"
                 : "+f"(c[0]), "+f"(c[1]), "+f"(c[2]), "+f"(c[3])
                 : "r"(a[0]), "r"(a[1]), "r"(a[2]), "r"(a[3]), "r"(b[0]), "r"(b[1]));
}

// ---------------------------------------------------------------------------
// Big GEMM core: C[m,n] = EPI( sum_k A[m,k]*B[n,k] + bias[n] )
// NPROD=2: Ah*Bh + Al*Bh (full A precision); NPROD=1: Ah*Bh only.
// Tile 128x128x64, 256 threads, 8 warps of 64x32.
// 2-stage cp.async pipeline + 2 CTAs/SM for cross-CTA bubble filling.
// ---------------------------------------------------------------------------
#define BKK 64
#define ROWB 144                       // padded row bytes (64*2 + 16)
#define MATB (128 * ROWB)              // 18432 bytes per matrix tile
#define STAGEB (3 * MATB)              // 55296 bytes per stage
#define NSTAGE 2
#define GEMM_SMEM (NSTAGE * STAGEB)    // 110592 bytes -> 2 CTAs/SM

template <int NPROD>
__device__ __forceinline__
void gemm_core(const __half* __restrict__ Ah, const __half* __restrict__ Al,
               const __half* __restrict__ Bh,
               const float* __restrict__ bias, float* __restrict__ C,
               int K, int lda, int ldb, int ldc, bool dogel)
{
    extern __shared__ char sm[];
    const uint32_t sbase = smem_u32(sm);
    const int tid  = threadIdx.x;
    const int lane = tid & 31;
    const int wid  = tid >> 5;
    const int m0 = blockIdx.y * 128;
    const int n0 = blockIdx.x * 128;

    const __half* AbH = Ah + (size_t)m0 * lda;
    const __half* AbL = (NPROD == 2) ? (Al + (size_t)m0 * lda) : AbH;
    const __half* BbH = Bh + (size_t)n0 * ldb;

    const int NIT = K / BKK;

    auto load_stage = [&](int it, int buf) {
        const int k0 = it * BKK;
        const __half* srcs[3] = {AbH, AbL, BbH};
#pragma unroll
        for (int mt = 0; mt < 3; mt++) {
            if (NPROD == 1 && mt == 1) continue;   // skip Al tile
            const int ld = (mt < 2) ? lda : ldb;
            const __half* src = srcs[mt];
#pragma unroll
            for (int i = 0; i < 4; i++) {
                int c = tid + 256 * i;           // 0..1023
                int row = c >> 3, col = c & 7;
                uint32_t sa = sbase + buf * STAGEB + mt * MATB + row * ROWB + col * 16;
                cp_async16(sa, src + (size_t)row * ld + k0 + col * 8);
            }
        }
        asm volatile("cp.async.commit_group;" ::: "memory");
    };

    const int m0w = (wid & 1) * 64;
    const int n0w = (wid >> 1) * 32;

    float acc[4][4][4];
#pragma unroll
    for (int i = 0; i < 4; i++)
#pragma unroll
        for (int j = 0; j < 4; j++)
#pragma unroll
            for (int e = 0; e < 4; e++) acc[i][j][e] = 0.f;

    load_stage(0, 0);
    if (NIT > 1) load_stage(1, 1);

    for (int it = 0; it < NIT; it++) {
        if (it + 1 < NIT) asm volatile("cp.async.wait_group 1;" ::: "memory");
        else              asm volatile("cp.async.wait_group 0;" ::: "memory");
        __syncthreads();

        const int buf = it & 1;
        const uint32_t sAh = sbase + buf * STAGEB;
        const uint32_t sAl = sAh + MATB;
        const uint32_t sBh = sAh + 2 * MATB;

#pragma unroll
        for (int ks = 0; ks < BKK; ks += 16) {
            uint32_t ah[4][4], al[4][4], bh[4][2];
            const uint32_t aoff = (uint32_t)(lane & 15) * ROWB + (uint32_t)ks * 2
                                + (uint32_t)(lane >> 4) * 16;
#pragma unroll
            for (int mf = 0; mf < 4; mf++) {
                uint32_t ad = (uint32_t)(m0w + mf * 16) * ROWB + aoff;
                ldm_x4(ah[mf], sAh + ad);
                if (NPROD == 2) ldm_x4(al[mf], sAl + ad);
            }
            const uint32_t boff = (uint32_t)(((lane >> 4) << 3) + (lane & 7)) * ROWB
                                + (uint32_t)ks * 2 + (uint32_t)((lane >> 3) & 1) * 16;
#pragma unroll
            for (int nf2 = 0; nf2 < 2; nf2++) {
                uint32_t bd = (uint32_t)(n0w + nf2 * 16) * ROWB + boff;
                uint32_t rh[4];
                ldm_x4(rh, sBh + bd);
                bh[nf2 * 2][0] = rh[0]; bh[nf2 * 2][1] = rh[1];
                bh[nf2 * 2 + 1][0] = rh[2]; bh[nf2 * 2 + 1][1] = rh[3];
            }
#pragma unroll
            for (int mf = 0; mf < 4; mf++)
#pragma unroll
                for (int nf = 0; nf < 4; nf++)
                    mma16816(acc[mf][nf], ah[mf], bh[nf]);
            if (NPROD == 2) {
#pragma unroll
                for (int mf = 0; mf < 4; mf++)
#pragma unroll
                    for (int nf = 0; nf < 4; nf++)
                        mma16816(acc[mf][nf], al[mf], bh[nf]);
            }
        }
        __syncthreads();
        if (it + 2 < NIT) load_stage(it + 2, it & 1);
    }

    // epilogue: bias + optional gelu, direct float2 stores
    const int rbase = m0 + m0w + (lane >> 2);
    const int cbase = n0 + n0w + (lane & 3) * 2;
#pragma unroll
    for (int mf = 0; mf < 4; mf++) {
#pragma unroll
        for (int nf = 0; nf < 4; nf++) {
            int col = cbase + nf * 8;
            float b0 = bias[col], b1 = bias[col + 1];
            float v[4] = {acc[mf][nf][0] + b0, acc[mf][nf][1] + b1,
                          acc[mf][nf][2] + b0, acc[mf][nf][3] + b1};
            if (dogel) {
#pragma unroll
                for (int e = 0; e < 4; e++) {
                    float x = v[e];
                    float t = tanhf(0.7978845608028654f * (x + 0.044715f * x * x * x));
                    v[e] = 0.5f * x * (1.f + t);
                }
            }
            int r0 = rbase + mf * 16;
            *(float2*)&C[(size_t)r0 * ldc + col]       = make_float2(v[0], v[1]);
            *(float2*)&C[(size_t)(r0 + 8) * ldc + col] = make_float2(v[2], v[3]);
        }
    }
}

// dual-output launch: z=0 -> gelu(x@w_y+b_y) into Y ; z=1 -> x@w_x+b_x into XB
// both 1-product (A-side fp16 single-rounded; error comparable to the
// already-present B-side fp16 weight quantization)
__global__ __launch_bounds__(256, 2)
void gemm_dual(const __half* __restrict__ Ah,
               const __half* __restrict__ B0, const __half* __restrict__ B1,
               const float* __restrict__ bias0, const float* __restrict__ bias1,
               float* __restrict__ C0, float* __restrict__ C1,
               int K, int lda, int ldb, int ldc)
{
    if (blockIdx.z == 0)
        gemm_core<1>(Ah, nullptr, B0, bias0, C0, K, lda, ldb, ldc, true);
    else
        gemm_core<1>(Ah, nullptr, B1, bias1, C1, K, lda, ldb, ldc, false);
}

// single-output 1-product launch (final GEMM)
__global__ __launch_bounds__(256, 2)
void gemm_single(const __half* __restrict__ Ah, const __half* __restrict__ Bh,
                 const float* __restrict__ bias, float* __restrict__ C,
                 int K, int lda, int ldb, int ldc)
{
    gemm_core<1>(Ah, nullptr, Bh, bias, C, K, lda, ldb, ldc, false);
}

// ---------------------------------------------------------------------------
// Dual gate GEMM + fused combine epilogue. 2xfp16 split (kept: sensitive path).
// 4 matrices per stage (Ah, Al, W1, W2). conv reconstructed as Ah+Al (~exact).
// ---------------------------------------------------------------------------
#define GMATB (128 * ROWB)             // 18432
#define GSTAGEB (4 * GMATB)            // 73728
#define GATE_SMEM (2 * GSTAGEB)        // 147456

__global__ __launch_bounds__(256, 1)
void gate_tc(const __half* __restrict__ cAh, const __half* __restrict__ cAl,
             const __half* __restrict__ W1, const __half* __restrict__ W2,
             const float* __restrict__ ib, const float* __restrict__ ab,
             const float* __restrict__ a_param, const int* __restrict__ seg,
             float* __restrict__ G1, float* __restrict__ G2)
{
    extern __shared__ char sm[];
    const uint32_t sbase = smem_u32(sm);
    const int tid  = threadIdx.x;
    const int lane = tid & 31;
    const int wid  = tid >> 5;
    const int z  = blockIdx.z;           // head
    const int m0 = blockIdx.y * 128;
    const int n0 = blockIdx.x * 128;     // 0 or 128 within head

    const __half* AbH = cAh + (size_t)m0 * LL + z * HD;
    const __half* AbL = cAl + (size_t)m0 * LL + z * HD;
    const __half* B1  = W1 + (size_t)z * HD * HD + (size_t)n0 * HD;
    const __half* B2  = W2 + (size_t)z * HD * HD + (size_t)n0 * HD;

    const int NIT = HD / BKK;   // 4

    auto load_stage = [&](int it, int buf) {
        const int k0 = it * BKK;
        const __half* srcs[4] = {AbH, AbL, B1, B2};
#pragma unroll
        for (int mt = 0; mt < 4; mt++) {
            const int ld = (mt < 2) ? LL : HD;
            const __half* src = srcs[mt];
#pragma unroll
            for (int i = 0; i < 4; i++) {
                int c = tid + 256 * i;
                int row = c >> 3, col = c & 7;
                uint32_t sa = sbase + buf * GSTAGEB + mt * GMATB + row * ROWB + col * 16;
                cp_async16(sa, src + (size_t)row * ld + k0 + col * 8);
            }
        }
        asm volatile("cp.async.commit_group;" ::: "memory");
    };

    const int m0w = (wid & 1) * 64;
    const int n0w = (wid >> 1) * 32;

    float acc[2][4][4][4];
#pragma unroll
    for (int s = 0; s < 2; s++)
#pragma unroll
        for (int i = 0; i < 4; i++)
#pragma unroll
            for (int j = 0; j < 4; j++)
#pragma unroll
                for (int e = 0; e < 4; e++) acc[s][i][j][e] = 0.f;

    load_stage(0, 0);
    load_stage(1, 1);

    for (int it = 0; it < NIT; it++) {
        if (it + 1 < NIT) asm volatile("cp.async.wait_group 1;" ::: "memory");
        else              asm volatile("cp.async.wait_group 0;" ::: "memory");
        __syncthreads();

        const int buf = it & 1;
        const uint32_t sA = sbase + buf * GSTAGEB;

#pragma unroll
        for (int ks = 0; ks < BKK; ks += 16) {
            uint32_t ah[4][4], al[4][4];
            const uint32_t aoff = (uint32_t)(lane & 15) * ROWB + (uint32_t)ks * 2
                                + (uint32_t)(lane >> 4) * 16;
#pragma unroll
            for (int mf = 0; mf < 4; mf++) {
                uint32_t ad = (uint32_t)(m0w + mf * 16) * ROWB + aoff;
                ldm_x4(ah[mf], sA + ad);
                ldm_x4(al[mf], sA + GMATB + ad);
            }
            const uint32_t boff = (uint32_t)(((lane >> 4) << 3) + (lane & 7)) * ROWB
                                + (uint32_t)ks * 2 + (uint32_t)((lane >> 3) & 1) * 16;
#pragma unroll
            for (int s = 0; s < 2; s++) {
                uint32_t bh[4][2];
                const uint32_t sB = sA + (2 + s) * GMATB;
#pragma unroll
                for (int nf2 = 0; nf2 < 2; nf2++) {
                    uint32_t bd = (uint32_t)(n0w + nf2 * 16) * ROWB + boff;
                    uint32_t rh[4];
                    ldm_x4(rh, sB + bd);
                    bh[nf2 * 2][0] = rh[0]; bh[nf2 * 2][1] = rh[1];
                    bh[nf2 * 2 + 1][0] = rh[2]; bh[nf2 * 2 + 1][1] = rh[3];
                }
#pragma unroll
                for (int mf = 0; mf < 4; mf++)
#pragma unroll
                    for (int nf = 0; nf < 4; nf++)
                        mma16816(acc[s][mf][nf], ah[mf], bh[nf]);
#pragma unroll
                for (int mf = 0; mf < 4; mf++)
#pragma unroll
                    for (int nf = 0; nf < 4; nf++)
                        mma16816(acc[s][mf][nf], al[mf], bh[nf]);
            }
        }
        __syncthreads();
        if (it + 2 < NIT) load_stage(it + 2, it & 1);
    }

    // fused combine epilogue (conv reconstructed from fp16 hi/lo split)
    const int rbase = m0 + m0w + (lane >> 2);          // global row
    const int cloc0 = n0 + n0w + (lane & 3) * 2;       // col within head
#pragma unroll
    for (int mf = 0; mf < 4; mf++) {
#pragma unroll
        for (int half = 0; half < 2; half++) {
            int row = rbase + mf * 16 + half * 8;
            bool reset = (seg[row] == 0);
#pragma unroll
            for (int nf = 0; nf < 4; nf++) {
                int cl = cloc0 + nf * 8;               // col within head (0..255)
                size_t go = (size_t)row * LL + (size_t)z * HD + cl;
                uint32_t chp = *(const uint32_t*)&cAh[go];
                uint32_t clp = *(const uint32_t*)&cAl[go];
                float outn[2], outa[2];
#pragma unroll
                for (int e = 0; e < 2; e++) {
                    float c1 = acc[0][mf][nf][half * 2 + e] + ib[z * HD + cl + e];
                    float c2 = acc[1][mf][nf][half * 2 + e] + ab[z * HD + cl + e];
                    float gi = 1.f / (1.f + expf(-c1));
                    float ga = 1.f / (1.f + expf(-c2));
                    float ap = a_param[z * HD + cl + e];
                    float sp = log1pf(expf(ap));
                    float la = -8.f * ga * sp;
                    float a = expf(la);
                    float mult = reset ? 1.f : sqrtf(fmaxf(1.f - expf(2.f * la), 0.f));
                    uint16_t hb = (uint16_t)((e == 0) ? (chp & 0xFFFF) : (chp >> 16));
                    uint16_t lb = (uint16_t)((e == 0) ? (clp & 0xFFFF) : (clp >> 16));
                    float cvv = __half2float(__ushort_as_half(hb))
                              + __half2float(__ushort_as_half(lb));
                    outn[e] = cvv * gi * mult;
                    outa[e] = reset ? 0.f : a;
                }
                *(float2*)&G1[go] = make_float2(outn[0], outn[1]);
                *(float2*)&G2[go] = make_float2(outa[0], outa[1]);
            }
        }
    }
}

// ---------------------------------------------------------------------------
// f32 -> fp16 convert (hi only, vectorized x4)
// ---------------------------------------------------------------------------
__device__ __forceinline__ uint32_t pk2h(__half a, __half b) {
    return (uint32_t)__half_as_ushort(a) | ((uint32_t)__half_as_ushort(b) << 16);
}
__device__ __forceinline__ void split_f4h(float4 v, uint2& H, uint2& L) {
    __half hx = __float2half_rn(v.x), hy = __float2half_rn(v.y);
    __half hz = __float2half_rn(v.z), hw = __float2half_rn(v.w);
    H.x = pk2h(hx, hy);
    H.y = pk2h(hz, hw);
    L.x = pk2h(__float2half_rn(v.x - __half2float(hx)), __float2half_rn(v.y - __half2float(hy)));
    L.y = pk2h(__float2half_rn(v.z - __half2float(hz)), __float2half_rn(v.w - __half2float(hw)));
}
__global__ void conv4_k(const float4* __restrict__ in, uint2* __restrict__ oh, long n4)
{
    long i = (long)blockIdx.x * blockDim.x + threadIdx.x;
    if (i >= n4) return;
    float4 v = in[i];
    uint2 H;
    H.x = pk2h(__float2half_rn(v.x), __float2half_rn(v.y));
    H.y = pk2h(__float2half_rn(v.z), __float2half_rn(v.w));
    oh[i] = H;
}

// ---------------------------------------------------------------------------
// Transposing convert for 3 big weights in one launch
// ---------------------------------------------------------------------------
__global__ void tsplit3_k(const float* __restrict__ s0, const float* __restrict__ s1,
                          const float* __restrict__ s2,
                          __half* __restrict__ d0, __half* __restrict__ d1,
                          __half* __restrict__ d2)
{
    __shared__ float t[32][33];
    const int z = blockIdx.z;
    const float* in = (z == 0) ? s0 : (z == 1) ? s1 : s2;
    __half* oh      = (z == 0) ? d0 : (z == 1) ? d1 : d2;
    const int K = WW, N = LL;
    int kb = blockIdx.y * 32, nb = blockIdx.x * 32;
    for (int i = threadIdx.y; i < 32; i += 8)
        t[i][threadIdx.x] = in[(size_t)(kb + i) * N + nb + threadIdx.x];
    __syncthreads();
    for (int i = threadIdx.y; i < 32; i += 8) {
        int n = nb + i, k = kb + threadIdx.x;
        oh[(size_t)n * K + k] = __float2half_rn(t[threadIdx.x][i]);
    }
}

// gate weights: z 0..15 -> (head = z&7, src = z>>3 ? agate : igate)
__global__ void tsplitg_k(const float* __restrict__ ig, const float* __restrict__ ag,
                          __half* __restrict__ d1, __half* __restrict__ d2)
{
    __shared__ float t[32][33];
    const int z = blockIdx.z;
    const int head = z & 7;
    const float* in = ((z >> 3) ? ag : ig) + (size_t)head * HD * HD;
    __half* oh      = ((z >> 3) ? d2 : d1) + (size_t)head * HD * HD;
    int kb = blockIdx.y * 32, nb = blockIdx.x * 32;
    for (int i = threadIdx.y; i < 32; i += 8)
        t[i][threadIdx.x] = in[(size_t)(kb + i) * HD + nb + threadIdx.x];
    __syncthreads();
    for (int i = threadIdx.y; i < 32; i += 8) {
        int n = nb + i, k = kb + threadIdx.x;
        oh[(size_t)n * HD + k] = __float2half_rn(t[threadIdx.x][i]);
    }
}

// ---------------------------------------------------------------------------
// Causal depthwise temporal conv (TW=4) -> fp16 hi/lo split output (gate path)
// ---------------------------------------------------------------------------
__global__ void conv_k(const float4* __restrict__ xb, const float4* __restrict__ cw,
                       const float4* __restrict__ cb,
                       uint2* __restrict__ oh, uint2* __restrict__ ol)
{
    long idx = (long)blockIdx.x * blockDim.x + threadIdx.x;
    if (idx >= (long)MTOT * L4C) return;
    int l4 = (int)(idx % L4C);
    int m = (int)(idx / L4C);
    int t = m % TT;
    float4 acc = cb[l4];
#pragma unroll
    for (int j = 0; j < TWD; j++) {
        int dt = TWD - 1 - j;
        if (t - dt >= 0) {
            float4 w = cw[j * L4C + l4];
            float4 x = xb[(long)(m - dt) * L4C + l4];
            acc.x = fmaf(w.x, x.x, acc.x);
            acc.y = fmaf(w.y, x.y, acc.y);
            acc.z = fmaf(w.z, x.z, acc.z);
            acc.w = fmaf(w.w, x.w, acc.w);
        }
    }
    uint2 H, L;
    split_f4h(acc, H, L);
    oh[idx] = H; ol[idx] = L;
}

// ---------------------------------------------------------------------------
// Chunked scan (scalar over L): h_t = a_t h_{t-1} + x_t
// Pass 3 fused with gate (h*y) and fp16 convert (hi only) for the final GEMM.
// ---------------------------------------------------------------------------
__global__ void scan_p1(const float* __restrict__ a, const float* __restrict__ x,
                        float* __restrict__ Aagg, float* __restrict__ Hend)
{
    long idx = (long)blockIdx.x * blockDim.x + threadIdx.x;  // over B*NCH*L
    if (idx >= (long)BB * NCH * LL) return;
    int l = (int)(idx % LL);
    int r = (int)(idx / LL);
    int c = r % NCH, b = r / NCH;
    size_t base = ((size_t)b * TT + (size_t)c * SCH) * LL + l;
    float h = 0.f, ap = 1.f;
#pragma unroll 4
    for (int t = 0; t < SCH; t++) {
        float av = a[base + (size_t)t * LL];
        h = fmaf(av, h, x[base + (size_t)t * LL]);
        ap *= av;
    }
    Aagg[idx] = ap; Hend[idx] = h;
}
__global__ void scan_p2(const float* __restrict__ Aagg, const float* __restrict__ Hend,
                        float* __restrict__ Cin)
{
    int idx = blockIdx.x * blockDim.x + threadIdx.x;
    if (idx >= BB * LL) return;
    int l = idx % LL, b = idx / LL;
    float cin = 0.f;
    for (int c = 0; c < NCH; c++) {
        size_t j = ((size_t)b * NCH + c) * LL + l;
        Cin[j] = cin;
        cin = fmaf(Aagg[j], cin, Hend[j]);
    }
}
__global__ void scan_p3f(const float* __restrict__ a, const float* __restrict__ x,
                         const float* __restrict__ Cin, const float* __restrict__ y,
                         __half* __restrict__ oh)
{
    long idx = (long)blockIdx.x * blockDim.x + threadIdx.x;
    if (idx >= (long)BB * NCH * LL) return;
    int l = (int)(idx % LL);
    int r = (int)(idx / LL);
    int c = r % NCH, b = r / NCH;
    size_t base = ((size_t)b * TT + (size_t)c * SCH) * LL + l;
    float h = Cin[idx];
#pragma unroll 4
    for (int t = 0; t < SCH; t++) {
        size_t o = base + (size_t)t * LL;
        h = fmaf(a[o], h, x[o]);
        oh[o] = __float2half_rn(h * y[o]);
    }
}

// ---------------------------------------------------------------------------
// Launch
// ---------------------------------------------------------------------------
extern "C" void kernel_launch(void* const* d_in, const int* in_sizes, int n_in,
                              void* d_out, int out_size)
{
    const float* x       = (const float*)d_in[0];
    const int*   seg     = (const int*)  d_in[1];
    const float* w_y     = (const float*)d_in[2];
    const float* b_y     = (const float*)d_in[3];
    const float* w_x     = (const float*)d_in[4];
    const float* b_x     = (const float*)d_in[5];
    const float* w_out   = (const float*)d_in[6];
    const float* b_out   = (const float*)d_in[7];
    const float* conv_w  = (const float*)d_in[8];
    const float* conv_b  = (const float*)d_in[9];
    const float* a_param = (const float*)d_in[10];
    const float* igate_w = (const float*)d_in[11];
    const float* igate_b = (const float*)d_in[12];
    const float* agate_w = (const float*)d_in[13];
    const float* agate_b = (const float*)d_in[14];
    float* out = (float*)d_out;

    float *Y, *XB, *G1, *G2, *Aagg, *Hend, *Cin;
    __half *Ah, *Al, *BY, *BX, *BO, *GW1, *GW2;
    cudaGetSymbolAddress((void**)&Y, g_Y);
    cudaGetSymbolAddress((void**)&XB, g_XB);
    cudaGetSymbolAddress((void**)&G1, g_G1);
    cudaGetSymbolAddress((void**)&G2, g_G2);
    cudaGetSymbolAddress((void**)&Ah, g_Ah);
    cudaGetSymbolAddress((void**)&Al, g_Al);
    cudaGetSymbolAddress((void**)&BY, g_BY);
    cudaGetSymbolAddress((void**)&BX, g_BX);
    cudaGetSymbolAddress((void**)&BO, g_BO);
    cudaGetSymbolAddress((void**)&GW1, g_GW1);
    cudaGetSymbolAddress((void**)&GW2, g_GW2);
    cudaGetSymbolAddress((void**)&Aagg, g_Aagg);
    cudaGetSymbolAddress((void**)&Hend, g_Hend);
    cudaGetSymbolAddress((void**)&Cin, g_Cin);

    cudaFuncSetAttribute(gemm_dual, cudaFuncAttributeMaxDynamicSharedMemorySize, GEMM_SMEM);
    cudaFuncSetAttribute(gemm_single, cudaFuncAttributeMaxDynamicSharedMemorySize, GEMM_SMEM);
    cudaFuncSetAttribute(gate_tc, cudaFuncAttributeMaxDynamicSharedMemorySize, GATE_SMEM);

    const long n4 = (long)ELEMS / 4;
    const int eb = (int)((n4 + 255) / 256);
    dim3 t3grid(WW / 32, WW / 32, 3);
    dim3 tblk(32, 8, 1);
    dim3 dualGrid(LL / 128, MTOT / 128, 2);    // (16, 64, 2)
    dim3 bigGrid(LL / 128, MTOT / 128, 1);     // (16, 64)
    dim3 gateGrid(HD / 128, MTOT / 128, HH);   // (2, 64, 8)
    dim3 ggrid(HD / 32, HD / 32, 16);

    // slot 0: convert x -> Ah (fp16, hi only)
    conv4_k<<<eb, 256>>>((const float4*)x, (uint2*)Ah, n4);
    // slot 1: all three big weight transposes in one launch
    tsplit3_k<<<t3grid, tblk>>>(w_y, w_x, w_out, BY, BX, BO);
    // slot 2: both gate weight transposes in one launch
    tsplitg_k<<<ggrid, tblk>>>(igate_w, agate_w, GW1, GW2);
    // slot 3: merged dual GEMM -> Y (gelu) and XB, both 1-product
    gemm_dual<<<dualGrid, 256, GEMM_SMEM>>>(Ah, BY, BX, b_y, b_x, Y, XB,
                                            WW, WW, WW, LL);
    // slot 4: conv -> fp16 hi/lo split into Ah/Al (gate path keeps 2-product)
    {
        long tot = (long)MTOT * L4C;
        conv_k<<<(int)((tot + 255) / 256), 256>>>((const float4*)XB, (const float4*)conv_w,
                                                  (const float4*)conv_b,
                                                  (uint2*)Ah, (uint2*)Al);
    }
    // slot 5: dual gate GEMM with fused combine
    gate_tc<<<gateGrid, 256, GATE_SMEM>>>(Ah, Al, GW1, GW2,
                                          igate_b, agate_b, a_param, seg, G1, G2);
    // slots 6-8: chunked scan ; pass 3 fused with h*y and fp16 convert into Ah
    {
        long tot = (long)BB * NCH * LL;
        int blocks = (int)((tot + 255) / 256);
        scan_p1<<<blocks, 256>>>(G2, G1, Aagg, Hend);
        scan_p2<<<(BB * LL + 255) / 256, 256>>>(Aagg, Hend, Cin);
        scan_p3f<<<blocks, 256>>>(G2, G1, Cin, Y, Ah);
    }
    // slot 9: final GEMM -> out (1-product)
    gemm_single<<<bigGrid, 256, GEMM_SMEM>>>(Ah, BO, b_out, out, LL, LL, LL, WW);
}

// round 15
// speedup vs baseline: 2.3673x; 1.0701x over previous
#include <cuda_runtime.h>
#include <cuda_bf16.h>
#include <cuda_fp16.h>
#include <math.h>
#include <stdint.h>

// Problem constants
#define BB 2
#define TT 4096
#define WW 2048
#define LL 2048
#define HH 8
#define TWD 4
#define HD 256                 // LL / HH
#define MTOT (BB * TT)         // 8192 rows
#define ELEMS ((size_t)MTOT * LL)  // 16,777,216
#define L4C (LL / 4)           // 512

#define SCH 128                // scan chunk length
#define NCH (TT / SCH)         // 32 chunks

// ---------------------------------------------------------------------------
// Scratch buffers (static device globals — no runtime allocation)
// ---------------------------------------------------------------------------
__device__ __half g_Yh[ELEMS];    // gelu(x @ w_y + b_y) in fp16 (1:1 output path)
__device__ float g_XB[ELEMS];     // x @ w_x + b_x
__device__ float g_G1[ELEMS];     // normed
__device__ float g_G2[ELEMS];     // a_masked

__device__ __half g_Ah[ELEMS];            // fp16 hi of current A operand
__device__ __half g_Al[ELEMS];            // fp16 lo residual (gate path only)
__device__ __half g_BY[(size_t)LL * WW];  // transposed w_y fp16 [N,K]
__device__ __half g_BX[(size_t)LL * WW];  // transposed w_x fp16 [N,K]
__device__ __half g_BO[(size_t)LL * WW];  // transposed w_out fp16 [N,K]
__device__ __half g_GW1[(size_t)HH * HD * HD];
__device__ __half g_GW2[(size_t)HH * HD * HD];

__device__ float g_Aagg[(size_t)BB * NCH * LL];
__device__ float g_Hend[(size_t)BB * NCH * LL];
__device__ float g_Cin [(size_t)BB * NCH * LL];

// ---------------------------------------------------------------------------
// Low-level helpers (sm_80-portable: ldmatrix / mma.sync / cp.async only)
// ---------------------------------------------------------------------------
__device__ __forceinline__ uint32_t smem_u32(const void* p) {
    uint32_t a;
    asm("{ .reg .u64 t; cvta.to.shared.u64 t, %1; cvt.u32.u64 %0, t; }" : "=r"(a) : "l"(p));
    return a;
}
__device__ __forceinline__ void cp_async16(uint32_t saddr, const void* gaddr) {
    asm volatile("cp.async.cg.shared.global [%0], [%1], 16;" :: "r"(saddr), "l"(gaddr) : "memory");
}
__device__ __forceinline__ void ldm_x4(uint32_t* r, uint32_t addr) {
    asm volatile("ldmatrix.sync.aligned.m8n8.x4.shared.b16 {%0,%1,%2,%3}, [%4];"
                 : "=r"(r[0]), "=r"(r[1]), "=r"(r[2]), "=r"(r[3]) : "r"(addr));
}
// fp16 inputs, fp32 accumulate
__device__ __forceinline__ void mma16816(float* c, const uint32_t* a, const uint32_t* b) {
    asm volatile("mma.sync.aligned.m16n8k16.row.col.f32.f16.f16.f32 "
                 "{%0,%1,%2,%3}, {%4,%5,%6,%7}, {%8,%9}, {%0,%1,%2,%3};"
                 : "+f"(c[0]), "+f"(c[1]), "+f"(c[2]), "+f"(c[3])
                 : "r"(a[0]), "r"(a[1]), "r"(a[2]), "r"(a[3]), "r"(b[0]), "r"(b[1]));
}

// ---------------------------------------------------------------------------
// Big GEMM core: C[m,n] = EPI( sum_k A[m,k]*B[n,k] + bias[n] )
// 1-product fp16 (Ah*Bh). HOUT selects f32 or fp16 output.
// Tile 128x128x64, 256 threads, 8 warps of 64x32.
// 2-stage cp.async pipeline + 2 CTAs/SM.
// ---------------------------------------------------------------------------
#define BKK 64
#define ROWB 144                       // padded row bytes (64*2 + 16)
#define MATB (128 * ROWB)              // 18432 bytes per matrix tile
#define STAGEB (3 * MATB)              // 55296 bytes per stage (Ah, spare, Bh)
#define NSTAGE 2
#define GEMM_SMEM (NSTAGE * STAGEB)    // 110592 bytes -> 2 CTAs/SM

template <bool HOUT>
__device__ __forceinline__
void gemm_core(const __half* __restrict__ Ah, const __half* __restrict__ Bh,
               const float* __restrict__ bias, void* __restrict__ Cv,
               int K, int lda, int ldb, int ldc, bool dogel)
{
    extern __shared__ char sm[];
    const uint32_t sbase = smem_u32(sm);
    const int tid  = threadIdx.x;
    const int lane = tid & 31;
    const int wid  = tid >> 5;
    const int m0 = blockIdx.y * 128;
    const int n0 = blockIdx.x * 128;

    const __half* AbH = Ah + (size_t)m0 * lda;
    const __half* BbH = Bh + (size_t)n0 * ldb;

    const int NIT = K / BKK;

    auto load_stage = [&](int it, int buf) {
        const int k0 = it * BKK;
        const __half* srcs[2] = {AbH, BbH};
#pragma unroll
        for (int mt = 0; mt < 2; mt++) {
            const int ld = (mt == 0) ? lda : ldb;
            const __half* src = srcs[mt];
#pragma unroll
            for (int i = 0; i < 4; i++) {
                int c = tid + 256 * i;           // 0..1023
                int row = c >> 3, col = c & 7;
                uint32_t sa = sbase + buf * STAGEB + (mt * 2) * MATB + row * ROWB + col * 16;
                cp_async16(sa, src + (size_t)row * ld + k0 + col * 8);
            }
        }
        asm volatile("cp.async.commit_group;" ::: "memory");
    };

    const int m0w = (wid & 1) * 64;
    const int n0w = (wid >> 1) * 32;

    float acc[4][4][4];
#pragma unroll
    for (int i = 0; i < 4; i++)
#pragma unroll
        for (int j = 0; j < 4; j++)
#pragma unroll
            for (int e = 0; e < 4; e++) acc[i][j][e] = 0.f;

    load_stage(0, 0);
    if (NIT > 1) load_stage(1, 1);

    for (int it = 0; it < NIT; it++) {
        if (it + 1 < NIT) asm volatile("cp.async.wait_group 1;" ::: "memory");
        else              asm volatile("cp.async.wait_group 0;" ::: "memory");
        __syncthreads();

        const int buf = it & 1;
        const uint32_t sAh = sbase + buf * STAGEB;
        const uint32_t sBh = sAh + 2 * MATB;

#pragma unroll
        for (int ks = 0; ks < BKK; ks += 16) {
            uint32_t ah[4][4], bh[4][2];
            const uint32_t aoff = (uint32_t)(lane & 15) * ROWB + (uint32_t)ks * 2
                                + (uint32_t)(lane >> 4) * 16;
#pragma unroll
            for (int mf = 0; mf < 4; mf++) {
                uint32_t ad = (uint32_t)(m0w + mf * 16) * ROWB + aoff;
                ldm_x4(ah[mf], sAh + ad);
            }
            const uint32_t boff = (uint32_t)(((lane >> 4) << 3) + (lane & 7)) * ROWB
                                + (uint32_t)ks * 2 + (uint32_t)((lane >> 3) & 1) * 16;
#pragma unroll
            for (int nf2 = 0; nf2 < 2; nf2++) {
                uint32_t bd = (uint32_t)(n0w + nf2 * 16) * ROWB + boff;
                uint32_t rh[4];
                ldm_x4(rh, sBh + bd);
                bh[nf2 * 2][0] = rh[0]; bh[nf2 * 2][1] = rh[1];
                bh[nf2 * 2 + 1][0] = rh[2]; bh[nf2 * 2 + 1][1] = rh[3];
            }
#pragma unroll
            for (int mf = 0; mf < 4; mf++)
#pragma unroll
                for (int nf = 0; nf < 4; nf++)
                    mma16816(acc[mf][nf], ah[mf], bh[nf]);
        }
        __syncthreads();
        if (it + 2 < NIT) load_stage(it + 2, it & 1);
    }

    // epilogue: bias + optional gelu
    const int rbase = m0 + m0w + (lane >> 2);
    const int cbase = n0 + n0w + (lane & 3) * 2;
    float* Cf = (float*)Cv;
    __half* Ch = (__half*)Cv;
#pragma unroll
    for (int mf = 0; mf < 4; mf++) {
#pragma unroll
        for (int nf = 0; nf < 4; nf++) {
            int col = cbase + nf * 8;
            float b0 = bias[col], b1 = bias[col + 1];
            float v[4] = {acc[mf][nf][0] + b0, acc[mf][nf][1] + b1,
                          acc[mf][nf][2] + b0, acc[mf][nf][3] + b1};
            if (dogel) {
#pragma unroll
                for (int e = 0; e < 4; e++) {
                    float x = v[e];
                    float t = tanhf(0.7978845608028654f * (x + 0.044715f * x * x * x));
                    v[e] = 0.5f * x * (1.f + t);
                }
            }
            int r0 = rbase + mf * 16;
            if (HOUT) {
                *(__half2*)&Ch[(size_t)r0 * ldc + col] =
                    __floats2half2_rn(v[0], v[1]);
                *(__half2*)&Ch[(size_t)(r0 + 8) * ldc + col] =
                    __floats2half2_rn(v[2], v[3]);
            } else {
                *(float2*)&Cf[(size_t)r0 * ldc + col]       = make_float2(v[0], v[1]);
                *(float2*)&Cf[(size_t)(r0 + 8) * ldc + col] = make_float2(v[2], v[3]);
            }
        }
    }
}

// dual-output launch: z=0 -> gelu(x@w_y+b_y) into Yh (fp16) ; z=1 -> XB (f32)
__global__ __launch_bounds__(256, 2)
void gemm_dual(const __half* __restrict__ Ah,
               const __half* __restrict__ B0, const __half* __restrict__ B1,
               const float* __restrict__ bias0, const float* __restrict__ bias1,
               __half* __restrict__ C0, float* __restrict__ C1,
               int K, int lda, int ldb, int ldc)
{
    if (blockIdx.z == 0)
        gemm_core<true >(Ah, B0, bias0, C0, K, lda, ldb, ldc, true);
    else
        gemm_core<false>(Ah, B1, bias1, C1, K, lda, ldb, ldc, false);
}

// single-output launch (final GEMM, f32 out)
__global__ __launch_bounds__(256, 2)
void gemm_single(const __half* __restrict__ Ah, const __half* __restrict__ Bh,
                 const float* __restrict__ bias, float* __restrict__ C,
                 int K, int lda, int ldb, int ldc)
{
    gemm_core<false>(Ah, Bh, bias, C, K, lda, ldb, ldc, false);
}

// ---------------------------------------------------------------------------
// Dual gate GEMM + fused combine epilogue. 2xfp16 A-split (sensitive path).
// Tile 128x64 per CTA -> stage = Ah,Al (128 rows) + W1,W2 (64 rows) = 55296 B,
// 2 stages = 110592 B -> 2 CTAs/SM.
// ---------------------------------------------------------------------------
#define GA_B (128 * ROWB)              // 18432 (A tile)
#define GW_B (64 * ROWB)               // 9216  (W tile)
#define GSTAGEB (2 * GA_B + 2 * GW_B)  // 55296
#define GATE_SMEM (2 * GSTAGEB)        // 110592

__global__ __launch_bounds__(256, 2)
void gate_tc(const __half* __restrict__ cAh, const __half* __restrict__ cAl,
             const __half* __restrict__ W1, const __half* __restrict__ W2,
             const float* __restrict__ ib, const float* __restrict__ ab,
             const float* __restrict__ a_param, const int* __restrict__ seg,
             float* __restrict__ G1, float* __restrict__ G2)
{
    extern __shared__ char sm[];
    const uint32_t sbase = smem_u32(sm);
    const int tid  = threadIdx.x;
    const int lane = tid & 31;
    const int wid  = tid >> 5;
    const int z  = blockIdx.z;           // head
    const int m0 = blockIdx.y * 128;
    const int n0 = blockIdx.x * 64;      // 64-col slab within head

    const __half* AbH = cAh + (size_t)m0 * LL + z * HD;
    const __half* AbL = cAl + (size_t)m0 * LL + z * HD;
    const __half* B1  = W1 + (size_t)z * HD * HD + (size_t)n0 * HD;
    const __half* B2  = W2 + (size_t)z * HD * HD + (size_t)n0 * HD;

    const int NIT = HD / BKK;   // 4

    auto load_stage = [&](int it, int buf) {
        const int k0 = it * BKK;
        const uint32_t sb = sbase + buf * GSTAGEB;
        // A tiles: 128 rows each
        const __half* asrc[2] = {AbH, AbL};
#pragma unroll
        for (int mt = 0; mt < 2; mt++) {
#pragma unroll
            for (int i = 0; i < 4; i++) {
                int c = tid + 256 * i;            // 0..1023
                int row = c >> 3, col = c & 7;
                uint32_t sa = sb + mt * GA_B + row * ROWB + col * 16;
                cp_async16(sa, asrc[mt] + (size_t)row * LL + k0 + col * 8);
            }
        }
        // W tiles: 64 rows each
        const __half* wsrc[2] = {B1, B2};
#pragma unroll
        for (int mt = 0; mt < 2; mt++) {
#pragma unroll
            for (int i = 0; i < 2; i++) {
                int c = tid + 256 * i;            // 0..511
                int row = c >> 3, col = c & 7;
                uint32_t sa = sb + 2 * GA_B + mt * GW_B + row * ROWB + col * 16;
                cp_async16(sa, wsrc[mt] + (size_t)row * HD + k0 + col * 8);
            }
        }
        asm volatile("cp.async.commit_group;" ::: "memory");
    };

    // 2 m-positions x 4 n-positions of 16 cols
    const int m0w = (wid & 1) * 64;
    const int n0w = (wid >> 1) * 16;

    float acc[2][4][2][4];
#pragma unroll
    for (int s = 0; s < 2; s++)
#pragma unroll
        for (int i = 0; i < 4; i++)
#pragma unroll
            for (int j = 0; j < 2; j++)
#pragma unroll
                for (int e = 0; e < 4; e++) acc[s][i][j][e] = 0.f;

    load_stage(0, 0);
    load_stage(1, 1);

    for (int it = 0; it < NIT; it++) {
        if (it + 1 < NIT) asm volatile("cp.async.wait_group 1;" ::: "memory");
        else              asm volatile("cp.async.wait_group 0;" ::: "memory");
        __syncthreads();

        const int buf = it & 1;
        const uint32_t sA = sbase + buf * GSTAGEB;

#pragma unroll
        for (int ks = 0; ks < BKK; ks += 16) {
            uint32_t ah[4][4], al[4][4];
            const uint32_t aoff = (uint32_t)(lane & 15) * ROWB + (uint32_t)ks * 2
                                + (uint32_t)(lane >> 4) * 16;
#pragma unroll
            for (int mf = 0; mf < 4; mf++) {
                uint32_t ad = (uint32_t)(m0w + mf * 16) * ROWB + aoff;
                ldm_x4(ah[mf], sA + ad);
                ldm_x4(al[mf], sA + GA_B + ad);
            }
            const uint32_t boff = (uint32_t)(((lane >> 4) << 3) + (lane & 7)) * ROWB
                                + (uint32_t)ks * 2 + (uint32_t)((lane >> 3) & 1) * 16;
#pragma unroll
            for (int s = 0; s < 2; s++) {
                uint32_t bh[2][2];
                const uint32_t sB = sA + 2 * GA_B + s * GW_B;
                uint32_t bd = (uint32_t)n0w * ROWB + boff;
                uint32_t rh[4];
                ldm_x4(rh, sB + bd);
                bh[0][0] = rh[0]; bh[0][1] = rh[1];
                bh[1][0] = rh[2]; bh[1][1] = rh[3];
#pragma unroll
                for (int mf = 0; mf < 4; mf++)
#pragma unroll
                    for (int nf = 0; nf < 2; nf++)
                        mma16816(acc[s][mf][nf], ah[mf], bh[nf]);
#pragma unroll
                for (int mf = 0; mf < 4; mf++)
#pragma unroll
                    for (int nf = 0; nf < 2; nf++)
                        mma16816(acc[s][mf][nf], al[mf], bh[nf]);
            }
        }
        __syncthreads();
        if (it + 2 < NIT) load_stage(it + 2, it & 1);
    }

    // fused combine epilogue (conv reconstructed from fp16 hi/lo split)
    const int rbase = m0 + m0w + (lane >> 2);          // global row
    const int cloc0 = n0 + n0w + (lane & 3) * 2;       // col within head
#pragma unroll
    for (int mf = 0; mf < 4; mf++) {
#pragma unroll
        for (int half = 0; half < 2; half++) {
            int row = rbase + mf * 16 + half * 8;
            bool reset = (seg[row] == 0);
#pragma unroll
            for (int nf = 0; nf < 2; nf++) {
                int cl = cloc0 + nf * 8;               // col within head (0..255)
                size_t go = (size_t)row * LL + (size_t)z * HD + cl;
                uint32_t chp = *(const uint32_t*)&cAh[go];
                uint32_t clp = *(const uint32_t*)&cAl[go];
                float outn[2], outa[2];
#pragma unroll
                for (int e = 0; e < 2; e++) {
                    float c1 = acc[0][mf][nf][half * 2 + e] + ib[z * HD + cl + e];
                    float c2 = acc[1][mf][nf][half * 2 + e] + ab[z * HD + cl + e];
                    float gi = 1.f / (1.f + expf(-c1));
                    float ga = 1.f / (1.f + expf(-c2));
                    float ap = a_param[z * HD + cl + e];
                    float sp = log1pf(expf(ap));
                    float la = -8.f * ga * sp;
                    float a = expf(la);
                    float mult = reset ? 1.f : sqrtf(fmaxf(1.f - expf(2.f * la), 0.f));
                    uint16_t hb = (uint16_t)((e == 0) ? (chp & 0xFFFF) : (chp >> 16));
                    uint16_t lb = (uint16_t)((e == 0) ? (clp & 0xFFFF) : (clp >> 16));
                    float cvv = __half2float(__ushort_as_half(hb))
                              + __half2float(__ushort_as_half(lb));
                    outn[e] = cvv * gi * mult;
                    outa[e] = reset ? 0.f : a;
                }
                *(float2*)&G1[go] = make_float2(outn[0], outn[1]);
                *(float2*)&G2[go] = make_float2(outa[0], outa[1]);
            }
        }
    }
}

// ---------------------------------------------------------------------------
// f32 -> fp16 convert (hi only, vectorized x4)
// ---------------------------------------------------------------------------
__device__ __forceinline__ uint32_t pk2h(__half a, __half b) {
    return (uint32_t)__half_as_ushort(a) | ((uint32_t)__half_as_ushort(b) << 16);
}
__device__ __forceinline__ void split_f4h(float4 v, uint2& H, uint2& L) {
    __half hx = __float2half_rn(v.x), hy = __float2half_rn(v.y);
    __half hz = __float2half_rn(v.z), hw = __float2half_rn(v.w);
    H.x = pk2h(hx, hy);
    H.y = pk2h(hz, hw);
    L.x = pk2h(__float2half_rn(v.x - __half2float(hx)), __float2half_rn(v.y - __half2float(hy)));
    L.y = pk2h(__float2half_rn(v.z - __half2float(hz)), __float2half_rn(v.w - __half2float(hw)));
}
__global__ void conv4_k(const float4* __restrict__ in, uint2* __restrict__ oh, long n4)
{
    long i = (long)blockIdx.x * blockDim.x + threadIdx.x;
    if (i >= n4) return;
    float4 v = in[i];
    uint2 H;
    H.x = pk2h(__float2half_rn(v.x), __float2half_rn(v.y));
    H.y = pk2h(__float2half_rn(v.z), __float2half_rn(v.w));
    oh[i] = H;
}

// ---------------------------------------------------------------------------
// Transposing convert for 3 big weights in one launch
// ---------------------------------------------------------------------------
__global__ void tsplit3_k(const float* __restrict__ s0, const float* __restrict__ s1,
                          const float* __restrict__ s2,
                          __half* __restrict__ d0, __half* __restrict__ d1,
                          __half* __restrict__ d2)
{
    __shared__ float t[32][33];
    const int z = blockIdx.z;
    const float* in = (z == 0) ? s0 : (z == 1) ? s1 : s2;
    __half* oh      = (z == 0) ? d0 : (z == 1) ? d1 : d2;
    const int K = WW, N = LL;
    int kb = blockIdx.y * 32, nb = blockIdx.x * 32;
    for (int i = threadIdx.y; i < 32; i += 8)
        t[i][threadIdx.x] = in[(size_t)(kb + i) * N + nb + threadIdx.x];
    __syncthreads();
    for (int i = threadIdx.y; i < 32; i += 8) {
        int n = nb + i, k = kb + threadIdx.x;
        oh[(size_t)n * K + k] = __float2half_rn(t[threadIdx.x][i]);
    }
}

// gate weights: z 0..15 -> (head = z&7, src = z>>3 ? agate : igate)
__global__ void tsplitg_k(const float* __restrict__ ig, const float* __restrict__ ag,
                          __half* __restrict__ d1, __half* __restrict__ d2)
{
    __shared__ float t[32][33];
    const int z = blockIdx.z;
    const int head = z & 7;
    const float* in = ((z >> 3) ? ag : ig) + (size_t)head * HD * HD;
    __half* oh      = ((z >> 3) ? d2 : d1) + (size_t)head * HD * HD;
    int kb = blockIdx.y * 32, nb = blockIdx.x * 32;
    for (int i = threadIdx.y; i < 32; i += 8)
        t[i][threadIdx.x] = in[(size_t)(kb + i) * HD + nb + threadIdx.x];
    __syncthreads();
    for (int i = threadIdx.y; i < 32; i += 8) {
        int n = nb + i, k = kb + threadIdx.x;
        oh[(size_t)n * HD + k] = __float2half_rn(t[threadIdx.x][i]);
    }
}

// ---------------------------------------------------------------------------
// Causal depthwise temporal conv (TW=4) -> fp16 hi/lo split output (gate path)
// ---------------------------------------------------------------------------
__global__ void conv_k(const float4* __restrict__ xb, const float4* __restrict__ cw,
                       const float4* __restrict__ cb,
                       uint2* __restrict__ oh, uint2* __restrict__ ol)
{
    long idx = (long)blockIdx.x * blockDim.x + threadIdx.x;
    if (idx >= (long)MTOT * L4C) return;
    int l4 = (int)(idx % L4C);
    int m = (int)(idx / L4C);
    int t = m % TT;
    float4 acc = cb[l4];
#pragma unroll
    for (int j = 0; j < TWD; j++) {
        int dt = TWD - 1 - j;
        if (t - dt >= 0) {
            float4 w = cw[j * L4C + l4];
            float4 x = xb[(long)(m - dt) * L4C + l4];
            acc.x = fmaf(w.x, x.x, acc.x);
            acc.y = fmaf(w.y, x.y, acc.y);
            acc.z = fmaf(w.z, x.z, acc.z);
            acc.w = fmaf(w.w, x.w, acc.w);
        }
    }
    uint2 H, L;
    split_f4h(acc, H, L);
    oh[idx] = H; ol[idx] = L;
}

// ---------------------------------------------------------------------------
// Chunked scan (scalar over L): h_t = a_t h_{t-1} + x_t
// Pass 3 fused with gate (h*y, y in fp16) and fp16 convert for the final GEMM.
// ---------------------------------------------------------------------------
__global__ void scan_p1(const float* __restrict__ a, const float* __restrict__ x,
                        float* __restrict__ Aagg, float* __restrict__ Hend)
{
    long idx = (long)blockIdx.x * blockDim.x + threadIdx.x;  // over B*NCH*L
    if (idx >= (long)BB * NCH * LL) return;
    int l = (int)(idx % LL);
    int r = (int)(idx / LL);
    int c = r % NCH, b = r / NCH;
    size_t base = ((size_t)b * TT + (size_t)c * SCH) * LL + l;
    float h = 0.f, ap = 1.f;
#pragma unroll 4
    for (int t = 0; t < SCH; t++) {
        float av = a[base + (size_t)t * LL];
        h = fmaf(av, h, x[base + (size_t)t * LL]);
        ap *= av;
    }
    Aagg[idx] = ap; Hend[idx] = h;
}
__global__ void scan_p2(const float* __restrict__ Aagg, const float* __restrict__ Hend,
                        float* __restrict__ Cin)
{
    int idx = blockIdx.x * blockDim.x + threadIdx.x;
    if (idx >= BB * LL) return;
    int l = idx % LL, b = idx / LL;
    float cin = 0.f;
    for (int c = 0; c < NCH; c++) {
        size_t j = ((size_t)b * NCH + c) * LL + l;
        Cin[j] = cin;
        cin = fmaf(Aagg[j], cin, Hend[j]);
    }
}
__global__ void scan_p3f(const float* __restrict__ a, const float* __restrict__ x,
                         const float* __restrict__ Cin, const __half* __restrict__ y,
                         __half* __restrict__ oh)
{
    long idx = (long)blockIdx.x * blockDim.x + threadIdx.x;
    if (idx >= (long)BB * NCH * LL) return;
    int l = (int)(idx % LL);
    int r = (int)(idx / LL);
    int c = r % NCH, b = r / NCH;
    size_t base = ((size_t)b * TT + (size_t)c * SCH) * LL + l;
    float h = Cin[idx];
#pragma unroll 4
    for (int t = 0; t < SCH; t++) {
        size_t o = base + (size_t)t * LL;
        h = fmaf(a[o], h, x[o]);
        oh[o] = __float2half_rn(h * __half2float(y[o]));
    }
}

// ---------------------------------------------------------------------------
// Launch
// ---------------------------------------------------------------------------
extern "C" void kernel_launch(void* const* d_in, const int* in_sizes, int n_in,
                              void* d_out, int out_size)
{
    const float* x       = (const float*)d_in[0];
    const int*   seg     = (const int*)  d_in[1];
    const float* w_y     = (const float*)d_in[2];
    const float* b_y     = (const float*)d_in[3];
    const float* w_x     = (const float*)d_in[4];
    const float* b_x     = (const float*)d_in[5];
    const float* w_out   = (const float*)d_in[6];
    const float* b_out   = (const float*)d_in[7];
    const float* conv_w  = (const float*)d_in[8];
    const float* conv_b  = (const float*)d_in[9];
    const float* a_param = (const float*)d_in[10];
    const float* igate_w = (const float*)d_in[11];
    const float* igate_b = (const float*)d_in[12];
    const float* agate_w = (const float*)d_in[13];
    const float* agate_b = (const float*)d_in[14];
    float* out = (float*)d_out;

    float *XB, *G1, *G2, *Aagg, *Hend, *Cin;
    __half *Yh, *Ah, *Al, *BY, *BX, *BO, *GW1, *GW2;
    cudaGetSymbolAddress((void**)&Yh, g_Yh);
    cudaGetSymbolAddress((void**)&XB, g_XB);
    cudaGetSymbolAddress((void**)&G1, g_G1);
    cudaGetSymbolAddress((void**)&G2, g_G2);
    cudaGetSymbolAddress((void**)&Ah, g_Ah);
    cudaGetSymbolAddress((void**)&Al, g_Al);
    cudaGetSymbolAddress((void**)&BY, g_BY);
    cudaGetSymbolAddress((void**)&BX, g_BX);
    cudaGetSymbolAddress((void**)&BO, g_BO);
    cudaGetSymbolAddress((void**)&GW1, g_GW1);
    cudaGetSymbolAddress((void**)&GW2, g_GW2);
    cudaGetSymbolAddress((void**)&Aagg, g_Aagg);
    cudaGetSymbolAddress((void**)&Hend, g_Hend);
    cudaGetSymbolAddress((void**)&Cin, g_Cin);

    cudaFuncSetAttribute(gemm_dual, cudaFuncAttributeMaxDynamicSharedMemorySize, GEMM_SMEM);
    cudaFuncSetAttribute(gemm_single, cudaFuncAttributeMaxDynamicSharedMemorySize, GEMM_SMEM);
    cudaFuncSetAttribute(gate_tc, cudaFuncAttributeMaxDynamicSharedMemorySize, GATE_SMEM);

    const long n4 = (long)ELEMS / 4;
    const int eb = (int)((n4 + 255) / 256);
    dim3 t3grid(WW / 32, WW / 32, 3);
    dim3 tblk(32, 8, 1);
    dim3 dualGrid(LL / 128, MTOT / 128, 2);    // (16, 64, 2)
    dim3 bigGrid(LL / 128, MTOT / 128, 1);     // (16, 64)
    dim3 gateGrid(HD / 64, MTOT / 128, HH);    // (4, 64, 8)
    dim3 ggrid(HD / 32, HD / 32, 16);

    // slot 0: convert x -> Ah (fp16, hi only)
    conv4_k<<<eb, 256>>>((const float4*)x, (uint2*)Ah, n4);
    // slot 1: all three big weight transposes in one launch
    tsplit3_k<<<t3grid, tblk>>>(w_y, w_x, w_out, BY, BX, BO);
    // slot 2: both gate weight transposes in one launch
    tsplitg_k<<<ggrid, tblk>>>(igate_w, agate_w, GW1, GW2);
    // slot 3: merged dual GEMM -> Yh (gelu, fp16) and XB (f32)
    gemm_dual<<<dualGrid, 256, GEMM_SMEM>>>(Ah, BY, BX, b_y, b_x, Yh, XB,
                                            WW, WW, WW, LL);
    // slot 4: conv -> fp16 hi/lo split into Ah/Al (gate path keeps 2-product)
    {
        long tot = (long)MTOT * L4C;
        conv_k<<<(int)((tot + 255) / 256), 256>>>((const float4*)XB, (const float4*)conv_w,
                                                  (const float4*)conv_b,
                                                  (uint2*)Ah, (uint2*)Al);
    }
    // slot 5: dual gate GEMM with fused combine (128x64 tiles, 2 CTAs/SM)
    gate_tc<<<gateGrid, 256, GATE_SMEM>>>(Ah, Al, GW1, GW2,
                                          igate_b, agate_b, a_param, seg, G1, G2);
    // slots 6-8: chunked scan ; pass 3 fused with h*y and fp16 convert into Ah
    {
        long tot = (long)BB * NCH * LL;
        int blocks = (int)((tot + 255) / 256);
        scan_p1<<<blocks, 256>>>(G2, G1, Aagg, Hend);
        scan_p2<<<(BB * LL + 255) / 256, 256>>>(Aagg, Hend, Cin);
        scan_p3f<<<blocks, 256>>>(G2, G1, Cin, Yh, Ah);
    }
    // slot 9: final GEMM -> out
    gemm_single<<<bigGrid, 256, GEMM_SMEM>>>(Ah, BO, b_out, out, LL, LL, LL, WW);
}

// round 16
// speedup vs baseline: 2.4091x; 1.0177x over previous
#include <cuda_runtime.h>
#include <cuda_bf16.h>
#include <cuda_fp16.h>
#include <math.h>
#include <stdint.h>

// Problem constants
#define BB 2
#define TT 4096
#define WW 2048
#define LL 2048
#define HH 8
#define TWD 4
#define HD 256                 // LL / HH
#define MTOT (BB * TT)         // 8192 rows
#define ELEMS ((size_t)MTOT * LL)  // 16,777,216
#define L4C (LL / 4)           // 512

#define SCH 128                // scan chunk length
#define NCH (TT / SCH)         // 32 chunks

// ---------------------------------------------------------------------------
// Scratch buffers (static device globals — no runtime allocation)
// ---------------------------------------------------------------------------
__device__ __half g_Yh[ELEMS];    // gelu(x @ w_y + b_y) in fp16 (1:1 output path)
__device__ float g_XB[ELEMS];     // x @ w_x + b_x
__device__ __half g_G1h[ELEMS];   // normed (fp16, 1:1 scan input path)
__device__ float g_G2[ELEMS];     // a_masked (f32 — recurrence-sensitive)

__device__ __half g_Ah[ELEMS];            // fp16 hi of current A operand
__device__ __half g_Al[ELEMS];            // fp16 lo residual (gate path only)
__device__ __half g_BY[(size_t)LL * WW];  // transposed w_y fp16 [N,K]
__device__ __half g_BX[(size_t)LL * WW];  // transposed w_x fp16 [N,K]
__device__ __half g_BO[(size_t)LL * WW];  // transposed w_out fp16 [N,K]
__device__ __half g_GW1[(size_t)HH * HD * HD];
__device__ __half g_GW2[(size_t)HH * HD * HD];

__device__ float g_Aagg[(size_t)BB * NCH * LL];
__device__ float g_Hend[(size_t)BB * NCH * LL];
__device__ float g_Cin [(size_t)BB * NCH * LL];

// ---------------------------------------------------------------------------
// Low-level helpers (sm_80-portable: ldmatrix / mma.sync / cp.async only)
// ---------------------------------------------------------------------------
__device__ __forceinline__ uint32_t smem_u32(const void* p) {
    uint32_t a;
    asm("{ .reg .u64 t; cvta.to.shared.u64 t, %1; cvt.u32.u64 %0, t; }" : "=r"(a) : "l"(p));
    return a;
}
__device__ __forceinline__ void cp_async16(uint32_t saddr, const void* gaddr) {
    asm volatile("cp.async.cg.shared.global [%0], [%1], 16;" :: "r"(saddr), "l"(gaddr) : "memory");
}
__device__ __forceinline__ void ldm_x4(uint32_t* r, uint32_t addr) {
    asm volatile("ldmatrix.sync.aligned.m8n8.x4.shared.b16 {%0,%1,%2,%3}, [%4];"
                 : "=r"(r[0]), "=r"(r[1]), "=r"(r[2]), "=r"(r[3]) : "r"(addr));
}
// fp16 inputs, fp32 accumulate
__device__ __forceinline__ void mma16816(float* c, const uint32_t* a, const uint32_t* b) {
    asm volatile("mma.sync.aligned.m16n8k16.row.col.f32.f16.f16.f32 "
                 "{%0,%1,%2,%3}, {%4,%5,%6,%7}, {%8,%9}, {%0,%1,%2,%3};"
                 : "+f"(c[0]), "+f"(c[1]), "+f"(c[2]), "+f"(c[3])
                 : "r"(a[0]), "r"(a[1]), "r"(a[2]), "r"(a[3]), "r"(b[0]), "r"(b[1]));
}

// ---------------------------------------------------------------------------
// Big GEMM core: C[m,n] = EPI( sum_k A[m,k]*B[n,k] + bias[n] )
// 1-product fp16 (Ah*Bh). HOUT selects f32 or fp16 output.
// Tile 128x128x64, 256 threads, 8 warps of 64x32.
// Packed 2-matrix stages -> 3-stage cp.async pipeline at 2 CTAs/SM.
// ---------------------------------------------------------------------------
#define BKK 64
#define ROWB 144                       // padded row bytes (64*2 + 16)
#define MATB (128 * ROWB)              // 18432 bytes per matrix tile
#define STAGEB (2 * MATB)              // 36864 bytes per stage (Ah, Bh packed)
#define NSTAGE 3
#define GEMM_SMEM (NSTAGE * STAGEB)    // 110592 bytes -> 2 CTAs/SM

template <bool HOUT>
__device__ __forceinline__
void gemm_core(const __half* __restrict__ Ah, const __half* __restrict__ Bh,
               const float* __restrict__ bias, void* __restrict__ Cv,
               int K, int lda, int ldb, int ldc, bool dogel)
{
    extern __shared__ char sm[];
    const uint32_t sbase = smem_u32(sm);
    const int tid  = threadIdx.x;
    const int lane = tid & 31;
    const int wid  = tid >> 5;
    const int m0 = blockIdx.y * 128;
    const int n0 = blockIdx.x * 128;

    const __half* AbH = Ah + (size_t)m0 * lda;
    const __half* BbH = Bh + (size_t)n0 * ldb;

    const int NIT = K / BKK;

    auto load_stage = [&](int it, int buf) {
        const int k0 = it * BKK;
        const __half* srcs[2] = {AbH, BbH};
#pragma unroll
        for (int mt = 0; mt < 2; mt++) {
            const int ld = (mt == 0) ? lda : ldb;
            const __half* src = srcs[mt];
#pragma unroll
            for (int i = 0; i < 4; i++) {
                int c = tid + 256 * i;           // 0..1023
                int row = c >> 3, col = c & 7;
                uint32_t sa = sbase + buf * STAGEB + mt * MATB + row * ROWB + col * 16;
                cp_async16(sa, src + (size_t)row * ld + k0 + col * 8);
            }
        }
        asm volatile("cp.async.commit_group;" ::: "memory");
    };

    const int m0w = (wid & 1) * 64;
    const int n0w = (wid >> 1) * 32;

    float acc[4][4][4];
#pragma unroll
    for (int i = 0; i < 4; i++)
#pragma unroll
        for (int j = 0; j < 4; j++)
#pragma unroll
            for (int e = 0; e < 4; e++) acc[i][j][e] = 0.f;

    load_stage(0, 0);
    if (NIT > 1) load_stage(1, 1);

    for (int it = 0; it < NIT; it++) {
        if (it + 1 < NIT) asm volatile("cp.async.wait_group 1;" ::: "memory");
        else              asm volatile("cp.async.wait_group 0;" ::: "memory");
        __syncthreads();
        // buffer (it+2)%3 was last consumed in iteration it-1; the sync above
        // guarantees it's free -> issue next load now, overlapping with MMAs
        if (it + 2 < NIT) load_stage(it + 2, (it + 2) % NSTAGE);

        const int buf = it % NSTAGE;
        const uint32_t sAh = sbase + buf * STAGEB;
        const uint32_t sBh = sAh + MATB;

#pragma unroll
        for (int ks = 0; ks < BKK; ks += 16) {
            uint32_t ah[4][4], bh[4][2];
            const uint32_t aoff = (uint32_t)(lane & 15) * ROWB + (uint32_t)ks * 2
                                + (uint32_t)(lane >> 4) * 16;
#pragma unroll
            for (int mf = 0; mf < 4; mf++) {
                uint32_t ad = (uint32_t)(m0w + mf * 16) * ROWB + aoff;
                ldm_x4(ah[mf], sAh + ad);
            }
            const uint32_t boff = (uint32_t)(((lane >> 4) << 3) + (lane & 7)) * ROWB
                                + (uint32_t)ks * 2 + (uint32_t)((lane >> 3) & 1) * 16;
#pragma unroll
            for (int nf2 = 0; nf2 < 2; nf2++) {
                uint32_t bd = (uint32_t)(n0w + nf2 * 16) * ROWB + boff;
                uint32_t rh[4];
                ldm_x4(rh, sBh + bd);
                bh[nf2 * 2][0] = rh[0]; bh[nf2 * 2][1] = rh[1];
                bh[nf2 * 2 + 1][0] = rh[2]; bh[nf2 * 2 + 1][1] = rh[3];
            }
#pragma unroll
            for (int mf = 0; mf < 4; mf++)
#pragma unroll
                for (int nf = 0; nf < 4; nf++)
                    mma16816(acc[mf][nf], ah[mf], bh[nf]);
        }
    }

    // epilogue: bias + optional gelu
    const int rbase = m0 + m0w + (lane >> 2);
    const int cbase = n0 + n0w + (lane & 3) * 2;
    float* Cf = (float*)Cv;
    __half* Ch = (__half*)Cv;
#pragma unroll
    for (int mf = 0; mf < 4; mf++) {
#pragma unroll
        for (int nf = 0; nf < 4; nf++) {
            int col = cbase + nf * 8;
            float b0 = bias[col], b1 = bias[col + 1];
            float v[4] = {acc[mf][nf][0] + b0, acc[mf][nf][1] + b1,
                          acc[mf][nf][2] + b0, acc[mf][nf][3] + b1};
            if (dogel) {
#pragma unroll
                for (int e = 0; e < 4; e++) {
                    float x = v[e];
                    float t = tanhf(0.7978845608028654f * (x + 0.044715f * x * x * x));
                    v[e] = 0.5f * x * (1.f + t);
                }
            }
            int r0 = rbase + mf * 16;
            if (HOUT) {
                *(__half2*)&Ch[(size_t)r0 * ldc + col] =
                    __floats2half2_rn(v[0], v[1]);
                *(__half2*)&Ch[(size_t)(r0 + 8) * ldc + col] =
                    __floats2half2_rn(v[2], v[3]);
            } else {
                *(float2*)&Cf[(size_t)r0 * ldc + col]       = make_float2(v[0], v[1]);
                *(float2*)&Cf[(size_t)(r0 + 8) * ldc + col] = make_float2(v[2], v[3]);
            }
        }
    }
}

// dual-output launch: z=0 -> gelu(x@w_y+b_y) into Yh (fp16) ; z=1 -> XB (f32)
__global__ __launch_bounds__(256, 2)
void gemm_dual(const __half* __restrict__ Ah,
               const __half* __restrict__ B0, const __half* __restrict__ B1,
               const float* __restrict__ bias0, const float* __restrict__ bias1,
               __half* __restrict__ C0, float* __restrict__ C1,
               int K, int lda, int ldb, int ldc)
{
    if (blockIdx.z == 0)
        gemm_core<true >(Ah, B0, bias0, C0, K, lda, ldb, ldc, true);
    else
        gemm_core<false>(Ah, B1, bias1, C1, K, lda, ldb, ldc, false);
}

// single-output launch (final GEMM, f32 out)
__global__ __launch_bounds__(256, 2)
void gemm_single(const __half* __restrict__ Ah, const __half* __restrict__ Bh,
                 const float* __restrict__ bias, float* __restrict__ C,
                 int K, int lda, int ldb, int ldc)
{
    gemm_core<false>(Ah, Bh, bias, C, K, lda, ldb, ldc, false);
}

// ---------------------------------------------------------------------------
// Dual gate GEMM + fused combine epilogue. 2xfp16 A-split (sensitive path).
// Tile 128x64 per CTA, 2 stages of 55296 B -> 2 CTAs/SM.
// G1 (normed) written fp16; G2 (a_masked) stays f32.
// ---------------------------------------------------------------------------
#define GA_B (128 * ROWB)              // 18432 (A tile)
#define GW_B (64 * ROWB)               // 9216  (W tile)
#define GSTAGEB (2 * GA_B + 2 * GW_B)  // 55296
#define GATE_SMEM (2 * GSTAGEB)        // 110592

__global__ __launch_bounds__(256, 2)
void gate_tc(const __half* __restrict__ cAh, const __half* __restrict__ cAl,
             const __half* __restrict__ W1, const __half* __restrict__ W2,
             const float* __restrict__ ib, const float* __restrict__ ab,
             const float* __restrict__ a_param, const int* __restrict__ seg,
             __half* __restrict__ G1, float* __restrict__ G2)
{
    extern __shared__ char sm[];
    const uint32_t sbase = smem_u32(sm);
    const int tid  = threadIdx.x;
    const int lane = tid & 31;
    const int wid  = tid >> 5;
    const int z  = blockIdx.z;           // head
    const int m0 = blockIdx.y * 128;
    const int n0 = blockIdx.x * 64;      // 64-col slab within head

    const __half* AbH = cAh + (size_t)m0 * LL + z * HD;
    const __half* AbL = cAl + (size_t)m0 * LL + z * HD;
    const __half* B1  = W1 + (size_t)z * HD * HD + (size_t)n0 * HD;
    const __half* B2  = W2 + (size_t)z * HD * HD + (size_t)n0 * HD;

    const int NIT = HD / BKK;   // 4

    auto load_stage = [&](int it, int buf) {
        const int k0 = it * BKK;
        const uint32_t sb = sbase + buf * GSTAGEB;
        const __half* asrc[2] = {AbH, AbL};
#pragma unroll
        for (int mt = 0; mt < 2; mt++) {
#pragma unroll
            for (int i = 0; i < 4; i++) {
                int c = tid + 256 * i;            // 0..1023
                int row = c >> 3, col = c & 7;
                uint32_t sa = sb + mt * GA_B + row * ROWB + col * 16;
                cp_async16(sa, asrc[mt] + (size_t)row * LL + k0 + col * 8);
            }
        }
        const __half* wsrc[2] = {B1, B2};
#pragma unroll
        for (int mt = 0; mt < 2; mt++) {
#pragma unroll
            for (int i = 0; i < 2; i++) {
                int c = tid + 256 * i;            // 0..511
                int row = c >> 3, col = c & 7;
                uint32_t sa = sb + 2 * GA_B + mt * GW_B + row * ROWB + col * 16;
                cp_async16(sa, wsrc[mt] + (size_t)row * HD + k0 + col * 8);
            }
        }
        asm volatile("cp.async.commit_group;" ::: "memory");
    };

    const int m0w = (wid & 1) * 64;
    const int n0w = (wid >> 1) * 16;

    float acc[2][4][2][4];
#pragma unroll
    for (int s = 0; s < 2; s++)
#pragma unroll
        for (int i = 0; i < 4; i++)
#pragma unroll
            for (int j = 0; j < 2; j++)
#pragma unroll
                for (int e = 0; e < 4; e++) acc[s][i][j][e] = 0.f;

    load_stage(0, 0);
    load_stage(1, 1);

    for (int it = 0; it < NIT; it++) {
        if (it + 1 < NIT) asm volatile("cp.async.wait_group 1;" ::: "memory");
        else              asm volatile("cp.async.wait_group 0;" ::: "memory");
        __syncthreads();

        const int buf = it & 1;
        const uint32_t sA = sbase + buf * GSTAGEB;

#pragma unroll
        for (int ks = 0; ks < BKK; ks += 16) {
            uint32_t ah[4][4], al[4][4];
            const uint32_t aoff = (uint32_t)(lane & 15) * ROWB + (uint32_t)ks * 2
                                + (uint32_t)(lane >> 4) * 16;
#pragma unroll
            for (int mf = 0; mf < 4; mf++) {
                uint32_t ad = (uint32_t)(m0w + mf * 16) * ROWB + aoff;
                ldm_x4(ah[mf], sA + ad);
                ldm_x4(al[mf], sA + GA_B + ad);
            }
            const uint32_t boff = (uint32_t)(((lane >> 4) << 3) + (lane & 7)) * ROWB
                                + (uint32_t)ks * 2 + (uint32_t)((lane >> 3) & 1) * 16;
#pragma unroll
            for (int s = 0; s < 2; s++) {
                uint32_t bh[2][2];
                const uint32_t sB = sA + 2 * GA_B + s * GW_B;
                uint32_t bd = (uint32_t)n0w * ROWB + boff;
                uint32_t rh[4];
                ldm_x4(rh, sB + bd);
                bh[0][0] = rh[0]; bh[0][1] = rh[1];
                bh[1][0] = rh[2]; bh[1][1] = rh[3];
#pragma unroll
                for (int mf = 0; mf < 4; mf++)
#pragma unroll
                    for (int nf = 0; nf < 2; nf++)
                        mma16816(acc[s][mf][nf], ah[mf], bh[nf]);
#pragma unroll
                for (int mf = 0; mf < 4; mf++)
#pragma unroll
                    for (int nf = 0; nf < 2; nf++)
                        mma16816(acc[s][mf][nf], al[mf], bh[nf]);
            }
        }
        __syncthreads();
        if (it + 2 < NIT) load_stage(it + 2, it & 1);
    }

    // fused combine epilogue (conv reconstructed from fp16 hi/lo split)
    const int rbase = m0 + m0w + (lane >> 2);          // global row
    const int cloc0 = n0 + n0w + (lane & 3) * 2;       // col within head
#pragma unroll
    for (int mf = 0; mf < 4; mf++) {
#pragma unroll
        for (int half = 0; half < 2; half++) {
            int row = rbase + mf * 16 + half * 8;
            bool reset = (seg[row] == 0);
#pragma unroll
            for (int nf = 0; nf < 2; nf++) {
                int cl = cloc0 + nf * 8;               // col within head (0..255)
                size_t go = (size_t)row * LL + (size_t)z * HD + cl;
                uint32_t chp = *(const uint32_t*)&cAh[go];
                uint32_t clp = *(const uint32_t*)&cAl[go];
                float outn[2], outa[2];
#pragma unroll
                for (int e = 0; e < 2; e++) {
                    float c1 = acc[0][mf][nf][half * 2 + e] + ib[z * HD + cl + e];
                    float c2 = acc[1][mf][nf][half * 2 + e] + ab[z * HD + cl + e];
                    float gi = 1.f / (1.f + expf(-c1));
                    float ga = 1.f / (1.f + expf(-c2));
                    float ap = a_param[z * HD + cl + e];
                    float sp = log1pf(expf(ap));
                    float la = -8.f * ga * sp;
                    float a = expf(la);
                    float mult = reset ? 1.f : sqrtf(fmaxf(1.f - expf(2.f * la), 0.f));
                    uint16_t hb = (uint16_t)((e == 0) ? (chp & 0xFFFF) : (chp >> 16));
                    uint16_t lb = (uint16_t)((e == 0) ? (clp & 0xFFFF) : (clp >> 16));
                    float cvv = __half2float(__ushort_as_half(hb))
                              + __half2float(__ushort_as_half(lb));
                    outn[e] = cvv * gi * mult;
                    outa[e] = reset ? 0.f : a;
                }
                *(__half2*)&G1[go] = __floats2half2_rn(outn[0], outn[1]);
                *(float2*)&G2[go]  = make_float2(outa[0], outa[1]);
            }
        }
    }
}

// ---------------------------------------------------------------------------
// f32 -> fp16 convert (hi only, vectorized x4)
// ---------------------------------------------------------------------------
__device__ __forceinline__ uint32_t pk2h(__half a, __half b) {
    return (uint32_t)__half_as_ushort(a) | ((uint32_t)__half_as_ushort(b) << 16);
}
__device__ __forceinline__ void split_f4h(float4 v, uint2& H, uint2& L) {
    __half hx = __float2half_rn(v.x), hy = __float2half_rn(v.y);
    __half hz = __float2half_rn(v.z), hw = __float2half_rn(v.w);
    H.x = pk2h(hx, hy);
    H.y = pk2h(hz, hw);
    L.x = pk2h(__float2half_rn(v.x - __half2float(hx)), __float2half_rn(v.y - __half2float(hy)));
    L.y = pk2h(__float2half_rn(v.z - __half2float(hz)), __float2half_rn(v.w - __half2float(hw)));
}
__global__ void conv4_k(const float4* __restrict__ in, uint2* __restrict__ oh, long n4)
{
    long i = (long)blockIdx.x * blockDim.x + threadIdx.x;
    if (i >= n4) return;
    float4 v = in[i];
    uint2 H;
    H.x = pk2h(__float2half_rn(v.x), __float2half_rn(v.y));
    H.y = pk2h(__float2half_rn(v.z), __float2half_rn(v.w));
    oh[i] = H;
}

// ---------------------------------------------------------------------------
// Transposing convert for 3 big weights in one launch
// ---------------------------------------------------------------------------
__global__ void tsplit3_k(const float* __restrict__ s0, const float* __restrict__ s1,
                          const float* __restrict__ s2,
                          __half* __restrict__ d0, __half* __restrict__ d1,
                          __half* __restrict__ d2)
{
    __shared__ float t[32][33];
    const int z = blockIdx.z;
    const float* in = (z == 0) ? s0 : (z == 1) ? s1 : s2;
    __half* oh      = (z == 0) ? d0 : (z == 1) ? d1 : d2;
    const int K = WW, N = LL;
    int kb = blockIdx.y * 32, nb = blockIdx.x * 32;
    for (int i = threadIdx.y; i < 32; i += 8)
        t[i][threadIdx.x] = in[(size_t)(kb + i) * N + nb + threadIdx.x];
    __syncthreads();
    for (int i = threadIdx.y; i < 32; i += 8) {
        int n = nb + i, k = kb + threadIdx.x;
        oh[(size_t)n * K + k] = __float2half_rn(t[threadIdx.x][i]);
    }
}

// gate weights: z 0..15 -> (head = z&7, src = z>>3 ? agate : igate)
__global__ void tsplitg_k(const float* __restrict__ ig, const float* __restrict__ ag,
                          __half* __restrict__ d1, __half* __restrict__ d2)
{
    __shared__ float t[32][33];
    const int z = blockIdx.z;
    const int head = z & 7;
    const float* in = ((z >> 3) ? ag : ig) + (size_t)head * HD * HD;
    __half* oh      = ((z >> 3) ? d2 : d1) + (size_t)head * HD * HD;
    int kb = blockIdx.y * 32, nb = blockIdx.x * 32;
    for (int i = threadIdx.y; i < 32; i += 8)
        t[i][threadIdx.x] = in[(size_t)(kb + i) * HD + nb + threadIdx.x];
    __syncthreads();
    for (int i = threadIdx.y; i < 32; i += 8) {
        int n = nb + i, k = kb + threadIdx.x;
        oh[(size_t)n * HD + k] = __float2half_rn(t[threadIdx.x][i]);
    }
}

// ---------------------------------------------------------------------------
// Causal depthwise temporal conv (TW=4) -> fp16 hi/lo split output (gate path)
// ---------------------------------------------------------------------------
__global__ void conv_k(const float4* __restrict__ xb, const float4* __restrict__ cw,
                       const float4* __restrict__ cb,
                       uint2* __restrict__ oh, uint2* __restrict__ ol)
{
    long idx = (long)blockIdx.x * blockDim.x + threadIdx.x;
    if (idx >= (long)MTOT * L4C) return;
    int l4 = (int)(idx % L4C);
    int m = (int)(idx / L4C);
    int t = m % TT;
    float4 acc = cb[l4];
#pragma unroll
    for (int j = 0; j < TWD; j++) {
        int dt = TWD - 1 - j;
        if (t - dt >= 0) {
            float4 w = cw[j * L4C + l4];
            float4 x = xb[(long)(m - dt) * L4C + l4];
            acc.x = fmaf(w.x, x.x, acc.x);
            acc.y = fmaf(w.y, x.y, acc.y);
            acc.z = fmaf(w.z, x.z, acc.z);
            acc.w = fmaf(w.w, x.w, acc.w);
        }
    }
    uint2 H, L;
    split_f4h(acc, H, L);
    oh[idx] = H; ol[idx] = L;
}

// ---------------------------------------------------------------------------
// Chunked scan (scalar over L): h_t = a_t h_{t-1} + x_t
// x (normed) read as fp16; a (a_masked) f32.
// Pass 3 fused with gate (h*y, fp16) and fp16 convert for the final GEMM.
// ---------------------------------------------------------------------------
__global__ void scan_p1(const float* __restrict__ a, const __half* __restrict__ x,
                        float* __restrict__ Aagg, float* __restrict__ Hend)
{
    long idx = (long)blockIdx.x * blockDim.x + threadIdx.x;  // over B*NCH*L
    if (idx >= (long)BB * NCH * LL) return;
    int l = (int)(idx % LL);
    int r = (int)(idx / LL);
    int c = r % NCH, b = r / NCH;
    size_t base = ((size_t)b * TT + (size_t)c * SCH) * LL + l;
    float h = 0.f, ap = 1.f;
#pragma unroll 4
    for (int t = 0; t < SCH; t++) {
        float av = a[base + (size_t)t * LL];
        h = fmaf(av, h, __half2float(x[base + (size_t)t * LL]));
        ap *= av;
    }
    Aagg[idx] = ap; Hend[idx] = h;
}
__global__ void scan_p2(const float* __restrict__ Aagg, const float* __restrict__ Hend,
                        float* __restrict__ Cin)
{
    int idx = blockIdx.x * blockDim.x + threadIdx.x;
    if (idx >= BB * LL) return;
    int l = idx % LL, b = idx / LL;
    float cin = 0.f;
    for (int c = 0; c < NCH; c++) {
        size_t j = ((size_t)b * NCH + c) * LL + l;
        Cin[j] = cin;
        cin = fmaf(Aagg[j], cin, Hend[j]);
    }
}
__global__ void scan_p3f(const float* __restrict__ a, const __half* __restrict__ x,
                         const float* __restrict__ Cin, const __half* __restrict__ y,
                         __half* __restrict__ oh)
{
    long idx = (long)blockIdx.x * blockDim.x + threadIdx.x;
    if (idx >= (long)BB * NCH * LL) return;
    int l = (int)(idx % LL);
    int r = (int)(idx / LL);
    int c = r % NCH, b = r / NCH;
    size_t base = ((size_t)b * TT + (size_t)c * SCH) * LL + l;
    float h = Cin[idx];
#pragma unroll 4
    for (int t = 0; t < SCH; t++) {
        size_t o = base + (size_t)t * LL;
        h = fmaf(a[o], h, __half2float(x[o]));
        oh[o] = __float2half_rn(h * __half2float(y[o]));
    }
}

// ---------------------------------------------------------------------------
// Launch
// ---------------------------------------------------------------------------
extern "C" void kernel_launch(void* const* d_in, const int* in_sizes, int n_in,
                              void* d_out, int out_size)
{
    const float* x       = (const float*)d_in[0];
    const int*   seg     = (const int*)  d_in[1];
    const float* w_y     = (const float*)d_in[2];
    const float* b_y     = (const float*)d_in[3];
    const float* w_x     = (const float*)d_in[4];
    const float* b_x     = (const float*)d_in[5];
    const float* w_out   = (const float*)d_in[6];
    const float* b_out   = (const float*)d_in[7];
    const float* conv_w  = (const float*)d_in[8];
    const float* conv_b  = (const float*)d_in[9];
    const float* a_param = (const float*)d_in[10];
    const float* igate_w = (const float*)d_in[11];
    const float* igate_b = (const float*)d_in[12];
    const float* agate_w = (const float*)d_in[13];
    const float* agate_b = (const float*)d_in[14];
    float* out = (float*)d_out;

    float *XB, *G2, *Aagg, *Hend, *Cin;
    __half *Yh, *G1h, *Ah, *Al, *BY, *BX, *BO, *GW1, *GW2;
    cudaGetSymbolAddress((void**)&Yh, g_Yh);
    cudaGetSymbolAddress((void**)&XB, g_XB);
    cudaGetSymbolAddress((void**)&G1h, g_G1h);
    cudaGetSymbolAddress((void**)&G2, g_G2);
    cudaGetSymbolAddress((void**)&Ah, g_Ah);
    cudaGetSymbolAddress((void**)&Al, g_Al);
    cudaGetSymbolAddress((void**)&BY, g_BY);
    cudaGetSymbolAddress((void**)&BX, g_BX);
    cudaGetSymbolAddress((void**)&BO, g_BO);
    cudaGetSymbolAddress((void**)&GW1, g_GW1);
    cudaGetSymbolAddress((void**)&GW2, g_GW2);
    cudaGetSymbolAddress((void**)&Aagg, g_Aagg);
    cudaGetSymbolAddress((void**)&Hend, g_Hend);
    cudaGetSymbolAddress((void**)&Cin, g_Cin);

    cudaFuncSetAttribute(gemm_dual, cudaFuncAttributeMaxDynamicSharedMemorySize, GEMM_SMEM);
    cudaFuncSetAttribute(gemm_single, cudaFuncAttributeMaxDynamicSharedMemorySize, GEMM_SMEM);
    cudaFuncSetAttribute(gate_tc, cudaFuncAttributeMaxDynamicSharedMemorySize, GATE_SMEM);

    const long n4 = (long)ELEMS / 4;
    const int eb = (int)((n4 + 255) / 256);
    dim3 t3grid(WW / 32, WW / 32, 3);
    dim3 tblk(32, 8, 1);
    dim3 dualGrid(LL / 128, MTOT / 128, 2);    // (16, 64, 2)
    dim3 bigGrid(LL / 128, MTOT / 128, 1);     // (16, 64)
    dim3 gateGrid(HD / 64, MTOT / 128, HH);    // (4, 64, 8)
    dim3 ggrid(HD / 32, HD / 32, 16);

    // slot 0: convert x -> Ah (fp16, hi only)
    conv4_k<<<eb, 256>>>((const float4*)x, (uint2*)Ah, n4);
    // slot 1: all three big weight transposes in one launch
    tsplit3_k<<<t3grid, tblk>>>(w_y, w_x, w_out, BY, BX, BO);
    // slot 2: both gate weight transposes in one launch
    tsplitg_k<<<ggrid, tblk>>>(igate_w, agate_w, GW1, GW2);
    // slot 3: merged dual GEMM -> Yh (gelu, fp16) and XB (f32)
    gemm_dual<<<dualGrid, 256, GEMM_SMEM>>>(Ah, BY, BX, b_y, b_x, Yh, XB,
                                            WW, WW, WW, LL);
    // slot 4: conv -> fp16 hi/lo split into Ah/Al (gate path keeps 2-product)
    {
        long tot = (long)MTOT * L4C;
        conv_k<<<(int)((tot + 255) / 256), 256>>>((const float4*)XB, (const float4*)conv_w,
                                                  (const float4*)conv_b,
                                                  (uint2*)Ah, (uint2*)Al);
    }
    // slot 5: dual gate GEMM with fused combine (128x64 tiles, 2 CTAs/SM)
    gate_tc<<<gateGrid, 256, GATE_SMEM>>>(Ah, Al, GW1, GW2,
                                          igate_b, agate_b, a_param, seg, G1h, G2);
    // slots 6-8: chunked scan ; pass 3 fused with h*y and fp16 convert into Ah
    {
        long tot = (long)BB * NCH * LL;
        int blocks = (int)((tot + 255) / 256);
        scan_p1<<<blocks, 256>>>(G2, G1h, Aagg, Hend);
        scan_p2<<<(BB * LL + 255) / 256, 256>>>(Aagg, Hend, Cin);
        scan_p3f<<<blocks, 256>>>(G2, G1h, Cin, Yh, Ah);
    }
    // slot 9: final GEMM -> out
    gemm_single<<<bigGrid, 256, GEMM_SMEM>>>(Ah, BO, b_out, out, LL, LL, LL, WW);
}

// round 17
// speedup vs baseline: 2.5228x; 1.0472x over previous
#include <cuda_runtime.h>
#include <cuda_bf16.h>
#include <cuda_fp16.h>
#include <math.h>
#include <stdint.h>

// Problem constants
#define BB 2
#define TT 4096
#define WW 2048
#define LL 2048
#define HH 8
#define TWD 4
#define HD 256                 // LL / HH
#define MTOT (BB * TT)         // 8192 rows
#define ELEMS ((size_t)MTOT * LL)  // 16,777,216
#define L4C (LL / 4)           // 512

#define SCH 128                // scan chunk length
#define NCH (TT / SCH)         // 32 chunks

// ---------------------------------------------------------------------------
// Scratch buffers (static device globals — no runtime allocation)
// ---------------------------------------------------------------------------
__device__ __half g_Yh[ELEMS];    // gelu(x @ w_y + b_y) in fp16 (1:1 output path)
__device__ float g_XB[ELEMS];     // x @ w_x + b_x
__device__ __half g_G1h[ELEMS];   // normed (fp16, 1:1 scan input path)
__device__ float g_G2[ELEMS];     // a_masked (f32 — recurrence-sensitive)

__device__ __half g_Ah[ELEMS];            // fp16 of current A operand
__device__ __half g_BY[(size_t)LL * WW];  // transposed w_y fp16 [N,K]
__device__ __half g_BX[(size_t)LL * WW];  // transposed w_x fp16 [N,K]
__device__ __half g_BO[(size_t)LL * WW];  // transposed w_out fp16 [N,K]
__device__ __half g_GW1[(size_t)HH * HD * HD];
__device__ __half g_GW2[(size_t)HH * HD * HD];

__device__ float g_Aagg[(size_t)BB * NCH * LL];
__device__ float g_Hend[(size_t)BB * NCH * LL];
__device__ float g_Cin [(size_t)BB * NCH * LL];

// ---------------------------------------------------------------------------
// Low-level helpers (sm_80-portable: ldmatrix / mma.sync / cp.async only)
// ---------------------------------------------------------------------------
__device__ __forceinline__ uint32_t smem_u32(const void* p) {
    uint32_t a;
    asm("{ .reg .u64 t; cvta.to.shared.u64 t, %1; cvt.u32.u64 %0, t; }" : "=r"(a) : "l"(p));
    return a;
}
__device__ __forceinline__ void cp_async16(uint32_t saddr, const void* gaddr) {
    asm volatile("cp.async.cg.shared.global [%0], [%1], 16;" :: "r"(saddr), "l"(gaddr) : "memory");
}
__device__ __forceinline__ void ldm_x4(uint32_t* r, uint32_t addr) {
    asm volatile("ldmatrix.sync.aligned.m8n8.x4.shared.b16 {%0,%1,%2,%3}, [%4];"
                 : "=r"(r[0]), "=r"(r[1]), "=r"(r[2]), "=r"(r[3]) : "r"(addr));
}
// fp16 inputs, fp32 accumulate
__device__ __forceinline__ void mma16816(float* c, const uint32_t* a, const uint32_t* b) {
    asm volatile("mma.sync.aligned.m16n8k16.row.col.f32.f16.f16.f32 "
                 "{%0,%1,%2,%3}, {%4,%5,%6,%7}, {%8,%9}, {%0,%1,%2,%3};"
                 : "+f"(c[0]), "+f"(c[1]), "+f"(c[2]), "+f"(c[3])
                 : "r"(a[0]), "r"(a[1]), "r"(a[2]), "r"(a[3]), "r"(b[0]), "r"(b[1]));
}

// ---------------------------------------------------------------------------
// Big GEMM core: C[m,n] = EPI( sum_k A[m,k]*B[n,k] + bias[n] )
// 1-product fp16. HOUT selects f32 or fp16 output.
// Tile 128x128x64, 256 threads, 8 warps of 64x32.
// Packed 2-matrix stages, 3-stage cp.async pipeline, 2 CTAs/SM.
// ---------------------------------------------------------------------------
#define BKK 64
#define ROWB 144                       // padded row bytes (64*2 + 16)
#define MATB (128 * ROWB)              // 18432 bytes per matrix tile
#define STAGEB (2 * MATB)              // 36864 bytes per stage (Ah, Bh packed)
#define NSTAGE 3
#define GEMM_SMEM (NSTAGE * STAGEB)    // 110592 bytes -> 2 CTAs/SM

template <bool HOUT>
__device__ __forceinline__
void gemm_core(const __half* __restrict__ Ah, const __half* __restrict__ Bh,
               const float* __restrict__ bias, void* __restrict__ Cv,
               int K, int lda, int ldb, int ldc, bool dogel)
{
    extern __shared__ char sm[];
    const uint32_t sbase = smem_u32(sm);
    const int tid  = threadIdx.x;
    const int lane = tid & 31;
    const int wid  = tid >> 5;
    const int m0 = blockIdx.y * 128;
    const int n0 = blockIdx.x * 128;

    const __half* AbH = Ah + (size_t)m0 * lda;
    const __half* BbH = Bh + (size_t)n0 * ldb;

    const int NIT = K / BKK;

    auto load_stage = [&](int it, int buf) {
        const int k0 = it * BKK;
        const __half* srcs[2] = {AbH, BbH};
#pragma unroll
        for (int mt = 0; mt < 2; mt++) {
            const int ld = (mt == 0) ? lda : ldb;
            const __half* src = srcs[mt];
#pragma unroll
            for (int i = 0; i < 4; i++) {
                int c = tid + 256 * i;           // 0..1023
                int row = c >> 3, col = c & 7;
                uint32_t sa = sbase + buf * STAGEB + mt * MATB + row * ROWB + col * 16;
                cp_async16(sa, src + (size_t)row * ld + k0 + col * 8);
            }
        }
        asm volatile("cp.async.commit_group;" ::: "memory");
    };

    const int m0w = (wid & 1) * 64;
    const int n0w = (wid >> 1) * 32;

    float acc[4][4][4];
#pragma unroll
    for (int i = 0; i < 4; i++)
#pragma unroll
        for (int j = 0; j < 4; j++)
#pragma unroll
            for (int e = 0; e < 4; e++) acc[i][j][e] = 0.f;

    load_stage(0, 0);
    if (NIT > 1) load_stage(1, 1);

    for (int it = 0; it < NIT; it++) {
        if (it + 1 < NIT) asm volatile("cp.async.wait_group 1;" ::: "memory");
        else              asm volatile("cp.async.wait_group 0;" ::: "memory");
        __syncthreads();
        if (it + 2 < NIT) load_stage(it + 2, (it + 2) % NSTAGE);

        const int buf = it % NSTAGE;
        const uint32_t sAh = sbase + buf * STAGEB;
        const uint32_t sBh = sAh + MATB;

#pragma unroll
        for (int ks = 0; ks < BKK; ks += 16) {
            uint32_t ah[4][4], bh[4][2];
            const uint32_t aoff = (uint32_t)(lane & 15) * ROWB + (uint32_t)ks * 2
                                + (uint32_t)(lane >> 4) * 16;
#pragma unroll
            for (int mf = 0; mf < 4; mf++) {
                uint32_t ad = (uint32_t)(m0w + mf * 16) * ROWB + aoff;
                ldm_x4(ah[mf], sAh + ad);
            }
            const uint32_t boff = (uint32_t)(((lane >> 4) << 3) + (lane & 7)) * ROWB
                                + (uint32_t)ks * 2 + (uint32_t)((lane >> 3) & 1) * 16;
#pragma unroll
            for (int nf2 = 0; nf2 < 2; nf2++) {
                uint32_t bd = (uint32_t)(n0w + nf2 * 16) * ROWB + boff;
                uint32_t rh[4];
                ldm_x4(rh, sBh + bd);
                bh[nf2 * 2][0] = rh[0]; bh[nf2 * 2][1] = rh[1];
                bh[nf2 * 2 + 1][0] = rh[2]; bh[nf2 * 2 + 1][1] = rh[3];
            }
#pragma unroll
            for (int mf = 0; mf < 4; mf++)
#pragma unroll
                for (int nf = 0; nf < 4; nf++)
                    mma16816(acc[mf][nf], ah[mf], bh[nf]);
        }
    }

    // epilogue: bias + optional gelu
    const int rbase = m0 + m0w + (lane >> 2);
    const int cbase = n0 + n0w + (lane & 3) * 2;
    float* Cf = (float*)Cv;
    __half* Ch = (__half*)Cv;
#pragma unroll
    for (int mf = 0; mf < 4; mf++) {
#pragma unroll
        for (int nf = 0; nf < 4; nf++) {
            int col = cbase + nf * 8;
            float b0 = bias[col], b1 = bias[col + 1];
            float v[4] = {acc[mf][nf][0] + b0, acc[mf][nf][1] + b1,
                          acc[mf][nf][2] + b0, acc[mf][nf][3] + b1};
            if (dogel) {
#pragma unroll
                for (int e = 0; e < 4; e++) {
                    float x = v[e];
                    float t = tanhf(0.7978845608028654f * (x + 0.044715f * x * x * x));
                    v[e] = 0.5f * x * (1.f + t);
                }
            }
            int r0 = rbase + mf * 16;
            if (HOUT) {
                *(__half2*)&Ch[(size_t)r0 * ldc + col] =
                    __floats2half2_rn(v[0], v[1]);
                *(__half2*)&Ch[(size_t)(r0 + 8) * ldc + col] =
                    __floats2half2_rn(v[2], v[3]);
            } else {
                *(float2*)&Cf[(size_t)r0 * ldc + col]       = make_float2(v[0], v[1]);
                *(float2*)&Cf[(size_t)(r0 + 8) * ldc + col] = make_float2(v[2], v[3]);
            }
        }
    }
}

// dual-output launch: z=0 -> gelu(x@w_y+b_y) into Yh (fp16) ; z=1 -> XB (f32)
__global__ __launch_bounds__(256, 2)
void gemm_dual(const __half* __restrict__ Ah,
               const __half* __restrict__ B0, const __half* __restrict__ B1,
               const float* __restrict__ bias0, const float* __restrict__ bias1,
               __half* __restrict__ C0, float* __restrict__ C1,
               int K, int lda, int ldb, int ldc)
{
    if (blockIdx.z == 0)
        gemm_core<true >(Ah, B0, bias0, C0, K, lda, ldb, ldc, true);
    else
        gemm_core<false>(Ah, B1, bias1, C1, K, lda, ldb, ldc, false);
}

// single-output launch (final GEMM, f32 out)
__global__ __launch_bounds__(256, 2)
void gemm_single(const __half* __restrict__ Ah, const __half* __restrict__ Bh,
                 const float* __restrict__ bias, float* __restrict__ C,
                 int K, int lda, int ldb, int ldc)
{
    gemm_core<false>(Ah, Bh, bias, C, K, lda, ldb, ldc, false);
}

// ---------------------------------------------------------------------------
// Dual gate GEMM + fused combine epilogue. 1-product fp16 A.
// Tile 128x64 per CTA, stage = A (128 rows) + W1,W2 (64 rows) = 36864 B,
// 2 stages = 73728 B -> 2 CTAs/SM.
// G1 (normed) written fp16; G2 (a_masked) stays f32.
// ---------------------------------------------------------------------------
#define GA_B (128 * ROWB)              // 18432 (A tile)
#define GW_B (64 * ROWB)               // 9216  (W tile)
#define GSTAGEB (GA_B + 2 * GW_B)      // 36864
#define GATE_SMEM (2 * GSTAGEB)        // 73728

__global__ __launch_bounds__(256, 2)
void gate_tc(const __half* __restrict__ cAh,
             const __half* __restrict__ W1, const __half* __restrict__ W2,
             const float* __restrict__ ib, const float* __restrict__ ab,
             const float* __restrict__ a_param, const int* __restrict__ seg,
             __half* __restrict__ G1, float* __restrict__ G2)
{
    extern __shared__ char sm[];
    const uint32_t sbase = smem_u32(sm);
    const int tid  = threadIdx.x;
    const int lane = tid & 31;
    const int wid  = tid >> 5;
    const int z  = blockIdx.z;           // head
    const int m0 = blockIdx.y * 128;
    const int n0 = blockIdx.x * 64;      // 64-col slab within head

    const __half* AbH = cAh + (size_t)m0 * LL + z * HD;
    const __half* B1  = W1 + (size_t)z * HD * HD + (size_t)n0 * HD;
    const __half* B2  = W2 + (size_t)z * HD * HD + (size_t)n0 * HD;

    const int NIT = HD / BKK;   // 4

    auto load_stage = [&](int it, int buf) {
        const int k0 = it * BKK;
        const uint32_t sb = sbase + buf * GSTAGEB;
        // A tile: 128 rows
#pragma unroll
        for (int i = 0; i < 4; i++) {
            int c = tid + 256 * i;            // 0..1023
            int row = c >> 3, col = c & 7;
            uint32_t sa = sb + row * ROWB + col * 16;
            cp_async16(sa, AbH + (size_t)row * LL + k0 + col * 8);
        }
        // W tiles: 64 rows each
        const __half* wsrc[2] = {B1, B2};
#pragma unroll
        for (int mt = 0; mt < 2; mt++) {
#pragma unroll
            for (int i = 0; i < 2; i++) {
                int c = tid + 256 * i;            // 0..511
                int row = c >> 3, col = c & 7;
                uint32_t sa = sb + GA_B + mt * GW_B + row * ROWB + col * 16;
                cp_async16(sa, wsrc[mt] + (size_t)row * HD + k0 + col * 8);
            }
        }
        asm volatile("cp.async.commit_group;" ::: "memory");
    };

    const int m0w = (wid & 1) * 64;
    const int n0w = (wid >> 1) * 16;

    float acc[2][4][2][4];
#pragma unroll
    for (int s = 0; s < 2; s++)
#pragma unroll
        for (int i = 0; i < 4; i++)
#pragma unroll
            for (int j = 0; j < 2; j++)
#pragma unroll
                for (int e = 0; e < 4; e++) acc[s][i][j][e] = 0.f;

    load_stage(0, 0);
    load_stage(1, 1);

    for (int it = 0; it < NIT; it++) {
        if (it + 1 < NIT) asm volatile("cp.async.wait_group 1;" ::: "memory");
        else              asm volatile("cp.async.wait_group 0;" ::: "memory");
        __syncthreads();

        const int buf = it & 1;
        const uint32_t sA = sbase + buf * GSTAGEB;

#pragma unroll
        for (int ks = 0; ks < BKK; ks += 16) {
            uint32_t ah[4][4];
            const uint32_t aoff = (uint32_t)(lane & 15) * ROWB + (uint32_t)ks * 2
                                + (uint32_t)(lane >> 4) * 16;
#pragma unroll
            for (int mf = 0; mf < 4; mf++) {
                uint32_t ad = (uint32_t)(m0w + mf * 16) * ROWB + aoff;
                ldm_x4(ah[mf], sA + ad);
            }
            const uint32_t boff = (uint32_t)(((lane >> 4) << 3) + (lane & 7)) * ROWB
                                + (uint32_t)ks * 2 + (uint32_t)((lane >> 3) & 1) * 16;
#pragma unroll
            for (int s = 0; s < 2; s++) {
                uint32_t bh[2][2];
                const uint32_t sB = sA + GA_B + s * GW_B;
                uint32_t bd = (uint32_t)n0w * ROWB + boff;
                uint32_t rh[4];
                ldm_x4(rh, sB + bd);
                bh[0][0] = rh[0]; bh[0][1] = rh[1];
                bh[1][0] = rh[2]; bh[1][1] = rh[3];
#pragma unroll
                for (int mf = 0; mf < 4; mf++)
#pragma unroll
                    for (int nf = 0; nf < 2; nf++)
                        mma16816(acc[s][mf][nf], ah[mf], bh[nf]);
            }
        }
        __syncthreads();
        if (it + 2 < NIT) load_stage(it + 2, it & 1);
    }

    // fused combine epilogue (conv value from fp16 A operand)
    const int rbase = m0 + m0w + (lane >> 2);          // global row
    const int cloc0 = n0 + n0w + (lane & 3) * 2;       // col within head
#pragma unroll
    for (int mf = 0; mf < 4; mf++) {
#pragma unroll
        for (int half = 0; half < 2; half++) {
            int row = rbase + mf * 16 + half * 8;
            bool reset = (seg[row] == 0);
#pragma unroll
            for (int nf = 0; nf < 2; nf++) {
                int cl = cloc0 + nf * 8;               // col within head (0..255)
                size_t go = (size_t)row * LL + (size_t)z * HD + cl;
                uint32_t chp = *(const uint32_t*)&cAh[go];
                float outn[2], outa[2];
#pragma unroll
                for (int e = 0; e < 2; e++) {
                    float c1 = acc[0][mf][nf][half * 2 + e] + ib[z * HD + cl + e];
                    float c2 = acc[1][mf][nf][half * 2 + e] + ab[z * HD + cl + e];
                    float gi = 1.f / (1.f + expf(-c1));
                    float ga = 1.f / (1.f + expf(-c2));
                    float ap = a_param[z * HD + cl + e];
                    float sp = log1pf(expf(ap));
                    float la = -8.f * ga * sp;
                    float a = expf(la);
                    float mult = reset ? 1.f : sqrtf(fmaxf(1.f - expf(2.f * la), 0.f));
                    uint16_t hb = (uint16_t)((e == 0) ? (chp & 0xFFFF) : (chp >> 16));
                    float cvv = __half2float(__ushort_as_half(hb));
                    outn[e] = cvv * gi * mult;
                    outa[e] = reset ? 0.f : a;
                }
                *(__half2*)&G1[go] = __floats2half2_rn(outn[0], outn[1]);
                *(float2*)&G2[go]  = make_float2(outa[0], outa[1]);
            }
        }
    }
}

// ---------------------------------------------------------------------------
// f32 -> fp16 convert (vectorized x4)
// ---------------------------------------------------------------------------
__device__ __forceinline__ uint32_t pk2h(__half a, __half b) {
    return (uint32_t)__half_as_ushort(a) | ((uint32_t)__half_as_ushort(b) << 16);
}
__global__ void conv4_k(const float4* __restrict__ in, uint2* __restrict__ oh, long n4)
{
    long i = (long)blockIdx.x * blockDim.x + threadIdx.x;
    if (i >= n4) return;
    float4 v = in[i];
    uint2 H;
    H.x = pk2h(__float2half_rn(v.x), __float2half_rn(v.y));
    H.y = pk2h(__float2half_rn(v.z), __float2half_rn(v.w));
    oh[i] = H;
}

// ---------------------------------------------------------------------------
// Transposing convert for 3 big weights in one launch
// ---------------------------------------------------------------------------
__global__ void tsplit3_k(const float* __restrict__ s0, const float* __restrict__ s1,
                          const float* __restrict__ s2,
                          __half* __restrict__ d0, __half* __restrict__ d1,
                          __half* __restrict__ d2)
{
    __shared__ float t[32][33];
    const int z = blockIdx.z;
    const float* in = (z == 0) ? s0 : (z == 1) ? s1 : s2;
    __half* oh      = (z == 0) ? d0 : (z == 1) ? d1 : d2;
    const int K = WW, N = LL;
    int kb = blockIdx.y * 32, nb = blockIdx.x * 32;
    for (int i = threadIdx.y; i < 32; i += 8)
        t[i][threadIdx.x] = in[(size_t)(kb + i) * N + nb + threadIdx.x];
    __syncthreads();
    for (int i = threadIdx.y; i < 32; i += 8) {
        int n = nb + i, k = kb + threadIdx.x;
        oh[(size_t)n * K + k] = __float2half_rn(t[threadIdx.x][i]);
    }
}

// gate weights: z 0..15 -> (head = z&7, src = z>>3 ? agate : igate)
__global__ void tsplitg_k(const float* __restrict__ ig, const float* __restrict__ ag,
                          __half* __restrict__ d1, __half* __restrict__ d2)
{
    __shared__ float t[32][33];
    const int z = blockIdx.z;
    const int head = z & 7;
    const float* in = ((z >> 3) ? ag : ig) + (size_t)head * HD * HD;
    __half* oh      = ((z >> 3) ? d2 : d1) + (size_t)head * HD * HD;
    int kb = blockIdx.y * 32, nb = blockIdx.x * 32;
    for (int i = threadIdx.y; i < 32; i += 8)
        t[i][threadIdx.x] = in[(size_t)(kb + i) * HD + nb + threadIdx.x];
    __syncthreads();
    for (int i = threadIdx.y; i < 32; i += 8) {
        int n = nb + i, k = kb + threadIdx.x;
        oh[(size_t)n * HD + k] = __float2half_rn(t[threadIdx.x][i]);
    }
}

// ---------------------------------------------------------------------------
// Causal depthwise temporal conv (TW=4) -> fp16 output (gate A operand)
// ---------------------------------------------------------------------------
__global__ void conv_k(const float4* __restrict__ xb, const float4* __restrict__ cw,
                       const float4* __restrict__ cb, uint2* __restrict__ oh)
{
    long idx = (long)blockIdx.x * blockDim.x + threadIdx.x;
    if (idx >= (long)MTOT * L4C) return;
    int l4 = (int)(idx % L4C);
    int m = (int)(idx / L4C);
    int t = m % TT;
    float4 acc = cb[l4];
#pragma unroll
    for (int j = 0; j < TWD; j++) {
        int dt = TWD - 1 - j;
        if (t - dt >= 0) {
            float4 w = cw[j * L4C + l4];
            float4 x = xb[(long)(m - dt) * L4C + l4];
            acc.x = fmaf(w.x, x.x, acc.x);
            acc.y = fmaf(w.y, x.y, acc.y);
            acc.z = fmaf(w.z, x.z, acc.z);
            acc.w = fmaf(w.w, x.w, acc.w);
        }
    }
    uint2 H;
    H.x = pk2h(__float2half_rn(acc.x), __float2half_rn(acc.y));
    H.y = pk2h(__float2half_rn(acc.z), __float2half_rn(acc.w));
    oh[idx] = H;
}

// ---------------------------------------------------------------------------
// Chunked scan (scalar over L): h_t = a_t h_{t-1} + x_t
// x (normed) read as fp16; a (a_masked) f32.
// Pass 3 fused with gate (h*y, fp16) and fp16 convert for the final GEMM.
// ---------------------------------------------------------------------------
__global__ void scan_p1(const float* __restrict__ a, const __half* __restrict__ x,
                        float* __restrict__ Aagg, float* __restrict__ Hend)
{
    long idx = (long)blockIdx.x * blockDim.x + threadIdx.x;  // over B*NCH*L
    if (idx >= (long)BB * NCH * LL) return;
    int l = (int)(idx % LL);
    int r = (int)(idx / LL);
    int c = r % NCH, b = r / NCH;
    size_t base = ((size_t)b * TT + (size_t)c * SCH) * LL + l;
    float h = 0.f, ap = 1.f;
#pragma unroll 4
    for (int t = 0; t < SCH; t++) {
        float av = a[base + (size_t)t * LL];
        h = fmaf(av, h, __half2float(x[base + (size_t)t * LL]));
        ap *= av;
    }
    Aagg[idx] = ap; Hend[idx] = h;
}
__global__ void scan_p2(const float* __restrict__ Aagg, const float* __restrict__ Hend,
                        float* __restrict__ Cin)
{
    int idx = blockIdx.x * blockDim.x + threadIdx.x;
    if (idx >= BB * LL) return;
    int l = idx % LL, b = idx / LL;
    float cin = 0.f;
    for (int c = 0; c < NCH; c++) {
        size_t j = ((size_t)b * NCH + c) * LL + l;
        Cin[j] = cin;
        cin = fmaf(Aagg[j], cin, Hend[j]);
    }
}
__global__ void scan_p3f(const float* __restrict__ a, const __half* __restrict__ x,
                         const float* __restrict__ Cin, const __half* __restrict__ y,
                         __half* __restrict__ oh)
{
    long idx = (long)blockIdx.x * blockDim.x + threadIdx.x;
    if (idx >= (long)BB * NCH * LL) return;
    int l = (int)(idx % LL);
    int r = (int)(idx / LL);
    int c = r % NCH, b = r / NCH;
    size_t base = ((size_t)b * TT + (size_t)c * SCH) * LL + l;
    float h = Cin[idx];
#pragma unroll 4
    for (int t = 0; t < SCH; t++) {
        size_t o = base + (size_t)t * LL;
        h = fmaf(a[o], h, __half2float(x[o]));
        oh[o] = __float2half_rn(h * __half2float(y[o]));
    }
}

// ---------------------------------------------------------------------------
// Launch
// ---------------------------------------------------------------------------
extern "C" void kernel_launch(void* const* d_in, const int* in_sizes, int n_in,
                              void* d_out, int out_size)
{
    const float* x       = (const float*)d_in[0];
    const int*   seg     = (const int*)  d_in[1];
    const float* w_y     = (const float*)d_in[2];
    const float* b_y     = (const float*)d_in[3];
    const float* w_x     = (const float*)d_in[4];
    const float* b_x     = (const float*)d_in[5];
    const float* w_out   = (const float*)d_in[6];
    const float* b_out   = (const float*)d_in[7];
    const float* conv_w  = (const float*)d_in[8];
    const float* conv_b  = (const float*)d_in[9];
    const float* a_param = (const float*)d_in[10];
    const float* igate_w = (const float*)d_in[11];
    const float* igate_b = (const float*)d_in[12];
    const float* agate_w = (const float*)d_in[13];
    const float* agate_b = (const float*)d_in[14];
    float* out = (float*)d_out;

    float *XB, *G2, *Aagg, *Hend, *Cin;
    __half *Yh, *G1h, *Ah, *BY, *BX, *BO, *GW1, *GW2;
    cudaGetSymbolAddress((void**)&Yh, g_Yh);
    cudaGetSymbolAddress((void**)&XB, g_XB);
    cudaGetSymbolAddress((void**)&G1h, g_G1h);
    cudaGetSymbolAddress((void**)&G2, g_G2);
    cudaGetSymbolAddress((void**)&Ah, g_Ah);
    cudaGetSymbolAddress((void**)&BY, g_BY);
    cudaGetSymbolAddress((void**)&BX, g_BX);
    cudaGetSymbolAddress((void**)&BO, g_BO);
    cudaGetSymbolAddress((void**)&GW1, g_GW1);
    cudaGetSymbolAddress((void**)&GW2, g_GW2);
    cudaGetSymbolAddress((void**)&Aagg, g_Aagg);
    cudaGetSymbolAddress((void**)&Hend, g_Hend);
    cudaGetSymbolAddress((void**)&Cin, g_Cin);

    cudaFuncSetAttribute(gemm_dual, cudaFuncAttributeMaxDynamicSharedMemorySize, GEMM_SMEM);
    cudaFuncSetAttribute(gemm_single, cudaFuncAttributeMaxDynamicSharedMemorySize, GEMM_SMEM);
    cudaFuncSetAttribute(gate_tc, cudaFuncAttributeMaxDynamicSharedMemorySize, GATE_SMEM);

    const long n4 = (long)ELEMS / 4;
    const int eb = (int)((n4 + 255) / 256);
    dim3 t3grid(WW / 32, WW / 32, 3);
    dim3 tblk(32, 8, 1);
    dim3 dualGrid(LL / 128, MTOT / 128, 2);    // (16, 64, 2)
    dim3 bigGrid(LL / 128, MTOT / 128, 1);     // (16, 64)
    dim3 gateGrid(HD / 64, MTOT / 128, HH);    // (4, 64, 8)
    dim3 ggrid(HD / 32, HD / 32, 16);

    // slot 0: convert x -> Ah (fp16)
    conv4_k<<<eb, 256>>>((const float4*)x, (uint2*)Ah, n4);
    // slot 1: all three big weight transposes in one launch
    tsplit3_k<<<t3grid, tblk>>>(w_y, w_x, w_out, BY, BX, BO);
    // slot 2: both gate weight transposes in one launch
    tsplitg_k<<<ggrid, tblk>>>(igate_w, agate_w, GW1, GW2);
    // slot 3: merged dual GEMM -> Yh (gelu, fp16) and XB (f32)
    gemm_dual<<<dualGrid, 256, GEMM_SMEM>>>(Ah, BY, BX, b_y, b_x, Yh, XB,
                                            WW, WW, WW, LL);
    // slot 4: conv -> fp16 into Ah (gate A operand)
    {
        long tot = (long)MTOT * L4C;
        conv_k<<<(int)((tot + 255) / 256), 256>>>((const float4*)XB, (const float4*)conv_w,
                                                  (const float4*)conv_b, (uint2*)Ah);
    }
    // slot 5: dual gate GEMM (1-product) with fused combine
    gate_tc<<<gateGrid, 256, GATE_SMEM>>>(Ah, GW1, GW2,
                                          igate_b, agate_b, a_param, seg, G1h, G2);
    // slots 6-8: chunked scan ; pass 3 fused with h*y and fp16 convert into Ah
    {
        long tot = (long)BB * NCH * LL;
        int blocks = (int)((tot + 255) / 256);
        scan_p1<<<blocks, 256>>>(G2, G1h, Aagg, Hend);
        scan_p2<<<(BB * LL + 255) / 256, 256>>>(Aagg, Hend, Cin);
        scan_p3f<<<blocks, 256>>>(G2, G1h, Cin, Yh, Ah);
    }
    // slot 9: final GEMM -> out
    gemm_single<<<bigGrid, 256, GEMM_SMEM>>>(Ah, BO, b_out, out, LL, LL, LL, WW);
}